// round 12
// speedup vs baseline: 8.2681x; 1.0937x over previous
#include <cuda_runtime.h>
#include <cuda_bf16.h>
#include <math.h>
#include <stdint.h>

#define B_ 8
#define N_ 2048
#define F_ 256
#define H_ 128
#define K_ 1025
#define OUTC 384
#define CAP 256

// ---------------- scratch (device globals; no allocation allowed) ----------
__device__ float g_T [(size_t)B_*N_*N_];   // Tc (layer1, stride cnp)
__device__ float g_Ac[(size_t)B_*N_*N_];   // compacted A2 (stride N_)
__device__ float g_A3[(size_t)B_*N_*N_];   // compacted A3 (stride N_)
__device__ __nv_bfloat16 g_Ahi[(size_t)B_*N_*N_], g_Alo[(size_t)B_*N_*N_];
__device__ __nv_bfloat16 g_SThi[(size_t)B_*N_*N_], g_STlo[(size_t)B_*N_*N_];
__device__ __nv_bfloat16 g_TThi[(size_t)B_*N_*N_], g_TTlo[(size_t)B_*N_*N_];
__device__ __nv_bfloat16 g_xTh[B_*H_*N_], g_xTl[B_*H_*N_];   // xc^T split
__device__ float g_xW [B_*N_*F_];
__device__ float g_x1 [B_*N_*H_];
__device__ float g_xc [B_*N_*H_];
__device__ float g_x3 [B_*N_*H_];
__device__ int   g_lst[(size_t)B_*N_*CAP];
__device__ int   g_deg[B_*N_];
__device__ int   g_hasd[B_*N_];
__device__ float g_d0[B_*N_], g_d1[B_*N_], g_rnz[B_*N_];
__device__ float g_d2[B_*N_], g_rz2[B_*N_];
__device__ float g_v[B_*N_], g_alp[B_*N_], g_ca[B_*N_], g_srec[B_*N_];
__device__ float g_cut[B_];
__device__ float g_maskc[B_*N_], g_mrest[B_];
__device__ int   g_idx[B_*N_], g_ginv[B_*N_], g_cnt[B_];
__device__ float g_p1[B_*4*H_], g_p2[B_*4*F_];

// ---------------- async-copy / mma helpers -----------------------------------
#define CP16(dst, src) { \
    unsigned _a = (unsigned)__cvta_generic_to_shared(dst); \
    asm volatile("cp.async.cg.shared.global [%0], [%1], 16;\n" :: "r"(_a), "l"(src)); }
#define CP_COMMIT() asm volatile("cp.async.commit_group;\n")
#define CP_WAIT0()  asm volatile("cp.async.wait_group 0;\n")

__device__ __forceinline__ void mma_bf16(float* c, const uint32_t* a, uint32_t b0, uint32_t b1) {
    asm volatile("mma.sync.aligned.m16n8k16.row.col.f32.bf16.bf16.f32 "
        "{%0,%1,%2,%3}, {%4,%5,%6,%7}, {%8,%9}, {%0,%1,%2,%3};"
        : "+f"(c[0]), "+f"(c[1]), "+f"(c[2]), "+f"(c[3])
        : "r"(a[0]), "r"(a[1]), "r"(a[2]), "r"(a[3]), "r"(b0), "r"(b1));
}
__device__ __forceinline__ void ldsm4(uint32_t* r, const void* p) {
    uint32_t a = (uint32_t)__cvta_generic_to_shared(p);
    asm volatile("ldmatrix.sync.aligned.m8n8.x4.shared.b16 {%0,%1,%2,%3}, [%4];"
        : "=r"(r[0]), "=r"(r[1]), "=r"(r[2]), "=r"(r[3]) : "r"(a));
}
__device__ __forceinline__ __nv_bfloat162 split_hi2(float v0, float v1) {
    __nv_bfloat162 h; h.x = __float2bfloat16(v0); h.y = __float2bfloat16(v1); return h;
}
__device__ __forceinline__ __nv_bfloat162 split_lo2(float v0, float v1, __nv_bfloat162 h) {
    __nv_bfloat162 l;
    l.x = __float2bfloat16(v0 - __bfloat162float(h.x));
    l.y = __float2bfloat16(v1 - __bfloat162float(h.y));
    return l;
}

// ---------------- CSR build + degree stats (one adj scan, float4) -----------
__global__ void csr_build_kernel(const float* __restrict__ adj, int* __restrict__ lst,
                                 int* __restrict__ deg, int* __restrict__ hasd,
                                 float* __restrict__ d0, float* __restrict__ d1,
                                 float* __restrict__ rnz) {
    __shared__ int sc[256];
    __shared__ int hd;
    int b = blockIdx.y, i = blockIdx.x, tid = threadIdx.x;
    const float4* arow4 = (const float4*)(adj + ((size_t)(b * N_ + i)) * N_);
    if (tid == 0) hd = 0;
    __syncthreads();
    float vals[8];
    *(float4*)(vals)     = arow4[tid * 2];
    *(float4*)(vals + 4) = arow4[tid * 2 + 1];
    int f[8];
    int c = 0, hloc = 0;
    #pragma unroll
    for (int e = 0; e < 8; e++) {
        int j = tid * 8 + e;
        f[e] = (vals[e] != 0.f) ? 1 : 0;
        c += f[e];
        if (f[e] && j == i) hloc = 1;
    }
    if (hloc) hd = 1;
    sc[tid] = c; __syncthreads();
    for (int o = 1; o < 256; o <<= 1) {
        int v = (tid >= o) ? sc[tid - o] : 0; __syncthreads();
        sc[tid] += v; __syncthreads();
    }
    int base = sc[tid] - c;
    int* l = lst + ((size_t)(b * N_ + i)) * CAP;
    #pragma unroll
    for (int e = 0; e < 8; e++) {
        if (f[e]) { if (base < CAP) l[base] = tid * 8 + e; base++; }
    }
    __syncthreads();
    if (tid == 0) {
        int total = sc[255];
        deg[b * N_ + i] = (total > CAP) ? CAP : total;
        hasd[b * N_ + i] = hd;
        d0[b * N_ + i] = rsqrtf(fmaxf((float)(total - hd) + 1.f, 1.f));
        d1[b * N_ + i] = rsqrtf((float)total + 1.f);
        rnz[b * N_ + i] = (total > 0) ? 1.f : 0.f;
    }
}

// ------- GCN layer 1 sparse aggregation (staged coef lists, pipelined) ------
__global__ void gcn1_kernel(const int* __restrict__ lst, const int* __restrict__ deg,
                            const float* __restrict__ d0, const float* __restrict__ xW,
                            const float* __restrict__ b1, const float* __restrict__ mask,
                            float* __restrict__ x1) {
    __shared__ int   jl[CAP];
    __shared__ float cf[CAP];
    int b = blockIdx.y, i = blockIdx.x, c = threadIdx.x;   // 128 threads
    int dg = deg[b * N_ + i];
    const int* l = lst + ((size_t)(b * N_ + i)) * CAP;
    float di = d0[b * N_ + i];
    for (int p = c; p < dg; p += 128) {
        int j = l[p];
        jl[p] = j;
        cf[p] = (j == i) ? 0.f : di * d0[b * N_ + j];
    }
    __syncthreads();
    float acc = di * di * xW[((size_t)(b * N_ + i)) * H_ + c];
    #pragma unroll 4
    for (int p = 0; p < dg; p++)
        acc = fmaf(cf[p], xW[((size_t)(b * N_ + jl[p])) * H_ + c], acc);
    float vv = (acc + b1[c]) * mask[b * N_ + i];
    x1[((size_t)(b * N_ + i)) * H_ + c] = fmaxf(vv, 0.f);
}

// ---------------- v = x @ Watt + batt ----------------------------------------
__global__ void gemv_watt_kernel(const float* __restrict__ x, const float* __restrict__ Watt,
                                 const float* __restrict__ batt, float* __restrict__ v) {
    int w = blockIdx.x * 8 + (threadIdx.x >> 5);
    int lane = threadIdx.x & 31;
    if (w >= B_ * N_) return;
    const float* xr = x + (size_t)w * H_;
    float s = 0.f;
    #pragma unroll
    for (int c = lane; c < H_; c += 32) s += xr[c] * Watt[c];
    #pragma unroll
    for (int o = 16; o > 0; o >>= 1) s += __shfl_down_sync(0xffffffffu, s, o);
    if (lane == 0) v[w] = s + batt[0];
}

// ---------------- layer-1 alpha (sparse) --------------------------------------
__global__ void alpha1_kernel(const int* __restrict__ lst, const int* __restrict__ deg,
                              const float* __restrict__ d1, const float* __restrict__ rnz,
                              const float* __restrict__ v, float* __restrict__ alp) {
    int b = blockIdx.y;
    int i = blockIdx.x * 8 + (threadIdx.x >> 5);
    int lane = threadIdx.x & 31;
    const int* l = lst + ((size_t)(b * N_ + i)) * CAP;
    int dg = deg[b * N_ + i];
    float s = 0.f;
    for (int p = lane; p < dg; p += 32) { int j = l[p]; s += d1[b * N_ + j] * v[b * N_ + j]; }
    #pragma unroll
    for (int o = 16; o > 0; o >>= 1) s += __shfl_down_sync(0xffffffffu, s, o);
    if (lane == 0) {
        float di = d1[b * N_ + i];
        float r = rnz[b * N_ + i] * di * (s + di * v[b * N_ + i]);
        float z = r * r;
        alp[b * N_ + i] = 1.f / (1.f + expf(-z));
    }
}

// ---------------- exact K-th largest via bitonic sort ------------------------
__global__ void topk_cut_kernel(const float* __restrict__ alp, float* __restrict__ cut) {
    __shared__ float s[N_];
    int b = blockIdx.x, t = threadIdx.x;   // 1024 threads
    s[t] = alp[b * N_ + t];
    s[t + 1024] = alp[b * N_ + t + 1024];
    __syncthreads();
    for (int k = 2; k <= N_; k <<= 1) {
        for (int j = k >> 1; j > 0; j >>= 1) {
            for (int i = t; i < N_; i += 1024) {
                int ixj = i ^ j;
                if (ixj > i) {
                    float a = s[i], c = s[ixj];
                    if (((i & k) == 0) ? (a > c) : (a < c)) { s[i] = c; s[ixj] = a; }
                }
            }
            __syncthreads();
        }
    }
    if (t == 0) cut[b] = s[N_ - K_];
}

__global__ void ca_kernel(const float* __restrict__ alp, const float* __restrict__ cut,
                          float* __restrict__ ca) {
    int idx = blockIdx.x * 256 + threadIdx.x;
    int b = idx / N_;
    ca[idx] = fmaxf(alp[idx] + 1e-7f - cut[b], 0.f);
}

// ---------------- deterministic kept-set compaction (prefix scan) -----------
__global__ void compact_kernel(const float* __restrict__ ca, int* __restrict__ idx,
                               int* __restrict__ ginv, int* __restrict__ cnt) {
    __shared__ int sc[1024];
    int b = blockIdx.x, t = threadIdx.x;   // 1024 threads
    int f0 = (ca[b * N_ + 2 * t]     > 0.f) ? 1 : 0;
    int f1 = (ca[b * N_ + 2 * t + 1] > 0.f) ? 1 : 0;
    ginv[b * N_ + 2 * t] = -1;
    ginv[b * N_ + 2 * t + 1] = -1;
    int c = f0 + f1;
    sc[t] = c; __syncthreads();
    for (int o = 1; o < 1024; o <<= 1) {
        int v = (t >= o) ? sc[t - o] : 0; __syncthreads();
        sc[t] += v; __syncthreads();
    }
    int base = sc[t] - c;
    if (f0) { idx[b * N_ + base] = 2 * t;     ginv[b * N_ + 2 * t]     = base; base++; }
    if (f1) { idx[b * N_ + base] = 2 * t + 1; ginv[b * N_ + 2 * t + 1] = base; }
    if (t == 1023) cnt[b] = sc[1023];
}

// maskc = compacted mask; mrest = TOTAL mask sum (for final-layer bias fold)
__global__ void compact_mask_kernel(const float* __restrict__ mask, const int* __restrict__ idx,
                                    const int* __restrict__ cnt, float* __restrict__ maskc,
                                    float* __restrict__ mrest) {
    __shared__ float red[256];
    int b = blockIdx.x, t = threadIdx.x;
    int c = cnt[b];
    float local = 0.f;
    for (int i = t; i < N_; i += 256) {
        float mv = 0.f;
        if (i < c) mv = mask[b * N_ + idx[b * N_ + i]];
        maskc[b * N_ + i] = mv;
        local += mask[b * N_ + i];
    }
    red[t] = local; __syncthreads();
    for (int o = 128; o > 0; o >>= 1) { if (t < o) red[t] += red[t + o]; __syncthreads(); }
    if (t == 0) mrest[b] = red[0];
}

// ---------------- layer-1 S row normalizer -----------------------------------
__global__ void srec_kernel(const int* __restrict__ lst, const int* __restrict__ deg,
                            const float* __restrict__ d1, const float* __restrict__ rnz,
                            const float* __restrict__ ca, float* __restrict__ srec) {
    int b = blockIdx.y;
    int i = blockIdx.x * 8 + (threadIdx.x >> 5);
    int lane = threadIdx.x & 31;
    const int* l = lst + ((size_t)(b * N_ + i)) * CAP;
    int dg = deg[b * N_ + i];
    float s = 0.f;
    for (int p = lane; p < dg; p += 32) { int j = l[p]; s += d1[b * N_ + j] * ca[b * N_ + j]; }
    #pragma unroll
    for (int o = 16; o > 0; o >>= 1) s += __shfl_down_sync(0xffffffffu, s, o);
    if (lane == 0) {
        float di = d1[b * N_ + i];
        float raw = rnz[b * N_ + i] * di * (s + di * ca[b * N_ + i]);
        srec[b * N_ + i] = rnz[b * N_ + i] * di / fmaxf(raw, 1e-12f);
    }
}

// ---- xc[ic,:] = sum_n S[n, idx[ic]] * x1[n,:]  (staged lists, pipelined) ----
__global__ void xupd_kernel(const int* __restrict__ lst, const int* __restrict__ deg,
                            const int* __restrict__ hasd, const float* __restrict__ d1,
                            const float* __restrict__ ca, const float* __restrict__ srec,
                            const int* __restrict__ idx, const int* __restrict__ cnt,
                            const float* __restrict__ x1, float* __restrict__ xc) {
    __shared__ int   jl[CAP + 1];
    __shared__ float sv[CAP + 1];
    int b = blockIdx.y, ic = blockIdx.x, c = threadIdx.x;   // 128 threads
    int cn = cnt[b], cnp = (cn + 127) & ~127;
    if (ic >= cnp) return;
    float* orow = xc + ((size_t)(b * N_ + ic)) * H_;
    if (ic >= cn) { orow[c] = 0.f; return; }
    int m = idx[b * N_ + ic];
    float dmcam = d1[b * N_ + m] * ca[b * N_ + m];
    int dg = deg[b * N_ + m];
    const int* l = lst + ((size_t)(b * N_ + m)) * CAP;
    for (int p = c; p < dg; p += 128) {
        int n = l[p];
        jl[p] = n;
        sv[p] = srec[b * N_ + n] * dmcam * ((n == m) ? 2.f : 1.f);
    }
    int dgE = dg + (hasd[b * N_ + m] ? 0 : 1);
    if (c == 0 && dgE > dg) { jl[dg] = m; sv[dg] = srec[b * N_ + m] * dmcam; }
    __syncthreads();
    float acc = 0.f;
    #pragma unroll 4
    for (int p = 0; p < dgE; p++)
        acc = fmaf(sv[p], x1[((size_t)(b * N_ + jl[p])) * H_ + c], acc);
    orow[c] = acc;
}

// ---- Tc[i,:] = sum_{j in list_i} S_row_j, S rows expanded on the fly --------
__global__ void adjS_sparse_kernel(const int* __restrict__ lst, const int* __restrict__ deg,
                                   const int* __restrict__ hasd, const float* __restrict__ d1,
                                   const float* __restrict__ ca, const float* __restrict__ srec,
                                   const int* __restrict__ ginv, const int* __restrict__ cnt,
                                   float* __restrict__ Tc) {
    __shared__ float acc[4][N_];
    int b = blockIdx.y, tid = threadIdx.x;   // 128 threads = 4 warps
    int w = tid >> 5, lane = tid & 31;
    int i = blockIdx.x * 4 + w;
    int cnp = (cnt[b] + 127) & ~127;
    float* a = acc[w];
    float4* a4 = (float4*)a;
    float4 z4 = make_float4(0.f, 0.f, 0.f, 0.f);
    for (int jc = lane; jc < (cnp >> 2); jc += 32) a4[jc] = z4;
    __syncwarp();
    int dgi = deg[b * N_ + i];
    const int* li = lst + ((size_t)(b * N_ + i)) * CAP;
    const int* gv = ginv + b * N_;
    for (int p = 0; p < dgi; p++) {
        int j = li[p];
        int dgj = deg[b * N_ + j];
        const int* lj = lst + ((size_t)(b * N_ + j)) * CAP;
        float sr = srec[b * N_ + j];
        for (int q = lane; q < dgj; q += 32) {
            int m = lj[q];
            int jc = gv[m];
            if (jc >= 0) {
                float coef = (m == j) ? 2.f : 1.f;
                a[jc] += sr * d1[b * N_ + m] * ca[b * N_ + m] * coef;
            }
        }
        __syncwarp();
        if (lane == 0 && !hasd[b * N_ + j]) {
            int jc = gv[j];
            if (jc >= 0) a[jc] += sr * d1[b * N_ + j] * ca[b * N_ + j];
        }
        __syncwarp();
    }
    float4* trow4 = (float4*)(Tc + (size_t)b * N_ * N_ + (size_t)i * cnp);
    for (int jc = lane; jc < (cnp >> 2); jc += 32) trow4[jc] = a4[jc];
}

// -- Ac row = floorq(sum S*Tc); REGISTER accumulators + staged coef lists -----
__global__ void STT_kernel(const int* __restrict__ lst, const int* __restrict__ deg,
                           const int* __restrict__ hasd, const float* __restrict__ d1,
                           const float* __restrict__ ca, const float* __restrict__ srec,
                           const int* __restrict__ idx, const int* __restrict__ cnt,
                           const float* __restrict__ Tc, float* __restrict__ Ac,
                           __nv_bfloat16* __restrict__ Achi, __nv_bfloat16* __restrict__ Aclo,
                           float* __restrict__ d2out, float* __restrict__ rz2out) {
    __shared__ int   nls[CAP + 1];
    __shared__ float svs[CAP + 1];
    __shared__ float red[256];
    int b = blockIdx.y, ic = blockIdx.x, tid = threadIdx.x;
    int cn = cnt[b], cnp = (cn + 127) & ~127, cnp4 = cnp >> 2;
    if (ic >= cnp) return;
    size_t rowoff = ((size_t)(b * N_ + ic)) * N_;
    float4* orow4 = (float4*)(Ac + rowoff);
    __nv_bfloat162* ohi = (__nv_bfloat162*)(Achi + rowoff);
    __nv_bfloat162* olo = (__nv_bfloat162*)(Aclo + rowoff);
    float4 z4 = make_float4(0.f, 0.f, 0.f, 0.f);
    if (ic >= cn) {
        __nv_bfloat162 zb; zb.x = __float2bfloat16(0.f); zb.y = zb.x;
        for (int jc = tid; jc < cnp4; jc += 256) {
            orow4[jc] = z4;
            ohi[jc * 2] = zb; ohi[jc * 2 + 1] = zb;
            olo[jc * 2] = zb; olo[jc * 2 + 1] = zb;
        }
        if (tid == 0) { d2out[b * N_ + ic] = 1.f; rz2out[b * N_ + ic] = 0.f; }
        return;
    }
    int m = idx[b * N_ + ic];
    float dmcam = d1[b * N_ + m] * ca[b * N_ + m];
    int dg = deg[b * N_ + m];
    const int* l = lst + ((size_t)(b * N_ + m)) * CAP;
    for (int p = tid; p < dg; p += 256) {
        int n = l[p];
        nls[p] = n;
        svs[p] = srec[b * N_ + n] * dmcam * ((n == m) ? 2.f : 1.f);
    }
    int dgE = dg + (hasd[b * N_ + m] ? 0 : 1);
    if (tid == 0 && dgE > dg) { nls[dg] = m; svs[dg] = srec[b * N_ + m] * dmcam; }
    __syncthreads();
    const float* Tb = Tc + (size_t)b * N_ * N_;
    int j0 = tid, j1 = tid + 256;
    bool h1 = (j1 < cnp4);
    float4 a0 = z4, a1 = z4;
    #pragma unroll 2
    for (int p = 0; p < dgE; p++) {
        float sv = svs[p];
        const float4* trow = (const float4*)(Tb + (size_t)nls[p] * cnp);
        float4 t0 = trow[j0];
        a0.x = fmaf(sv, t0.x, a0.x); a0.y = fmaf(sv, t0.y, a0.y);
        a0.z = fmaf(sv, t0.z, a0.z); a0.w = fmaf(sv, t0.w, a0.w);
        if (h1) {
            float4 t1 = trow[j1];
            a1.x = fmaf(sv, t1.x, a1.x); a1.y = fmaf(sv, t1.y, a1.y);
            a1.z = fmaf(sv, t1.z, a1.z); a1.w = fmaf(sv, t1.w, a1.w);
        }
    }
    float part = 0.f;
    #pragma unroll
    for (int r = 0; r < 2; r++) {
        int jc = (r == 0) ? j0 : j1;
        if (r == 1 && !h1) break;
        float4 a = (r == 0) ? a0 : a1;
        a.x = floorf(a.x * 10000.f) / 10000.f;
        a.y = floorf(a.y * 10000.f) / 10000.f;
        a.z = floorf(a.z * 10000.f) / 10000.f;
        a.w = floorf(a.w * 10000.f) / 10000.f;
        orow4[jc] = a;
        part += (a.x + a.y) + (a.z + a.w);
        __nv_bfloat162 h01 = split_hi2(a.x, a.y), h23 = split_hi2(a.z, a.w);
        ohi[jc * 2] = h01; ohi[jc * 2 + 1] = h23;
        olo[jc * 2] = split_lo2(a.x, a.y, h01); olo[jc * 2 + 1] = split_lo2(a.z, a.w, h23);
    }
    red[tid] = part; __syncthreads();
    for (int o = 128; o > 0; o >>= 1) { if (tid < o) red[tid] += red[tid + o]; __syncthreads(); }
    if (tid == 0) {
        float sum = red[0];
        d2out[b * N_ + ic] = rsqrtf(fmaxf(sum + 1.f, 1.f));
        rz2out[b * N_ + ic] = (sum > 0.f) ? 1.f : 0.f;
    }
}

// ---------------- layer-2 / final helpers (read Ac/A3 directly) --------------
__global__ void rowstats_c_kernel(const float* __restrict__ A, const int* __restrict__ cnt,
                                  float* __restrict__ dout, float* __restrict__ rnz, int mode) {
    int b = blockIdx.y, i = blockIdx.x, tid = threadIdx.x;
    int cnp = (cnt[b] + 127) & ~127;
    if (i >= cnp) return;
    const float* row = A + ((size_t)(b * N_ + i)) * N_;
    const float4* row4 = (const float4*)row;
    float s = 0.f;
    for (int j = tid; j < (cnp >> 2); j += 256) {
        float4 a = row4[j]; s += (a.x + a.y) + (a.z + a.w);
    }
    __shared__ float red[256];
    red[tid] = s; __syncthreads();
    for (int o = 128; o > 0; o >>= 1) { if (tid < o) red[tid] += red[tid + o]; __syncthreads(); }
    if (tid == 0) {
        float sum = red[0];
        if (mode == 0) {
            dout[b * N_ + i] = rsqrtf(fmaxf(sum - row[i] + 1.f, 1.f));
        } else {
            dout[b * N_ + i] = rsqrtf(fmaxf(sum + 1.f, 1.f));
            rnz[b * N_ + i] = (sum > 0.f) ? 1.f : 0.f;
        }
    }
}

__global__ void alpha2d_kernel(const float* __restrict__ Ac, const float* __restrict__ d2,
                               const float* __restrict__ rz2, const float* __restrict__ v,
                               const int* __restrict__ cnt, float* __restrict__ alp) {
    __shared__ float dv[N_];
    __shared__ float red[256];
    int b = blockIdx.y, n = blockIdx.x, tid = threadIdx.x;
    int cnp = (cnt[b] + 127) & ~127;
    if (n >= cnp) { if (tid == 0) alp[b * N_ + n] = 0.5f; return; }
    for (int m = tid; m < cnp; m += 256) dv[m] = d2[b * N_ + m] * v[b * N_ + m];
    __syncthreads();
    const float4* row4 = (const float4*)(Ac + ((size_t)(b * N_ + n)) * N_);
    const float4* dv4 = (const float4*)dv;
    float s = 0.f;
    for (int m = tid; m < (cnp >> 2); m += 256) {
        float4 a = row4[m], w = dv4[m];
        s += a.x * w.x + a.y * w.y + a.z * w.z + a.w * w.w;
    }
    red[tid] = s; __syncthreads();
    for (int o = 128; o > 0; o >>= 1) { if (tid < o) red[tid] += red[tid + o]; __syncthreads(); }
    if (tid == 0) {
        float r = rz2[b * N_ + n] * d2[b * N_ + n] * (red[0] + dv[n]);
        alp[b * N_ + n] = 1.f / (1.f + expf(-r * r));
    }
}

// sinv[n] = f / max(f * sum_m (Ac[n][m]+delta)*dca[m], 1e-12), f = rz2*d2
__global__ void s2inv_kernel(const float* __restrict__ Ac, const float* __restrict__ d2,
                             const float* __restrict__ rz2, const float* __restrict__ ca,
                             const int* __restrict__ cnt, float* __restrict__ sinv) {
    __shared__ float dca[N_];
    __shared__ float red[256];
    int b = blockIdx.y, n = blockIdx.x, tid = threadIdx.x;
    int cnp = (cnt[b] + 127) & ~127;
    if (n >= cnp) return;
    for (int m = tid; m < cnp; m += 256) dca[m] = d2[b * N_ + m] * ca[b * N_ + m];
    __syncthreads();
    const float4* row4 = (const float4*)(Ac + ((size_t)(b * N_ + n)) * N_);
    const float4* dca4 = (const float4*)dca;
    float s = 0.f;
    for (int m = tid; m < (cnp >> 2); m += 256) {
        float4 a = row4[m], w = dca4[m];
        s += a.x * w.x + a.y * w.y + a.z * w.z + a.w * w.w;
    }
    red[tid] = s; __syncthreads();
    for (int o = 128; o > 0; o >>= 1) { if (tid < o) red[tid] += red[tid + o]; __syncthreads(); }
    if (tid == 0) {
        float sum = red[0] + dca[n];
        float f = rz2[b * N_ + n] * d2[b * N_ + n];
        sinv[b * N_ + n] = f / fmaxf(f * sum, 1e-12f);
    }
}

// ST[m][n] = S2[n][m] = (Ac[m][n] + (m==n)) * dca[m] * sinv[n]  (Ac symmetric)
__global__ void buildST_kernel(const float* __restrict__ Ac, const float* __restrict__ d2,
                               const float* __restrict__ ca, const float* __restrict__ sinv,
                               const int* __restrict__ cnt,
                               __nv_bfloat16* __restrict__ SThi, __nv_bfloat16* __restrict__ STlo) {
    __shared__ float siv[N_];
    int b = blockIdx.y, m = blockIdx.x, tid = threadIdx.x;
    int cnp = (cnt[b] + 127) & ~127;
    if (m >= cnp) return;
    for (int n = tid; n < cnp; n += 256) siv[n] = sinv[b * N_ + n];
    __syncthreads();
    float dcam = d2[b * N_ + m] * ca[b * N_ + m];
    size_t ro = ((size_t)(b * N_ + m)) * N_;
    const float4* row4 = (const float4*)(Ac + ro);
    __nv_bfloat162* ohi = (__nv_bfloat162*)(SThi + ro);
    __nv_bfloat162* olo = (__nv_bfloat162*)(STlo + ro);
    for (int q = tid; q < (cnp >> 2); q += 256) {
        float4 a = row4[q];
        int n = q << 2;
        float v0 = (a.x + ((n    ) == m ? 1.f : 0.f)) * dcam * siv[n];
        float v1 = (a.y + ((n + 1) == m ? 1.f : 0.f)) * dcam * siv[n + 1];
        float v2 = (a.z + ((n + 2) == m ? 1.f : 0.f)) * dcam * siv[n + 2];
        float v3 = (a.w + ((n + 3) == m ? 1.f : 0.f)) * dcam * siv[n + 3];
        __nv_bfloat162 h01 = split_hi2(v0, v1), h23 = split_hi2(v2, v3);
        ohi[q * 2] = h01; ohi[q * 2 + 1] = h23;
        olo[q * 2] = split_lo2(v0, v1, h01); olo[q * 2 + 1] = split_lo2(v2, v3, h23);
    }
}

// w[k] = d2[k] * (sum_m A3[k][m]*dv[m] - A3[k][k]*dv[k] + dv[k]), dv = d2*maskc
__global__ void wvec_kernel(const float* __restrict__ A3, const float* __restrict__ d2,
                            const float* __restrict__ maskc, const int* __restrict__ cnt,
                            float* __restrict__ wv) {
    __shared__ float dv[N_];
    __shared__ float red[256];
    int b = blockIdx.y, k = blockIdx.x, tid = threadIdx.x;
    int cnp = (cnt[b] + 127) & ~127;
    if (k >= cnp) return;
    for (int m = tid; m < cnp; m += 256) dv[m] = d2[b * N_ + m] * maskc[b * N_ + m];
    __syncthreads();
    const float* row = A3 + ((size_t)(b * N_ + k)) * N_;
    const float4* row4 = (const float4*)row;
    const float4* dv4 = (const float4*)dv;
    float s = 0.f;
    for (int m = tid; m < (cnp >> 2); m += 256) {
        float4 a = row4[m], w = dv4[m];
        s += a.x * w.x + a.y * w.y + a.z * w.z + a.w * w.w;
    }
    red[tid] = s; __syncthreads();
    for (int o = 128; o > 0; o >>= 1) { if (tid < o) red[tid] += red[tid + o]; __syncthreads(); }
    if (tid == 0)
        wv[b * N_ + k] = d2[b * N_ + k] * (red[0] - row[k] * dv[k] + dv[k]);
}

// p2 partial: sum_k wv[k]*xW[k,:] over k-chunk q
__global__ void out2_part_kernel(const float* __restrict__ xW, const float* __restrict__ wv,
                                 const int* __restrict__ cnt, float* __restrict__ p2) {
    int b = blockIdx.y, q = blockIdx.x, c = threadIdx.x;   // 256 threads
    int cnp = (cnt[b] + 127) & ~127;
    int lo = q * 512, hi = (q + 1) * 512; if (hi > cnp) hi = cnp;
    float s = 0.f;
    for (int k = lo; k < hi; k++)
        s = fmaf(wv[b * N_ + k], xW[((size_t)(b * N_ + k)) * F_ + c], s);
    p2[(b * 4 + q) * F_ + c] = s;
}

// generic transposed split: out[j][i] = in[i][j]; in R x C (ld), out stride N_
__global__ void split_tr_kernel(const float* __restrict__ in, __nv_bfloat16* __restrict__ hi,
                                __nv_bfloat16* __restrict__ lo, const int* __restrict__ cnt,
                                int Rfixed, int Cfixed, int ld, long sIn, long sOut) {
    __shared__ float tile[32][33];
    int b = blockIdx.z;
    int cnp = (cnt[b] + 127) & ~127;
    int R = Rfixed ? Rfixed : cnp;
    int C = Cfixed ? Cfixed : cnp;
    int i0 = blockIdx.y * 32, j0 = blockIdx.x * 32;
    if (i0 >= R || j0 >= C) return;
    const float* inb = in + (size_t)b * sIn;
    size_t boff = (size_t)b * sOut;
    int tx = threadIdx.x, ty = threadIdx.y;   // (32, 8)
    #pragma unroll
    for (int r = 0; r < 4; r++) {
        int i = ty + r * 8;
        tile[i][tx] = inb[(size_t)(i0 + i) * ld + j0 + tx];
    }
    __syncthreads();
    #pragma unroll
    for (int r = 0; r < 4; r++) {
        int j = ty + r * 8;
        float v = tile[tx][j];
        __nv_bfloat16 h = __float2bfloat16(v);
        size_t o = boff + (size_t)(j0 + j) * N_ + i0 + tx;
        hi[o] = h;
        lo[o] = __float2bfloat16(v - __bfloat162float(h));
    }
}

// ---------------- bf16-split tensor GEMM, single-K-pass ----------------------
#define TSZ (128 * 40)
template<int EPI>
__global__ void __launch_bounds__(256, 2) gemm_bf16_kernel(
    const __nv_bfloat16* __restrict__ Ahi, const __nv_bfloat16* __restrict__ Alo,
    const __nv_bfloat16* __restrict__ BThi, const __nv_bfloat16* __restrict__ BTlo,
    float* __restrict__ C, const int* __restrict__ cnt,
    int ldc, long sC,
    __nv_bfloat16* __restrict__ Chi, __nv_bfloat16* __restrict__ Clo,
    const __nv_bfloat16* __restrict__ B2hi, const __nv_bfloat16* __restrict__ B2lo,
    float* __restrict__ C2, int ldc2, long sC2) {
    extern __shared__ __nv_bfloat16 sm[];   // [2 stages][4 tiles][128*40]
    const int b = blockIdx.z;
    const int cnp = (cnt[b] + 127) & ~127;
    const int m0 = blockIdx.y * 128;
    const int n0 = blockIdx.x * 128;
    const bool reg2 = (EPI == 4) && (blockIdx.x == gridDim.x - 1);
    if (m0 >= cnp) return;
    if (!reg2) {
        if (n0 >= cnp) return;
        if (EPI == 5 && m0 > n0) return;   // symmetric: upper-triangle blocks only
    }
    const size_t boff = (size_t)b * N_ * N_;
    const int tid = threadIdx.x;
    const int wid = tid >> 5, lane = tid & 31;
    const int wm = wid >> 1, wn = wid & 1;
    const int g = lane >> 2, t4 = lane & 3;
    const int a_row = lane & 15;
    const int a_k   = (lane & 16) ? 8 : 0;
    const int b_row = (lane & 7) + ((lane & 16) ? 8 : 0);
    const int b_k   = (lane & 8) ? 8 : 0;
    const int KT = cnp >> 5;

    float acc[2][8][4];
    #pragma unroll
    for (int fm = 0; fm < 2; fm++)
        #pragma unroll
        for (int fn = 0; fn < 8; fn++)
            #pragma unroll
            for (int r = 0; r < 4; r++) acc[fm][fn][r] = 0.f;

    const __nv_bfloat16* gsrc[4];
    auto stage = [&](int kt, int buf) {
        gsrc[0] = Ahi + boff + (size_t)m0 * N_ + kt * 32;
        gsrc[1] = Alo + boff + (size_t)m0 * N_ + kt * 32;
        if (reg2) {
            gsrc[2] = B2hi + (size_t)b * H_ * N_ + kt * 32;
            gsrc[3] = B2lo + (size_t)b * H_ * N_ + kt * 32;
        } else {
            gsrc[2] = BThi + boff + (size_t)n0 * N_ + kt * 32;
            gsrc[3] = BTlo + boff + (size_t)n0 * N_ + kt * 32;
        }
        int row = tid >> 2, cc = (tid & 3) * 8;
        #pragma unroll
        for (int w = 0; w < 4; w++) {
            __nv_bfloat16* dst = sm + (size_t)(buf * 4 + w) * TSZ;
            CP16(dst + row * 40 + cc,        gsrc[w] + (size_t)row * N_ + cc);
            CP16(dst + (row + 64) * 40 + cc, gsrc[w] + (size_t)(row + 64) * N_ + cc);
        }
    };

    stage(0, 0);
    CP_COMMIT();

    for (int t = 0; t < KT; t++) {
        CP_WAIT0();
        __syncthreads();
        if (t + 1 < KT) { stage(t + 1, (t + 1) & 1); CP_COMMIT(); }
        const __nv_bfloat16* Ah = sm + (size_t)((t & 1) * 4 + 0) * TSZ;
        const __nv_bfloat16* Al = sm + (size_t)((t & 1) * 4 + 1) * TSZ;
        const __nv_bfloat16* Bh = sm + (size_t)((t & 1) * 4 + 2) * TSZ;
        const __nv_bfloat16* Bl = sm + (size_t)((t & 1) * 4 + 3) * TSZ;
        #pragma unroll
        for (int kh = 0; kh < 32; kh += 16) {
            uint32_t ah[2][4], al[2][4];
            #pragma unroll
            for (int fm = 0; fm < 2; fm++) {
                int ao = (wm * 32 + fm * 16 + a_row) * 40 + kh + a_k;
                ldsm4(ah[fm], Ah + ao);
                ldsm4(al[fm], Al + ao);
            }
            #pragma unroll
            for (int fn2 = 0; fn2 < 4; fn2++) {
                int bo = (wn * 64 + fn2 * 16 + b_row) * 40 + kh + b_k;
                uint32_t bh[4], bl[4];
                ldsm4(bh, Bh + bo);
                ldsm4(bl, Bl + bo);
                #pragma unroll
                for (int fm = 0; fm < 2; fm++) {
                    mma_bf16(acc[fm][2 * fn2],     ah[fm], bh[0], bh[1]);
                    mma_bf16(acc[fm][2 * fn2],     ah[fm], bl[0], bl[1]);
                    mma_bf16(acc[fm][2 * fn2],     al[fm], bh[0], bh[1]);
                    mma_bf16(acc[fm][2 * fn2 + 1], ah[fm], bh[2], bh[3]);
                    mma_bf16(acc[fm][2 * fn2 + 1], ah[fm], bl[2], bl[3]);
                    mma_bf16(acc[fm][2 * fn2 + 1], al[fm], bh[2], bh[3]);
                }
            }
        }
        __syncthreads();
    }

    float* smf = (float*)sm;   // EPI==5: 128x133 fp32 transpose staging
    #pragma unroll
    for (int fm = 0; fm < 2; fm++) {
        int mr = m0 + wm * 32 + fm * 16 + g;
        #pragma unroll
        for (int fn = 0; fn < 8; fn++) {
            int lc = wn * 64 + fn * 8 + t4 * 2;
            float v0 = acc[fm][fn][0], v1 = acc[fm][fn][1];
            float v2 = acc[fm][fn][2], v3 = acc[fm][fn][3];
            if (reg2) {
                float* p0 = C2 + (size_t)b * sC2 + (size_t)mr * ldc2 + lc;
                p0[0] = v0; p0[1] = v1;
                float* p1 = p0 + 8 * (size_t)ldc2;
                p1[0] = v2; p1[1] = v3;
            } else if (EPI == 5) {
                v0 = floorf(v0 * 10000.f) / 10000.f;
                v1 = floorf(v1 * 10000.f) / 10000.f;
                v2 = floorf(v2 * 10000.f) / 10000.f;
                v3 = floorf(v3 * 10000.f) / 10000.f;
                int r = wm * 32 + fm * 16 + g;
                smf[(lc    ) * 133 + r]     = v0;
                smf[(lc + 1) * 133 + r]     = v1;
                smf[(lc    ) * 133 + r + 8] = v2;
                smf[(lc + 1) * 133 + r + 8] = v3;
                int n = n0 + lc;
                float* p0 = C + (size_t)b * sC + (size_t)mr * ldc + n;
                p0[0] = v0; p0[1] = v1;
                float* p1 = p0 + 8 * (size_t)ldc;
                p1[0] = v2; p1[1] = v3;
            } else {   // EPI 4 region 1: bf16 split out
                int n = n0 + lc;
                size_t o0 = (size_t)b * sC + (size_t)mr * ldc + n;
                size_t o1 = o0 + 8 * (size_t)ldc;
                __nv_bfloat162 h0 = split_hi2(v0, v1), h1 = split_hi2(v2, v3);
                *(__nv_bfloat162*)(Chi + o0) = h0;
                *(__nv_bfloat162*)(Chi + o1) = h1;
                *(__nv_bfloat162*)(Clo + o0) = split_lo2(v0, v1, h0);
                *(__nv_bfloat162*)(Clo + o1) = split_lo2(v2, v3, h1);
            }
        }
    }
    if (EPI == 5 && m0 != n0) {
        __syncthreads();
        float* Cb = C + (size_t)b * sC;
        for (int e = tid; e < 128 * 128; e += 256) {
            int r2 = e >> 7, c2 = e & 127;
            Cb[(size_t)(n0 + r2) * ldc + m0 + c2] = smf[r2 * 133 + c2];
        }
    }
}

// ---------------- double-buffered cp.async SIMT GEMM (small GEMMs) -----------
template<int TRANSA, int EPI>
__global__ void __launch_bounds__(256, 2) gemm2_kernel(
    const float* __restrict__ A, const float* __restrict__ Bm, float* __restrict__ C,
    int M, int Kd, int Nc, int lda, int ldb, int ldc,
    long sA, long sB, long sC,
    const float* __restrict__ bias, const float* __restrict__ mask,
    const int* __restrict__ cnt, int dynM, int dynK, int dynN) {
    __shared__ float As[2][128 * 16];
    __shared__ float Bs[2][16 * 128];
    const int b = blockIdx.z;
    int Mp = M, Kp = Kd, Np = Nc;
    if (cnt) {
        int p = (cnt[b] + 127) & ~127;
        if (dynM) Mp = p; if (dynK) Kp = p; if (dynN) Np = p;
    }
    const int n0 = blockIdx.x * 128, m0 = blockIdx.y * 128;
    if (m0 >= Mp || n0 >= Np) return;
    A  += (size_t)b * sA;
    Bm += (size_t)b * sB;
    C  += (size_t)b * sC;
    const int tid = threadIdx.x, tx = tid & 15, ty = tid >> 4;
    float acc[8][8];
    #pragma unroll
    for (int i = 0; i < 8; i++)
        #pragma unroll
        for (int j = 0; j < 8; j++) acc[i][j] = 0.f;

    const int Kt = Kp >> 4;

    auto load_tiles = [&](int k0, int buf) {
        if (!TRANSA) {
            #pragma unroll
            for (int q = 0; q < 2; q++) {
                int c = tid + q * 256;
                int row = c >> 2, col4 = (c & 3) * 4;
                const float* src = A + (size_t)(m0 + row) * lda + k0 + col4;
                CP16(&As[buf][row * 16 + col4], src);
            }
        } else {
            #pragma unroll
            for (int q = 0; q < 2; q++) {
                int c = tid + q * 256;
                int row = c >> 5, col4 = (c & 31) * 4;
                const float* src = A + (size_t)(k0 + row) * lda + m0 + col4;
                CP16(&As[buf][row * 128 + col4], src);
            }
        }
        #pragma unroll
        for (int q = 0; q < 2; q++) {
            int c = tid + q * 256;
            int row = c >> 5, col4 = (c & 31) * 4;
            const float* src = Bm + (size_t)(k0 + row) * ldb + n0 + col4;
            CP16(&Bs[buf][row * 128 + col4], src);
        }
    };

    load_tiles(0, 0);
    CP_COMMIT();

    for (int t = 0; t < Kt; t++) {
        CP_WAIT0();
        __syncthreads();
        if (t + 1 < Kt) { load_tiles((t + 1) << 4, (t + 1) & 1); CP_COMMIT(); }
        const int buf = t & 1;
        #pragma unroll
        for (int k = 0; k < 16; k++) {
            float a[8], bv[8];
            if (!TRANSA) {
                #pragma unroll
                for (int i = 0; i < 8; i++) a[i] = As[buf][(ty * 8 + i) * 16 + k];
            } else {
                *(float4*)(a)     = *(const float4*)&As[buf][k * 128 + ty * 8];
                *(float4*)(a + 4) = *(const float4*)&As[buf][k * 128 + ty * 8 + 4];
            }
            *(float4*)(bv)     = *(const float4*)&Bs[buf][k * 128 + tx * 8];
            *(float4*)(bv + 4) = *(const float4*)&Bs[buf][k * 128 + tx * 8 + 4];
            #pragma unroll
            for (int i = 0; i < 8; i++)
                #pragma unroll
                for (int j = 0; j < 8; j++) acc[i][j] = fmaf(a[i], bv[j], acc[i][j]);
        }
        __syncthreads();
    }
    #pragma unroll
    for (int i = 0; i < 8; i++) {
        int m = m0 + ty * 8 + i;
        float mk = (EPI == 2) ? mask[(size_t)b * N_ + m] : 1.f;
        #pragma unroll
        for (int j = 0; j < 8; j++) {
            int n = n0 + tx * 8 + j;
            float v = acc[i][j];
            if (EPI == 2)      { v = (v + bias[n]) * mk; }
            else if (EPI == 3) { v = floorf(v * 10000.f) / 10000.f; }
            C[(size_t)m * ldc + n] = v;
        }
    }
}

// ---------------- output means (two-stage, deterministic) --------------------
__global__ void mean1_part_kernel(const float* __restrict__ x1, float* __restrict__ p1) {
    int b = blockIdx.y, q = blockIdx.x, c = threadIdx.x;   // 128 threads
    float s = 0.f;
    for (int n = q * 512; n < (q + 1) * 512; n++) s += x1[((size_t)(b * N_ + n)) * H_ + c];
    p1[(b * 4 + q) * H_ + c] = s;
}

__global__ void mean_combine_kernel(const float* __restrict__ p1, const float* __restrict__ p2,
                                    const float* __restrict__ b2, const float* __restrict__ smask,
                                    float* __restrict__ out) {
    int b = blockIdx.x, c = threadIdx.x;   // 384 threads
    if (c < H_) {
        float s = 0.f;
        for (int q = 0; q < 4; q++) s += p1[(b * 4 + q) * H_ + c];
        out[b * OUTC + c] = s / (float)N_;
    } else {
        int cc = c - H_;
        float s = b2[cc] * smask[b];
        for (int q = 0; q < 4; q++) s += p2[(b * 4 + q) * F_ + cc];
        out[b * OUTC + c] = s / (float)N_;
    }
}

extern "C" void kernel_launch(void* const* d_in, const int* in_sizes, int n_in,
                              void* d_out, int out_size) {
    const float* x    = (const float*)d_in[0];
    const float* adj  = (const float*)d_in[1];
    const float* mask = (const float*)d_in[2];
    const float* W1   = (const float*)d_in[3];
    const float* b1   = (const float*)d_in[4];
    const float* Watt = (const float*)d_in[5];
    const float* batt = (const float*)d_in[6];
    const float* W2   = (const float*)d_in[7];
    const float* b2   = (const float*)d_in[8];
    float* out = (float*)d_out;

    float *pT,*pAc,*pA3,*pxW,*px1,*pxc,*px3;
    float *pv,*palp,*pca,*psrec,*pd0,*pd1,*prnz,*pd2,*prz2,*pcut,*pmaskc,*pmrest,*pp1,*pp2;
    __nv_bfloat16 *pAhi,*pAlo,*pSThi,*pSTlo,*pTThi,*pTTlo,*pxTh,*pxTl;
    int *plst,*pdeg,*phasd,*pidx,*pginv,*pcnt;
    cudaGetSymbolAddress((void**)&pT,   g_T);
    cudaGetSymbolAddress((void**)&pAc,  g_Ac);
    cudaGetSymbolAddress((void**)&pA3,  g_A3);
    cudaGetSymbolAddress((void**)&pAhi, g_Ahi);
    cudaGetSymbolAddress((void**)&pAlo, g_Alo);
    cudaGetSymbolAddress((void**)&pSThi,g_SThi);
    cudaGetSymbolAddress((void**)&pSTlo,g_STlo);
    cudaGetSymbolAddress((void**)&pTThi,g_TThi);
    cudaGetSymbolAddress((void**)&pTTlo,g_TTlo);
    cudaGetSymbolAddress((void**)&pxTh, g_xTh);
    cudaGetSymbolAddress((void**)&pxTl, g_xTl);
    cudaGetSymbolAddress((void**)&pxW,  g_xW);
    cudaGetSymbolAddress((void**)&px1,  g_x1);
    cudaGetSymbolAddress((void**)&pxc,  g_xc);
    cudaGetSymbolAddress((void**)&px3,  g_x3);
    cudaGetSymbolAddress((void**)&pv,   g_v);
    cudaGetSymbolAddress((void**)&palp, g_alp);
    cudaGetSymbolAddress((void**)&pca,  g_ca);
    cudaGetSymbolAddress((void**)&psrec,g_srec);
    cudaGetSymbolAddress((void**)&pd0,  g_d0);
    cudaGetSymbolAddress((void**)&pd1,  g_d1);
    cudaGetSymbolAddress((void**)&prnz, g_rnz);
    cudaGetSymbolAddress((void**)&pd2,  g_d2);
    cudaGetSymbolAddress((void**)&prz2, g_rz2);
    cudaGetSymbolAddress((void**)&pcut, g_cut);
    cudaGetSymbolAddress((void**)&pmaskc, g_maskc);
    cudaGetSymbolAddress((void**)&pmrest, g_mrest);
    cudaGetSymbolAddress((void**)&pp1,  g_p1);
    cudaGetSymbolAddress((void**)&pp2,  g_p2);
    cudaGetSymbolAddress((void**)&plst, g_lst);
    cudaGetSymbolAddress((void**)&pdeg, g_deg);
    cudaGetSymbolAddress((void**)&phasd,g_hasd);
    cudaGetSymbolAddress((void**)&pidx, g_idx);
    cudaGetSymbolAddress((void**)&pginv,g_ginv);
    cudaGetSymbolAddress((void**)&pcnt, g_cnt);

    const int BF16_SMEM = 2 * 4 * TSZ * 2;   // 81920 bytes
    cudaFuncSetAttribute(gemm_bf16_kernel<4>, cudaFuncAttributeMaxDynamicSharedMemorySize, BF16_SMEM);
    cudaFuncSetAttribute(gemm_bf16_kernel<5>, cudaFuncAttributeMaxDynamicSharedMemorySize, BF16_SMEM);

    // ---- CSR + degree stats (single adj scan) ----
    csr_build_kernel<<<dim3(N_, B_), 256>>>(adj, plst, pdeg, phasd, pd0, pd1, prnz);

    // ---- GCN layer 1 (sparse aggregation) ----
    gemm2_kernel<0,0><<<dim3(1,16,B_),256>>>(x, W1, pxW, N_, F_, H_, F_, H_, H_,
        (long)N_*F_, 0, (long)N_*H_, nullptr, nullptr, nullptr, 0,0,0);
    gcn1_kernel<<<dim3(N_, B_), 128>>>(plst, pdeg, pd0, pxW, b1, mask, px1);

    // ---- coarsen layer 1 (sparse, no dense S anywhere) ----
    gemv_watt_kernel<<<(B_*N_)/8, 256>>>(px1, Watt, batt, pv);
    alpha1_kernel<<<dim3(N_/8, B_), 256>>>(plst, pdeg, pd1, prnz, pv, palp);
    topk_cut_kernel<<<B_, 1024>>>(palp, pcut);
    ca_kernel<<<(B_*N_)/256, 256>>>(palp, pcut, pca);
    compact_kernel<<<B_, 1024>>>(pca, pidx, pginv, pcnt);
    compact_mask_kernel<<<B_, 256>>>(mask, pidx, pcnt, pmaskc, pmrest);
    srec_kernel<<<dim3(N_/8, B_), 256>>>(plst, pdeg, pd1, prnz, pca, psrec);
    xupd_kernel<<<dim3(N_, B_), 128>>>(plst, pdeg, phasd, pd1, pca, psrec, pidx, pcnt, px1, pxc);
    adjS_sparse_kernel<<<dim3(N_/4, B_), 128>>>(plst, pdeg, phasd, pd1, pca, psrec,
                                                pginv, pcnt, pT);
    // Ac + fused bf16 split + fused d2/rz2 row stats (register accumulators)
    STT_kernel<<<dim3(N_, B_), 256>>>(plst, pdeg, phasd, pd1, pca, psrec, pidx, pcnt,
                                      pT, pAc, pAhi, pAlo, pd2, prz2);

    // ---- coarsen layer 2 (symmetric Ac: direct row-major ST build) ----
    gemv_watt_kernel<<<(B_*N_)/8, 256>>>(pxc, Watt, batt, pv);
    alpha2d_kernel<<<dim3(N_, B_), 256>>>(pAc, pd2, prz2, pv, pcnt, palp);
    topk_cut_kernel<<<B_, 1024>>>(palp, pcut);
    ca_kernel<<<(B_*N_)/256, 256>>>(palp, pcut, pca);
    s2inv_kernel<<<dim3(N_, B_), 256>>>(pAc, pd2, prz2, pca, pcnt, psrec);
    buildST_kernel<<<dim3(N_, B_), 256>>>(pAc, pd2, pca, psrec, pcnt, pSThi, pSTlo);
    split_tr_kernel<<<dim3(4, 64, B_), dim3(32, 8)>>>(pxc, pxTh, pxTl, pcnt,
        0, H_, H_, (long)N_*H_, (long)H_*N_);
    // MERGED: T2^T = ST @ Ac^T (bf16 split -> TT)  AND  x3 = ST @ xc (fp32)
    gemm_bf16_kernel<4><<<dim3(17,16,B_),256,BF16_SMEM>>>(pSThi, pSTlo, pAhi, pAlo,
        nullptr, pcnt, N_, (long)N_*N_, pTThi, pTTlo,
        pxTh, pxTl, px3, H_, (long)N_*H_);
    // A3 = ST @ T2 (symmetric): upper blocks only, floor-quant, mirror write
    gemm_bf16_kernel<5><<<dim3(16,16,B_),256,BF16_SMEM>>>(pSThi, pSTlo, pTThi, pTTlo,
        pA3, pcnt, N_, (long)N_*N_, nullptr, nullptr,
        nullptr, nullptr, nullptr, 0, 0);

    // ---- final GCN: only the column mean is needed ----
    rowstats_c_kernel<<<dim3(N_, B_), 256>>>(pA3, pcnt, pd2, nullptr, 0);
    gemm2_kernel<0,0><<<dim3(2,16,B_),256>>>(px3, W2, pxW, N_, H_, F_, H_, F_, F_,
        (long)N_*H_, 0, (long)N_*F_, nullptr, nullptr, pcnt, 1,0,0);
    wvec_kernel<<<dim3(N_, B_), 256>>>(pA3, pd2, pmaskc, pcnt, pv);
    out2_part_kernel<<<dim3(4, B_), 256>>>(pxW, pv, pcnt, pp2);

    // ---- concat means ----
    mean1_part_kernel<<<dim3(4, B_), 128>>>(px1, pp1);
    mean_combine_kernel<<<B_, 384>>>(pp1, pp2, b2, pmrest, out);
}

// round 14
// speedup vs baseline: 8.5177x; 1.0302x over previous
#include <cuda_runtime.h>
#include <cuda_bf16.h>
#include <math.h>
#include <stdint.h>

#define B_ 8
#define N_ 2048
#define F_ 256
#define H_ 128
#define K_ 1025
#define OUTC 384
#define CAP 256

// ---------------- scratch (device globals; no allocation allowed) ----------
__device__ float g_T [(size_t)B_*N_*N_];
__device__ float g_Ac[(size_t)B_*N_*N_];
__device__ float g_A3[(size_t)B_*N_*N_];
__device__ __nv_bfloat16 g_Ahi[(size_t)B_*N_*N_], g_Alo[(size_t)B_*N_*N_];
__device__ __nv_bfloat16 g_SThi[(size_t)B_*N_*N_], g_STlo[(size_t)B_*N_*N_];
__device__ __nv_bfloat16 g_TThi[(size_t)B_*N_*N_], g_TTlo[(size_t)B_*N_*N_];
__device__ __nv_bfloat16 g_xTh[B_*H_*N_], g_xTl[B_*H_*N_];
__device__ float g_xW [B_*N_*F_];
__device__ float g_x1 [B_*N_*H_];
__device__ float g_xc [B_*N_*H_];
__device__ float g_x3 [B_*N_*H_];
__device__ int   g_lst[(size_t)B_*N_*CAP];
__device__ int   g_deg[B_*N_];
__device__ int   g_hasd[B_*N_];
__device__ float g_d0[B_*N_], g_d1[B_*N_], g_rnz[B_*N_];
__device__ float g_d2[B_*N_], g_rz2[B_*N_];
__device__ float g_v[B_*N_], g_alp[B_*N_], g_ca[B_*N_], g_srec[B_*N_];
__device__ float g_cut[B_];
__device__ float g_maskc[B_*N_], g_mrest[B_];
__device__ int   g_idx[B_*N_], g_ginv[B_*N_], g_cnt[B_];
__device__ float g_p1[B_*4*H_], g_p2[B_*4*F_];

// ---------------- async-copy / mma helpers -----------------------------------
#define CP16(dst, src) { \
    unsigned _a = (unsigned)__cvta_generic_to_shared(dst); \
    asm volatile("cp.async.cg.shared.global [%0], [%1], 16;\n" :: "r"(_a), "l"(src)); }
#define CP_COMMIT() asm volatile("cp.async.commit_group;\n")
#define CP_WAIT0()  asm volatile("cp.async.wait_group 0;\n")

__device__ __forceinline__ void mma_bf16(float* c, const uint32_t* a, uint32_t b0, uint32_t b1) {
    asm volatile("mma.sync.aligned.m16n8k16.row.col.f32.bf16.bf16.f32 "
        "{%0,%1,%2,%3}, {%4,%5,%6,%7}, {%8,%9}, {%0,%1,%2,%3};"
        : "+f"(c[0]), "+f"(c[1]), "+f"(c[2]), "+f"(c[3])
        : "r"(a[0]), "r"(a[1]), "r"(a[2]), "r"(a[3]), "r"(b0), "r"(b1));
}
__device__ __forceinline__ void ldsm4(uint32_t* r, const void* p) {
    uint32_t a = (uint32_t)__cvta_generic_to_shared(p);
    asm volatile("ldmatrix.sync.aligned.m8n8.x4.shared.b16 {%0,%1,%2,%3}, [%4];"
        : "=r"(r[0]), "=r"(r[1]), "=r"(r[2]), "=r"(r[3]) : "r"(a));
}
__device__ __forceinline__ __nv_bfloat162 split_hi2(float v0, float v1) {
    __nv_bfloat162 h; h.x = __float2bfloat16(v0); h.y = __float2bfloat16(v1); return h;
}
__device__ __forceinline__ __nv_bfloat162 split_lo2(float v0, float v1, __nv_bfloat162 h) {
    __nv_bfloat162 l;
    l.x = __float2bfloat16(v0 - __bfloat162float(h.x));
    l.y = __float2bfloat16(v1 - __bfloat162float(h.y));
    return l;
}

// ---------------- CSR build + degree stats (one adj scan, float4) -----------
__global__ void csr_build_kernel(const float* __restrict__ adj, int* __restrict__ lst,
                                 int* __restrict__ deg, int* __restrict__ hasd,
                                 float* __restrict__ d0, float* __restrict__ d1,
                                 float* __restrict__ rnz) {
    __shared__ int sc[256];
    __shared__ int hd;
    int b = blockIdx.y, i = blockIdx.x, tid = threadIdx.x;
    const float4* arow4 = (const float4*)(adj + ((size_t)(b * N_ + i)) * N_);
    if (tid == 0) hd = 0;
    __syncthreads();
    float vals[8];
    *(float4*)(vals)     = arow4[tid * 2];
    *(float4*)(vals + 4) = arow4[tid * 2 + 1];
    int f[8];
    int c = 0, hloc = 0;
    #pragma unroll
    for (int e = 0; e < 8; e++) {
        int j = tid * 8 + e;
        f[e] = (vals[e] != 0.f) ? 1 : 0;
        c += f[e];
        if (f[e] && j == i) hloc = 1;
    }
    if (hloc) hd = 1;
    sc[tid] = c; __syncthreads();
    for (int o = 1; o < 256; o <<= 1) {
        int v = (tid >= o) ? sc[tid - o] : 0; __syncthreads();
        sc[tid] += v; __syncthreads();
    }
    int base = sc[tid] - c;
    int* l = lst + ((size_t)(b * N_ + i)) * CAP;
    #pragma unroll
    for (int e = 0; e < 8; e++) {
        if (f[e]) { if (base < CAP) l[base] = tid * 8 + e; base++; }
    }
    __syncthreads();
    if (tid == 0) {
        int total = sc[255];
        deg[b * N_ + i] = (total > CAP) ? CAP : total;
        hasd[b * N_ + i] = hd;
        d0[b * N_ + i] = rsqrtf(fmaxf((float)(total - hd) + 1.f, 1.f));
        d1[b * N_ + i] = rsqrtf((float)total + 1.f);
        rnz[b * N_ + i] = (total > 0) ? 1.f : 0.f;
    }
}

// ------- GCN layer 1 sparse aggregation (staged coef lists) -----------------
__global__ void gcn1_kernel(const int* __restrict__ lst, const int* __restrict__ deg,
                            const float* __restrict__ d0, const float* __restrict__ xW,
                            const float* __restrict__ b1, const float* __restrict__ mask,
                            float* __restrict__ x1) {
    __shared__ int   jl[CAP];
    __shared__ float cf[CAP];
    int b = blockIdx.y, i = blockIdx.x, c = threadIdx.x;   // 128 threads
    int dg = deg[b * N_ + i];
    const int* l = lst + ((size_t)(b * N_ + i)) * CAP;
    float di = d0[b * N_ + i];
    for (int p = c; p < dg; p += 128) {
        int j = l[p];
        jl[p] = j;
        cf[p] = (j == i) ? 0.f : di * d0[b * N_ + j];
    }
    __syncthreads();
    float acc = di * di * xW[((size_t)(b * N_ + i)) * H_ + c];
    #pragma unroll 4
    for (int p = 0; p < dg; p++)
        acc = fmaf(cf[p], xW[((size_t)(b * N_ + jl[p])) * H_ + c], acc);
    float vv = (acc + b1[c]) * mask[b * N_ + i];
    x1[((size_t)(b * N_ + i)) * H_ + c] = fmaxf(vv, 0.f);
}

// ---------------- v = x @ Watt + batt ----------------------------------------
__global__ void gemv_watt_kernel(const float* __restrict__ x, const float* __restrict__ Watt,
                                 const float* __restrict__ batt, float* __restrict__ v) {
    int w = blockIdx.x * 8 + (threadIdx.x >> 5);
    int lane = threadIdx.x & 31;
    if (w >= B_ * N_) return;
    const float* xr = x + (size_t)w * H_;
    float s = 0.f;
    #pragma unroll
    for (int c = lane; c < H_; c += 32) s += xr[c] * Watt[c];
    #pragma unroll
    for (int o = 16; o > 0; o >>= 1) s += __shfl_down_sync(0xffffffffu, s, o);
    if (lane == 0) v[w] = s + batt[0];
}

// ---------------- layer-1 alpha (sparse) --------------------------------------
__global__ void alpha1_kernel(const int* __restrict__ lst, const int* __restrict__ deg,
                              const float* __restrict__ d1, const float* __restrict__ rnz,
                              const float* __restrict__ v, float* __restrict__ alp) {
    int b = blockIdx.y;
    int i = blockIdx.x * 8 + (threadIdx.x >> 5);
    int lane = threadIdx.x & 31;
    const int* l = lst + ((size_t)(b * N_ + i)) * CAP;
    int dg = deg[b * N_ + i];
    float s = 0.f;
    for (int p = lane; p < dg; p += 32) { int j = l[p]; s += d1[b * N_ + j] * v[b * N_ + j]; }
    #pragma unroll
    for (int o = 16; o > 0; o >>= 1) s += __shfl_down_sync(0xffffffffu, s, o);
    if (lane == 0) {
        float di = d1[b * N_ + i];
        float r = rnz[b * N_ + i] * di * (s + di * v[b * N_ + i]);
        float z = r * r;
        alp[b * N_ + i] = 1.f / (1.f + expf(-z));
    }
}

// ---- exact K-th largest via 4-pass radix select (alpha in (0,1): positive) --
// cut = ascending order statistic s[N_-K_]; counts via shared atomics are
// order-independent -> deterministic, identical multiset result to a sort.
__global__ void topk_cut_kernel(const float* __restrict__ alp, float* __restrict__ cut) {
    __shared__ int hist[256];
    __shared__ unsigned pref;
    __shared__ int rem;
    int b = blockIdx.x, t = threadIdx.x;   // 1024 threads
    unsigned v0 = __float_as_uint(alp[b * N_ + t]);
    unsigned v1 = __float_as_uint(alp[b * N_ + t + 1024]);
    if (t == 0) { pref = 0u; rem = N_ - K_ + 1; }   // rank = 1024th smallest (1-based)
    __syncthreads();
    #pragma unroll
    for (int pass = 0; pass < 4; pass++) {
        int shift = 24 - pass * 8;
        if (t < 256) hist[t] = 0;
        __syncthreads();
        unsigned maskA = (pass == 0) ? 0u : (0xFFFFFFFFu << (shift + 8));
        unsigned pr = pref;
        if ((v0 & maskA) == pr) atomicAdd(&hist[(v0 >> shift) & 255], 1);
        if ((v1 & maskA) == pr) atomicAdd(&hist[(v1 >> shift) & 255], 1);
        __syncthreads();
        if (t == 0) {
            int r = rem;
            unsigned bin = 0;
            #pragma unroll 8
            for (int q = 0; q < 256; q++) {
                int h = hist[q];
                if (r - h <= 0) { bin = q; break; }
                r -= h;
            }
            rem = r;
            pref = pr | (bin << shift);
        }
        __syncthreads();
    }
    if (t == 0) cut[b] = __uint_as_float(pref);
}

__global__ void ca_kernel(const float* __restrict__ alp, const float* __restrict__ cut,
                          float* __restrict__ ca) {
    int idx = blockIdx.x * 256 + threadIdx.x;
    int b = idx / N_;
    ca[idx] = fmaxf(alp[idx] + 1e-7f - cut[b], 0.f);
}

// ---------------- deterministic kept-set compaction (prefix scan) -----------
__global__ void compact_kernel(const float* __restrict__ ca, int* __restrict__ idx,
                               int* __restrict__ ginv, int* __restrict__ cnt) {
    __shared__ int sc[1024];
    int b = blockIdx.x, t = threadIdx.x;   // 1024 threads
    int f0 = (ca[b * N_ + 2 * t]     > 0.f) ? 1 : 0;
    int f1 = (ca[b * N_ + 2 * t + 1] > 0.f) ? 1 : 0;
    ginv[b * N_ + 2 * t] = -1;
    ginv[b * N_ + 2 * t + 1] = -1;
    int c = f0 + f1;
    sc[t] = c; __syncthreads();
    for (int o = 1; o < 1024; o <<= 1) {
        int v = (t >= o) ? sc[t - o] : 0; __syncthreads();
        sc[t] += v; __syncthreads();
    }
    int base = sc[t] - c;
    if (f0) { idx[b * N_ + base] = 2 * t;     ginv[b * N_ + 2 * t]     = base; base++; }
    if (f1) { idx[b * N_ + base] = 2 * t + 1; ginv[b * N_ + 2 * t + 1] = base; }
    if (t == 1023) cnt[b] = sc[1023];
}

__global__ void compact_mask_kernel(const float* __restrict__ mask, const int* __restrict__ idx,
                                    const int* __restrict__ cnt, float* __restrict__ maskc,
                                    float* __restrict__ mrest) {
    __shared__ float red[256];
    int b = blockIdx.x, t = threadIdx.x;
    int c = cnt[b];
    float local = 0.f;
    for (int i = t; i < N_; i += 256) {
        float mv = 0.f;
        if (i < c) mv = mask[b * N_ + idx[b * N_ + i]];
        maskc[b * N_ + i] = mv;
        local += mask[b * N_ + i];
    }
    red[t] = local; __syncthreads();
    for (int o = 128; o > 0; o >>= 1) { if (t < o) red[t] += red[t + o]; __syncthreads(); }
    if (t == 0) mrest[b] = red[0];
}

// ---------------- layer-1 S row normalizer -----------------------------------
__global__ void srec_kernel(const int* __restrict__ lst, const int* __restrict__ deg,
                            const float* __restrict__ d1, const float* __restrict__ rnz,
                            const float* __restrict__ ca, float* __restrict__ srec) {
    int b = blockIdx.y;
    int i = blockIdx.x * 8 + (threadIdx.x >> 5);
    int lane = threadIdx.x & 31;
    const int* l = lst + ((size_t)(b * N_ + i)) * CAP;
    int dg = deg[b * N_ + i];
    float s = 0.f;
    for (int p = lane; p < dg; p += 32) { int j = l[p]; s += d1[b * N_ + j] * ca[b * N_ + j]; }
    #pragma unroll
    for (int o = 16; o > 0; o >>= 1) s += __shfl_down_sync(0xffffffffu, s, o);
    if (lane == 0) {
        float di = d1[b * N_ + i];
        float raw = rnz[b * N_ + i] * di * (s + di * ca[b * N_ + i]);
        srec[b * N_ + i] = rnz[b * N_ + i] * di / fmaxf(raw, 1e-12f);
    }
}

// ---- xc[ic,:] = sum_n S[n, idx[ic]] * x1[n,:]  (staged lists) ---------------
__global__ void xupd_kernel(const int* __restrict__ lst, const int* __restrict__ deg,
                            const int* __restrict__ hasd, const float* __restrict__ d1,
                            const float* __restrict__ ca, const float* __restrict__ srec,
                            const int* __restrict__ idx, const int* __restrict__ cnt,
                            const float* __restrict__ x1, float* __restrict__ xc) {
    __shared__ int   jl[CAP + 1];
    __shared__ float sv[CAP + 1];
    int b = blockIdx.y, ic = blockIdx.x, c = threadIdx.x;   // 128 threads
    int cn = cnt[b], cnp = (cn + 127) & ~127;
    if (ic >= cnp) return;
    float* orow = xc + ((size_t)(b * N_ + ic)) * H_;
    if (ic >= cn) { orow[c] = 0.f; return; }
    int m = idx[b * N_ + ic];
    float dmcam = d1[b * N_ + m] * ca[b * N_ + m];
    int dg = deg[b * N_ + m];
    const int* l = lst + ((size_t)(b * N_ + m)) * CAP;
    for (int p = c; p < dg; p += 128) {
        int n = l[p];
        jl[p] = n;
        sv[p] = srec[b * N_ + n] * dmcam * ((n == m) ? 2.f : 1.f);
    }
    int dgE = dg + (hasd[b * N_ + m] ? 0 : 1);
    if (c == 0 && dgE > dg) { jl[dg] = m; sv[dg] = srec[b * N_ + m] * dmcam; }
    __syncthreads();
    float acc = 0.f;
    #pragma unroll 4
    for (int p = 0; p < dgE; p++)
        acc = fmaf(sv[p], x1[((size_t)(b * N_ + jl[p])) * H_ + c], acc);
    orow[c] = acc;
}

// ---- Tc[i,:] = sum_{j in list_i} S_row_j, S rows expanded on the fly --------
__global__ void adjS_sparse_kernel(const int* __restrict__ lst, const int* __restrict__ deg,
                                   const int* __restrict__ hasd, const float* __restrict__ d1,
                                   const float* __restrict__ ca, const float* __restrict__ srec,
                                   const int* __restrict__ ginv, const int* __restrict__ cnt,
                                   float* __restrict__ Tc) {
    __shared__ float acc[4][N_];
    int b = blockIdx.y, tid = threadIdx.x;   // 128 threads = 4 warps
    int w = tid >> 5, lane = tid & 31;
    int i = blockIdx.x * 4 + w;
    int cnp = (cnt[b] + 127) & ~127;
    float* a = acc[w];
    float4* a4 = (float4*)a;
    float4 z4 = make_float4(0.f, 0.f, 0.f, 0.f);
    for (int jc = lane; jc < (cnp >> 2); jc += 32) a4[jc] = z4;
    __syncwarp();
    int dgi = deg[b * N_ + i];
    const int* li = lst + ((size_t)(b * N_ + i)) * CAP;
    const int* gv = ginv + b * N_;
    for (int p = 0; p < dgi; p++) {
        int j = li[p];
        int dgj = deg[b * N_ + j];
        const int* lj = lst + ((size_t)(b * N_ + j)) * CAP;
        float sr = srec[b * N_ + j];
        for (int q = lane; q < dgj; q += 32) {
            int m = lj[q];
            int jc = gv[m];
            if (jc >= 0) {
                float coef = (m == j) ? 2.f : 1.f;
                a[jc] += sr * d1[b * N_ + m] * ca[b * N_ + m] * coef;
            }
        }
        __syncwarp();
        if (lane == 0 && !hasd[b * N_ + j]) {
            int jc = gv[j];
            if (jc >= 0) a[jc] += sr * d1[b * N_ + j] * ca[b * N_ + j];
        }
        __syncwarp();
    }
    float4* trow4 = (float4*)(Tc + (size_t)b * N_ * N_ + (size_t)i * cnp);
    for (int jc = lane; jc < (cnp >> 2); jc += 32) trow4[jc] = a4[jc];
}

// -- Ac row = floorq(sum S*Tc); REGISTER accumulators + staged coef lists -----
__global__ void STT_kernel(const int* __restrict__ lst, const int* __restrict__ deg,
                           const int* __restrict__ hasd, const float* __restrict__ d1,
                           const float* __restrict__ ca, const float* __restrict__ srec,
                           const int* __restrict__ idx, const int* __restrict__ cnt,
                           const float* __restrict__ Tc, float* __restrict__ Ac,
                           __nv_bfloat16* __restrict__ Achi, __nv_bfloat16* __restrict__ Aclo,
                           float* __restrict__ d2out, float* __restrict__ rz2out) {
    __shared__ int   nls[CAP + 1];
    __shared__ float svs[CAP + 1];
    __shared__ float red[256];
    int b = blockIdx.y, ic = blockIdx.x, tid = threadIdx.x;
    int cn = cnt[b], cnp = (cn + 127) & ~127, cnp4 = cnp >> 2;
    if (ic >= cnp) return;
    size_t rowoff = ((size_t)(b * N_ + ic)) * N_;
    float4* orow4 = (float4*)(Ac + rowoff);
    __nv_bfloat162* ohi = (__nv_bfloat162*)(Achi + rowoff);
    __nv_bfloat162* olo = (__nv_bfloat162*)(Aclo + rowoff);
    float4 z4 = make_float4(0.f, 0.f, 0.f, 0.f);
    if (ic >= cn) {
        __nv_bfloat162 zb; zb.x = __float2bfloat16(0.f); zb.y = zb.x;
        for (int jc = tid; jc < cnp4; jc += 256) {
            orow4[jc] = z4;
            ohi[jc * 2] = zb; ohi[jc * 2 + 1] = zb;
            olo[jc * 2] = zb; olo[jc * 2 + 1] = zb;
        }
        if (tid == 0) { d2out[b * N_ + ic] = 1.f; rz2out[b * N_ + ic] = 0.f; }
        return;
    }
    int m = idx[b * N_ + ic];
    float dmcam = d1[b * N_ + m] * ca[b * N_ + m];
    int dg = deg[b * N_ + m];
    const int* l = lst + ((size_t)(b * N_ + m)) * CAP;
    for (int p = tid; p < dg; p += 256) {
        int n = l[p];
        nls[p] = n;
        svs[p] = srec[b * N_ + n] * dmcam * ((n == m) ? 2.f : 1.f);
    }
    int dgE = dg + (hasd[b * N_ + m] ? 0 : 1);
    if (tid == 0 && dgE > dg) { nls[dg] = m; svs[dg] = srec[b * N_ + m] * dmcam; }
    __syncthreads();
    const float* Tb = Tc + (size_t)b * N_ * N_;
    int j0 = tid, j1 = tid + 256;
    bool h1 = (j1 < cnp4);
    float4 a0 = z4, a1 = z4;
    #pragma unroll 2
    for (int p = 0; p < dgE; p++) {
        float sv = svs[p];
        const float4* trow = (const float4*)(Tb + (size_t)nls[p] * cnp);
        float4 t0 = trow[j0];
        a0.x = fmaf(sv, t0.x, a0.x); a0.y = fmaf(sv, t0.y, a0.y);
        a0.z = fmaf(sv, t0.z, a0.z); a0.w = fmaf(sv, t0.w, a0.w);
        if (h1) {
            float4 t1 = trow[j1];
            a1.x = fmaf(sv, t1.x, a1.x); a1.y = fmaf(sv, t1.y, a1.y);
            a1.z = fmaf(sv, t1.z, a1.z); a1.w = fmaf(sv, t1.w, a1.w);
        }
    }
    float part = 0.f;
    #pragma unroll
    for (int r = 0; r < 2; r++) {
        int jc = (r == 0) ? j0 : j1;
        if (r == 1 && !h1) break;
        float4 a = (r == 0) ? a0 : a1;
        a.x = floorf(a.x * 10000.f) / 10000.f;
        a.y = floorf(a.y * 10000.f) / 10000.f;
        a.z = floorf(a.z * 10000.f) / 10000.f;
        a.w = floorf(a.w * 10000.f) / 10000.f;
        orow4[jc] = a;
        part += (a.x + a.y) + (a.z + a.w);
        __nv_bfloat162 h01 = split_hi2(a.x, a.y), h23 = split_hi2(a.z, a.w);
        ohi[jc * 2] = h01; ohi[jc * 2 + 1] = h23;
        olo[jc * 2] = split_lo2(a.x, a.y, h01); olo[jc * 2 + 1] = split_lo2(a.z, a.w, h23);
    }
    red[tid] = part; __syncthreads();
    for (int o = 128; o > 0; o >>= 1) { if (tid < o) red[tid] += red[tid + o]; __syncthreads(); }
    if (tid == 0) {
        float sum = red[0];
        d2out[b * N_ + ic] = rsqrtf(fmaxf(sum + 1.f, 1.f));
        rz2out[b * N_ + ic] = (sum > 0.f) ? 1.f : 0.f;
    }
}

// ---------------- layer-2 / final helpers ------------------------------------
__global__ void rowstats_c_kernel(const float* __restrict__ A, const int* __restrict__ cnt,
                                  float* __restrict__ dout, float* __restrict__ rnz, int mode) {
    int b = blockIdx.y, i = blockIdx.x, tid = threadIdx.x;
    int cnp = (cnt[b] + 127) & ~127;
    if (i >= cnp) return;
    const float* row = A + ((size_t)(b * N_ + i)) * N_;
    const float4* row4 = (const float4*)row;
    float s = 0.f;
    for (int j = tid; j < (cnp >> 2); j += 256) {
        float4 a = row4[j]; s += (a.x + a.y) + (a.z + a.w);
    }
    __shared__ float red[256];
    red[tid] = s; __syncthreads();
    for (int o = 128; o > 0; o >>= 1) { if (tid < o) red[tid] += red[tid + o]; __syncthreads(); }
    if (tid == 0) {
        float sum = red[0];
        if (mode == 0) {
            dout[b * N_ + i] = rsqrtf(fmaxf(sum - row[i] + 1.f, 1.f));
        } else {
            dout[b * N_ + i] = rsqrtf(fmaxf(sum + 1.f, 1.f));
            rnz[b * N_ + i] = (sum > 0.f) ? 1.f : 0.f;
        }
    }
}

__global__ void alpha2d_kernel(const float* __restrict__ Ac, const float* __restrict__ d2,
                               const float* __restrict__ rz2, const float* __restrict__ v,
                               const int* __restrict__ cnt, float* __restrict__ alp) {
    __shared__ float dv[N_];
    __shared__ float red[256];
    int b = blockIdx.y, n = blockIdx.x, tid = threadIdx.x;
    int cnp = (cnt[b] + 127) & ~127;
    if (n >= cnp) { if (tid == 0) alp[b * N_ + n] = 0.5f; return; }
    for (int m = tid; m < cnp; m += 256) dv[m] = d2[b * N_ + m] * v[b * N_ + m];
    __syncthreads();
    const float4* row4 = (const float4*)(Ac + ((size_t)(b * N_ + n)) * N_);
    const float4* dv4 = (const float4*)dv;
    float s = 0.f;
    for (int m = tid; m < (cnp >> 2); m += 256) {
        float4 a = row4[m], w = dv4[m];
        s += a.x * w.x + a.y * w.y + a.z * w.z + a.w * w.w;
    }
    red[tid] = s; __syncthreads();
    for (int o = 128; o > 0; o >>= 1) { if (tid < o) red[tid] += red[tid + o]; __syncthreads(); }
    if (tid == 0) {
        float r = rz2[b * N_ + n] * d2[b * N_ + n] * (red[0] + dv[n]);
        alp[b * N_ + n] = 1.f / (1.f + expf(-r * r));
    }
}

__global__ void s2inv_kernel(const float* __restrict__ Ac, const float* __restrict__ d2,
                             const float* __restrict__ rz2, const float* __restrict__ ca,
                             const int* __restrict__ cnt, float* __restrict__ sinv) {
    __shared__ float dca[N_];
    __shared__ float red[256];
    int b = blockIdx.y, n = blockIdx.x, tid = threadIdx.x;
    int cnp = (cnt[b] + 127) & ~127;
    if (n >= cnp) return;
    for (int m = tid; m < cnp; m += 256) dca[m] = d2[b * N_ + m] * ca[b * N_ + m];
    __syncthreads();
    const float4* row4 = (const float4*)(Ac + ((size_t)(b * N_ + n)) * N_);
    const float4* dca4 = (const float4*)dca;
    float s = 0.f;
    for (int m = tid; m < (cnp >> 2); m += 256) {
        float4 a = row4[m], w = dca4[m];
        s += a.x * w.x + a.y * w.y + a.z * w.z + a.w * w.w;
    }
    red[tid] = s; __syncthreads();
    for (int o = 128; o > 0; o >>= 1) { if (tid < o) red[tid] += red[tid + o]; __syncthreads(); }
    if (tid == 0) {
        float sum = red[0] + dca[n];
        float f = rz2[b * N_ + n] * d2[b * N_ + n];
        sinv[b * N_ + n] = f / fmaxf(f * sum, 1e-12f);
    }
}

__global__ void buildST_kernel(const float* __restrict__ Ac, const float* __restrict__ d2,
                               const float* __restrict__ ca, const float* __restrict__ sinv,
                               const int* __restrict__ cnt,
                               __nv_bfloat16* __restrict__ SThi, __nv_bfloat16* __restrict__ STlo) {
    __shared__ float siv[N_];
    int b = blockIdx.y, m = blockIdx.x, tid = threadIdx.x;
    int cnp = (cnt[b] + 127) & ~127;
    if (m >= cnp) return;
    for (int n = tid; n < cnp; n += 256) siv[n] = sinv[b * N_ + n];
    __syncthreads();
    float dcam = d2[b * N_ + m] * ca[b * N_ + m];
    size_t ro = ((size_t)(b * N_ + m)) * N_;
    const float4* row4 = (const float4*)(Ac + ro);
    __nv_bfloat162* ohi = (__nv_bfloat162*)(SThi + ro);
    __nv_bfloat162* olo = (__nv_bfloat162*)(STlo + ro);
    for (int q = tid; q < (cnp >> 2); q += 256) {
        float4 a = row4[q];
        int n = q << 2;
        float v0 = (a.x + ((n    ) == m ? 1.f : 0.f)) * dcam * siv[n];
        float v1 = (a.y + ((n + 1) == m ? 1.f : 0.f)) * dcam * siv[n + 1];
        float v2 = (a.z + ((n + 2) == m ? 1.f : 0.f)) * dcam * siv[n + 2];
        float v3 = (a.w + ((n + 3) == m ? 1.f : 0.f)) * dcam * siv[n + 3];
        __nv_bfloat162 h01 = split_hi2(v0, v1), h23 = split_hi2(v2, v3);
        ohi[q * 2] = h01; ohi[q * 2 + 1] = h23;
        olo[q * 2] = split_lo2(v0, v1, h01); olo[q * 2 + 1] = split_lo2(v2, v3, h23);
    }
}

__global__ void wvec_kernel(const float* __restrict__ A3, const float* __restrict__ d2,
                            const float* __restrict__ maskc, const int* __restrict__ cnt,
                            float* __restrict__ wv) {
    __shared__ float dv[N_];
    __shared__ float red[256];
    int b = blockIdx.y, k = blockIdx.x, tid = threadIdx.x;
    int cnp = (cnt[b] + 127) & ~127;
    if (k >= cnp) return;
    for (int m = tid; m < cnp; m += 256) dv[m] = d2[b * N_ + m] * maskc[b * N_ + m];
    __syncthreads();
    const float* row = A3 + ((size_t)(b * N_ + k)) * N_;
    const float4* row4 = (const float4*)row;
    const float4* dv4 = (const float4*)dv;
    float s = 0.f;
    for (int m = tid; m < (cnp >> 2); m += 256) {
        float4 a = row4[m], w = dv4[m];
        s += a.x * w.x + a.y * w.y + a.z * w.z + a.w * w.w;
    }
    red[tid] = s; __syncthreads();
    for (int o = 128; o > 0; o >>= 1) { if (tid < o) red[tid] += red[tid + o]; __syncthreads(); }
    if (tid == 0)
        wv[b * N_ + k] = d2[b * N_ + k] * (red[0] - row[k] * dv[k] + dv[k]);
}

__global__ void out2_part_kernel(const float* __restrict__ xW, const float* __restrict__ wv,
                                 const int* __restrict__ cnt, float* __restrict__ p2) {
    int b = blockIdx.y, q = blockIdx.x, c = threadIdx.x;   // 256 threads
    int cnp = (cnt[b] + 127) & ~127;
    int lo = q * 512, hi = (q + 1) * 512; if (hi > cnp) hi = cnp;
    float s = 0.f;
    for (int k = lo; k < hi; k++)
        s = fmaf(wv[b * N_ + k], xW[((size_t)(b * N_ + k)) * F_ + c], s);
    p2[(b * 4 + q) * F_ + c] = s;
}

__global__ void split_tr_kernel(const float* __restrict__ in, __nv_bfloat16* __restrict__ hi,
                                __nv_bfloat16* __restrict__ lo, const int* __restrict__ cnt,
                                int Rfixed, int Cfixed, int ld, long sIn, long sOut) {
    __shared__ float tile[32][33];
    int b = blockIdx.z;
    int cnp = (cnt[b] + 127) & ~127;
    int R = Rfixed ? Rfixed : cnp;
    int C = Cfixed ? Cfixed : cnp;
    int i0 = blockIdx.y * 32, j0 = blockIdx.x * 32;
    if (i0 >= R || j0 >= C) return;
    const float* inb = in + (size_t)b * sIn;
    size_t boff = (size_t)b * sOut;
    int tx = threadIdx.x, ty = threadIdx.y;   // (32, 8)
    #pragma unroll
    for (int r = 0; r < 4; r++) {
        int i = ty + r * 8;
        tile[i][tx] = inb[(size_t)(i0 + i) * ld + j0 + tx];
    }
    __syncthreads();
    #pragma unroll
    for (int r = 0; r < 4; r++) {
        int j = ty + r * 8;
        float v = tile[tx][j];
        __nv_bfloat16 h = __float2bfloat16(v);
        size_t o = boff + (size_t)(j0 + j) * N_ + i0 + tx;
        hi[o] = h;
        lo[o] = __float2bfloat16(v - __bfloat162float(h));
    }
}

// ---------------- bf16-split tensor GEMM, single-K-pass ----------------------
#define TSZ (128 * 40)
template<int EPI>
__global__ void __launch_bounds__(256, 2) gemm_bf16_kernel(
    const __nv_bfloat16* __restrict__ Ahi, const __nv_bfloat16* __restrict__ Alo,
    const __nv_bfloat16* __restrict__ BThi, const __nv_bfloat16* __restrict__ BTlo,
    float* __restrict__ C, const int* __restrict__ cnt,
    int ldc, long sC,
    __nv_bfloat16* __restrict__ Chi, __nv_bfloat16* __restrict__ Clo,
    const __nv_bfloat16* __restrict__ B2hi, const __nv_bfloat16* __restrict__ B2lo,
    float* __restrict__ C2, int ldc2, long sC2) {
    extern __shared__ __nv_bfloat16 sm[];   // [2 stages][4 tiles][128*40]
    const int b = blockIdx.z;
    const int cnp = (cnt[b] + 127) & ~127;
    const int m0 = blockIdx.y * 128;
    const int n0 = blockIdx.x * 128;
    const bool reg2 = (EPI == 4) && (blockIdx.x == gridDim.x - 1);
    if (m0 >= cnp) return;
    if (!reg2) {
        if (n0 >= cnp) return;
        if (EPI == 5 && m0 > n0) return;   // symmetric: upper-triangle blocks only
    }
    const size_t boff = (size_t)b * N_ * N_;
    const int tid = threadIdx.x;
    const int wid = tid >> 5, lane = tid & 31;
    const int wm = wid >> 1, wn = wid & 1;
    const int g = lane >> 2, t4 = lane & 3;
    const int a_row = lane & 15;
    const int a_k   = (lane & 16) ? 8 : 0;
    const int b_row = (lane & 7) + ((lane & 16) ? 8 : 0);
    const int b_k   = (lane & 8) ? 8 : 0;
    const int KT = cnp >> 5;

    float acc[2][8][4];
    #pragma unroll
    for (int fm = 0; fm < 2; fm++)
        #pragma unroll
        for (int fn = 0; fn < 8; fn++)
            #pragma unroll
            for (int r = 0; r < 4; r++) acc[fm][fn][r] = 0.f;

    const __nv_bfloat16* gsrc[4];
    auto stage = [&](int kt, int buf) {
        gsrc[0] = Ahi + boff + (size_t)m0 * N_ + kt * 32;
        gsrc[1] = Alo + boff + (size_t)m0 * N_ + kt * 32;
        if (reg2) {
            gsrc[2] = B2hi + (size_t)b * H_ * N_ + kt * 32;
            gsrc[3] = B2lo + (size_t)b * H_ * N_ + kt * 32;
        } else {
            gsrc[2] = BThi + boff + (size_t)n0 * N_ + kt * 32;
            gsrc[3] = BTlo + boff + (size_t)n0 * N_ + kt * 32;
        }
        int row = tid >> 2, cc = (tid & 3) * 8;
        #pragma unroll
        for (int w = 0; w < 4; w++) {
            __nv_bfloat16* dst = sm + (size_t)(buf * 4 + w) * TSZ;
            CP16(dst + row * 40 + cc,        gsrc[w] + (size_t)row * N_ + cc);
            CP16(dst + (row + 64) * 40 + cc, gsrc[w] + (size_t)(row + 64) * N_ + cc);
        }
    };

    stage(0, 0);
    CP_COMMIT();

    for (int t = 0; t < KT; t++) {
        CP_WAIT0();
        __syncthreads();
        if (t + 1 < KT) { stage(t + 1, (t + 1) & 1); CP_COMMIT(); }
        const __nv_bfloat16* Ah = sm + (size_t)((t & 1) * 4 + 0) * TSZ;
        const __nv_bfloat16* Al = sm + (size_t)((t & 1) * 4 + 1) * TSZ;
        const __nv_bfloat16* Bh = sm + (size_t)((t & 1) * 4 + 2) * TSZ;
        const __nv_bfloat16* Bl = sm + (size_t)((t & 1) * 4 + 3) * TSZ;
        #pragma unroll
        for (int kh = 0; kh < 32; kh += 16) {
            uint32_t ah[2][4], al[2][4];
            #pragma unroll
            for (int fm = 0; fm < 2; fm++) {
                int ao = (wm * 32 + fm * 16 + a_row) * 40 + kh + a_k;
                ldsm4(ah[fm], Ah + ao);
                ldsm4(al[fm], Al + ao);
            }
            #pragma unroll
            for (int fn2 = 0; fn2 < 4; fn2++) {
                int bo = (wn * 64 + fn2 * 16 + b_row) * 40 + kh + b_k;
                uint32_t bh[4], bl[4];
                ldsm4(bh, Bh + bo);
                ldsm4(bl, Bl + bo);
                #pragma unroll
                for (int fm = 0; fm < 2; fm++) {
                    mma_bf16(acc[fm][2 * fn2],     ah[fm], bh[0], bh[1]);
                    mma_bf16(acc[fm][2 * fn2],     ah[fm], bl[0], bl[1]);
                    mma_bf16(acc[fm][2 * fn2],     al[fm], bh[0], bh[1]);
                    mma_bf16(acc[fm][2 * fn2 + 1], ah[fm], bh[2], bh[3]);
                    mma_bf16(acc[fm][2 * fn2 + 1], ah[fm], bl[2], bl[3]);
                    mma_bf16(acc[fm][2 * fn2 + 1], al[fm], bh[2], bh[3]);
                }
            }
        }
        __syncthreads();
    }

    float* smf = (float*)sm;   // EPI==5: 128x133 fp32 transpose staging
    #pragma unroll
    for (int fm = 0; fm < 2; fm++) {
        int mr = m0 + wm * 32 + fm * 16 + g;
        #pragma unroll
        for (int fn = 0; fn < 8; fn++) {
            int lc = wn * 64 + fn * 8 + t4 * 2;
            float v0 = acc[fm][fn][0], v1 = acc[fm][fn][1];
            float v2 = acc[fm][fn][2], v3 = acc[fm][fn][3];
            if (reg2) {
                float* p0 = C2 + (size_t)b * sC2 + (size_t)mr * ldc2 + lc;
                p0[0] = v0; p0[1] = v1;
                float* p1 = p0 + 8 * (size_t)ldc2;
                p1[0] = v2; p1[1] = v3;
            } else if (EPI == 5) {
                v0 = floorf(v0 * 10000.f) / 10000.f;
                v1 = floorf(v1 * 10000.f) / 10000.f;
                v2 = floorf(v2 * 10000.f) / 10000.f;
                v3 = floorf(v3 * 10000.f) / 10000.f;
                int r = wm * 32 + fm * 16 + g;
                smf[(lc    ) * 133 + r]     = v0;
                smf[(lc + 1) * 133 + r]     = v1;
                smf[(lc    ) * 133 + r + 8] = v2;
                smf[(lc + 1) * 133 + r + 8] = v3;
                int n = n0 + lc;
                float* p0 = C + (size_t)b * sC + (size_t)mr * ldc + n;
                p0[0] = v0; p0[1] = v1;
                float* p1 = p0 + 8 * (size_t)ldc;
                p1[0] = v2; p1[1] = v3;
            } else {   // EPI 4 region 1: bf16 split out
                int n = n0 + lc;
                size_t o0 = (size_t)b * sC + (size_t)mr * ldc + n;
                size_t o1 = o0 + 8 * (size_t)ldc;
                __nv_bfloat162 h0 = split_hi2(v0, v1), h1 = split_hi2(v2, v3);
                *(__nv_bfloat162*)(Chi + o0) = h0;
                *(__nv_bfloat162*)(Chi + o1) = h1;
                *(__nv_bfloat162*)(Clo + o0) = split_lo2(v0, v1, h0);
                *(__nv_bfloat162*)(Clo + o1) = split_lo2(v2, v3, h1);
            }
        }
    }
    if (EPI == 5 && m0 != n0) {
        __syncthreads();
        float* Cb = C + (size_t)b * sC;
        for (int e = tid; e < 128 * 128; e += 256) {
            int r2 = e >> 7, c2 = e & 127;
            Cb[(size_t)(n0 + r2) * ldc + m0 + c2] = smf[r2 * 133 + c2];
        }
    }
}

// ---------------- double-buffered cp.async SIMT GEMM (small GEMMs) -----------
template<int TRANSA, int EPI>
__global__ void __launch_bounds__(256, 2) gemm2_kernel(
    const float* __restrict__ A, const float* __restrict__ Bm, float* __restrict__ C,
    int M, int Kd, int Nc, int lda, int ldb, int ldc,
    long sA, long sB, long sC,
    const float* __restrict__ bias, const float* __restrict__ mask,
    const int* __restrict__ cnt, int dynM, int dynK, int dynN) {
    __shared__ float As[2][128 * 16];
    __shared__ float Bs[2][16 * 128];
    const int b = blockIdx.z;
    int Mp = M, Kp = Kd, Np = Nc;
    if (cnt) {
        int p = (cnt[b] + 127) & ~127;
        if (dynM) Mp = p; if (dynK) Kp = p; if (dynN) Np = p;
    }
    const int n0 = blockIdx.x * 128, m0 = blockIdx.y * 128;
    if (m0 >= Mp || n0 >= Np) return;
    A  += (size_t)b * sA;
    Bm += (size_t)b * sB;
    C  += (size_t)b * sC;
    const int tid = threadIdx.x, tx = tid & 15, ty = tid >> 4;
    float acc[8][8];
    #pragma unroll
    for (int i = 0; i < 8; i++)
        #pragma unroll
        for (int j = 0; j < 8; j++) acc[i][j] = 0.f;

    const int Kt = Kp >> 4;

    auto load_tiles = [&](int k0, int buf) {
        if (!TRANSA) {
            #pragma unroll
            for (int q = 0; q < 2; q++) {
                int c = tid + q * 256;
                int row = c >> 2, col4 = (c & 3) * 4;
                const float* src = A + (size_t)(m0 + row) * lda + k0 + col4;
                CP16(&As[buf][row * 16 + col4], src);
            }
        } else {
            #pragma unroll
            for (int q = 0; q < 2; q++) {
                int c = tid + q * 256;
                int row = c >> 5, col4 = (c & 31) * 4;
                const float* src = A + (size_t)(k0 + row) * lda + m0 + col4;
                CP16(&As[buf][row * 128 + col4], src);
            }
        }
        #pragma unroll
        for (int q = 0; q < 2; q++) {
            int c = tid + q * 256;
            int row = c >> 5, col4 = (c & 31) * 4;
            const float* src = Bm + (size_t)(k0 + row) * ldb + n0 + col4;
            CP16(&Bs[buf][row * 128 + col4], src);
        }
    };

    load_tiles(0, 0);
    CP_COMMIT();

    for (int t = 0; t < Kt; t++) {
        CP_WAIT0();
        __syncthreads();
        if (t + 1 < Kt) { load_tiles((t + 1) << 4, (t + 1) & 1); CP_COMMIT(); }
        const int buf = t & 1;
        #pragma unroll
        for (int k = 0; k < 16; k++) {
            float a[8], bv[8];
            if (!TRANSA) {
                #pragma unroll
                for (int i = 0; i < 8; i++) a[i] = As[buf][(ty * 8 + i) * 16 + k];
            } else {
                *(float4*)(a)     = *(const float4*)&As[buf][k * 128 + ty * 8];
                *(float4*)(a + 4) = *(const float4*)&As[buf][k * 128 + ty * 8 + 4];
            }
            *(float4*)(bv)     = *(const float4*)&Bs[buf][k * 128 + tx * 8];
            *(float4*)(bv + 4) = *(const float4*)&Bs[buf][k * 128 + tx * 8 + 4];
            #pragma unroll
            for (int i = 0; i < 8; i++)
                #pragma unroll
                for (int j = 0; j < 8; j++) acc[i][j] = fmaf(a[i], bv[j], acc[i][j]);
        }
        __syncthreads();
    }
    #pragma unroll
    for (int i = 0; i < 8; i++) {
        int m = m0 + ty * 8 + i;
        float mk = (EPI == 2) ? mask[(size_t)b * N_ + m] : 1.f;
        #pragma unroll
        for (int j = 0; j < 8; j++) {
            int n = n0 + tx * 8 + j;
            float v = acc[i][j];
            if (EPI == 2)      { v = (v + bias[n]) * mk; }
            else if (EPI == 3) { v = floorf(v * 10000.f) / 10000.f; }
            C[(size_t)m * ldc + n] = v;
        }
    }
}

// ---------------- output means (two-stage, deterministic) --------------------
__global__ void mean1_part_kernel(const float* __restrict__ x1, float* __restrict__ p1) {
    int b = blockIdx.y, q = blockIdx.x, c = threadIdx.x;   // 128 threads
    float s = 0.f;
    for (int n = q * 512; n < (q + 1) * 512; n++) s += x1[((size_t)(b * N_ + n)) * H_ + c];
    p1[(b * 4 + q) * H_ + c] = s;
}

__global__ void mean_combine_kernel(const float* __restrict__ p1, const float* __restrict__ p2,
                                    const float* __restrict__ b2, const float* __restrict__ smask,
                                    float* __restrict__ out) {
    int b = blockIdx.x, c = threadIdx.x;   // 384 threads
    if (c < H_) {
        float s = 0.f;
        for (int q = 0; q < 4; q++) s += p1[(b * 4 + q) * H_ + c];
        out[b * OUTC + c] = s / (float)N_;
    } else {
        int cc = c - H_;
        float s = b2[cc] * smask[b];
        for (int q = 0; q < 4; q++) s += p2[(b * 4 + q) * F_ + cc];
        out[b * OUTC + c] = s / (float)N_;
    }
}

extern "C" void kernel_launch(void* const* d_in, const int* in_sizes, int n_in,
                              void* d_out, int out_size) {
    const float* x    = (const float*)d_in[0];
    const float* adj  = (const float*)d_in[1];
    const float* mask = (const float*)d_in[2];
    const float* W1   = (const float*)d_in[3];
    const float* b1   = (const float*)d_in[4];
    const float* Watt = (const float*)d_in[5];
    const float* batt = (const float*)d_in[6];
    const float* W2   = (const float*)d_in[7];
    const float* b2   = (const float*)d_in[8];
    float* out = (float*)d_out;

    float *pT,*pAc,*pA3,*pxW,*px1,*pxc,*px3;
    float *pv,*palp,*pca,*psrec,*pd0,*pd1,*prnz,*pd2,*prz2,*pcut,*pmaskc,*pmrest,*pp1,*pp2;
    __nv_bfloat16 *pAhi,*pAlo,*pSThi,*pSTlo,*pTThi,*pTTlo,*pxTh,*pxTl;
    int *plst,*pdeg,*phasd,*pidx,*pginv,*pcnt;
    cudaGetSymbolAddress((void**)&pT,   g_T);
    cudaGetSymbolAddress((void**)&pAc,  g_Ac);
    cudaGetSymbolAddress((void**)&pA3,  g_A3);
    cudaGetSymbolAddress((void**)&pAhi, g_Ahi);
    cudaGetSymbolAddress((void**)&pAlo, g_Alo);
    cudaGetSymbolAddress((void**)&pSThi,g_SThi);
    cudaGetSymbolAddress((void**)&pSTlo,g_STlo);
    cudaGetSymbolAddress((void**)&pTThi,g_TThi);
    cudaGetSymbolAddress((void**)&pTTlo,g_TTlo);
    cudaGetSymbolAddress((void**)&pxTh, g_xTh);
    cudaGetSymbolAddress((void**)&pxTl, g_xTl);
    cudaGetSymbolAddress((void**)&pxW,  g_xW);
    cudaGetSymbolAddress((void**)&px1,  g_x1);
    cudaGetSymbolAddress((void**)&pxc,  g_xc);
    cudaGetSymbolAddress((void**)&px3,  g_x3);
    cudaGetSymbolAddress((void**)&pv,   g_v);
    cudaGetSymbolAddress((void**)&palp, g_alp);
    cudaGetSymbolAddress((void**)&pca,  g_ca);
    cudaGetSymbolAddress((void**)&psrec,g_srec);
    cudaGetSymbolAddress((void**)&pd0,  g_d0);
    cudaGetSymbolAddress((void**)&pd1,  g_d1);
    cudaGetSymbolAddress((void**)&prnz, g_rnz);
    cudaGetSymbolAddress((void**)&pd2,  g_d2);
    cudaGetSymbolAddress((void**)&prz2, g_rz2);
    cudaGetSymbolAddress((void**)&pcut, g_cut);
    cudaGetSymbolAddress((void**)&pmaskc, g_maskc);
    cudaGetSymbolAddress((void**)&pmrest, g_mrest);
    cudaGetSymbolAddress((void**)&pp1,  g_p1);
    cudaGetSymbolAddress((void**)&pp2,  g_p2);
    cudaGetSymbolAddress((void**)&plst, g_lst);
    cudaGetSymbolAddress((void**)&pdeg, g_deg);
    cudaGetSymbolAddress((void**)&phasd,g_hasd);
    cudaGetSymbolAddress((void**)&pidx, g_idx);
    cudaGetSymbolAddress((void**)&pginv,g_ginv);
    cudaGetSymbolAddress((void**)&pcnt, g_cnt);

    const int BF16_SMEM = 2 * 4 * TSZ * 2;   // 81920 bytes
    cudaFuncSetAttribute(gemm_bf16_kernel<4>, cudaFuncAttributeMaxDynamicSharedMemorySize, BF16_SMEM);
    cudaFuncSetAttribute(gemm_bf16_kernel<5>, cudaFuncAttributeMaxDynamicSharedMemorySize, BF16_SMEM);

    // ---- CSR + degree stats ----
    csr_build_kernel<<<dim3(N_, B_), 256>>>(adj, plst, pdeg, phasd, pd0, pd1, prnz);

    // ---- GCN layer 1 ----
    gemm2_kernel<0,0><<<dim3(1,16,B_),256>>>(x, W1, pxW, N_, F_, H_, F_, H_, H_,
        (long)N_*F_, 0, (long)N_*H_, nullptr, nullptr, nullptr, 0,0,0);
    gcn1_kernel<<<dim3(N_, B_), 128>>>(plst, pdeg, pd0, pxW, b1, mask, px1);

    // ---- coarsen layer 1 (sparse) ----
    gemv_watt_kernel<<<(B_*N_)/8, 256>>>(px1, Watt, batt, pv);
    alpha1_kernel<<<dim3(N_/8, B_), 256>>>(plst, pdeg, pd1, prnz, pv, palp);
    topk_cut_kernel<<<B_, 1024>>>(palp, pcut);
    ca_kernel<<<(B_*N_)/256, 256>>>(palp, pcut, pca);
    compact_kernel<<<B_, 1024>>>(pca, pidx, pginv, pcnt);
    compact_mask_kernel<<<B_, 256>>>(mask, pidx, pcnt, pmaskc, pmrest);
    srec_kernel<<<dim3(N_/8, B_), 256>>>(plst, pdeg, pd1, prnz, pca, psrec);
    xupd_kernel<<<dim3(N_, B_), 128>>>(plst, pdeg, phasd, pd1, pca, psrec, pidx, pcnt, px1, pxc);
    adjS_sparse_kernel<<<dim3(N_/4, B_), 128>>>(plst, pdeg, phasd, pd1, pca, psrec,
                                                pginv, pcnt, pT);
    STT_kernel<<<dim3(N_, B_), 256>>>(plst, pdeg, phasd, pd1, pca, psrec, pidx, pcnt,
                                      pT, pAc, pAhi, pAlo, pd2, prz2);

    // ---- coarsen layer 2 (symmetric Ac: direct row-major ST build) ----
    gemv_watt_kernel<<<(B_*N_)/8, 256>>>(pxc, Watt, batt, pv);
    alpha2d_kernel<<<dim3(N_, B_), 256>>>(pAc, pd2, prz2, pv, pcnt, palp);
    topk_cut_kernel<<<B_, 1024>>>(palp, pcut);
    ca_kernel<<<(B_*N_)/256, 256>>>(palp, pcut, pca);
    s2inv_kernel<<<dim3(N_, B_), 256>>>(pAc, pd2, prz2, pca, pcnt, psrec);
    buildST_kernel<<<dim3(N_, B_), 256>>>(pAc, pd2, pca, psrec, pcnt, pSThi, pSTlo);
    split_tr_kernel<<<dim3(4, 64, B_), dim3(32, 8)>>>(pxc, pxTh, pxTl, pcnt,
        0, H_, H_, (long)N_*H_, (long)H_*N_);
    // MERGED: T2^T = ST @ Ac^T (bf16 split -> TT)  AND  x3 = ST @ xc (fp32)
    gemm_bf16_kernel<4><<<dim3(17,16,B_),256,BF16_SMEM>>>(pSThi, pSTlo, pAhi, pAlo,
        nullptr, pcnt, N_, (long)N_*N_, pTThi, pTTlo,
        pxTh, pxTl, px3, H_, (long)N_*H_);
    // A3 = ST @ T2 (symmetric): upper blocks only, floor-quant, mirror write
    gemm_bf16_kernel<5><<<dim3(16,16,B_),256,BF16_SMEM>>>(pSThi, pSTlo, pTThi, pTTlo,
        pA3, pcnt, N_, (long)N_*N_, nullptr, nullptr,
        nullptr, nullptr, nullptr, 0, 0);

    // ---- final GCN: only the column mean is needed ----
    rowstats_c_kernel<<<dim3(N_, B_), 256>>>(pA3, pcnt, pd2, nullptr, 0);
    gemm2_kernel<0,0><<<dim3(2,16,B_),256>>>(px3, W2, pxW, N_, H_, F_, H_, F_, F_,
        (long)N_*H_, 0, (long)N_*F_, nullptr, nullptr, pcnt, 1,0,0);
    wvec_kernel<<<dim3(N_, B_), 256>>>(pA3, pd2, pmaskc, pcnt, pv);
    out2_part_kernel<<<dim3(4, B_), 256>>>(pxW, pv, pcnt, pp2);

    // ---- concat means ----
    mean1_part_kernel<<<dim3(4, B_), 128>>>(px1, pp1);
    mean_combine_kernel<<<B_, 384>>>(pp1, pp2, b2, pmrest, out);
}

// round 15
// speedup vs baseline: 8.7467x; 1.0269x over previous
#include <cuda_runtime.h>
#include <cuda_bf16.h>
#include <math.h>
#include <stdint.h>

#define B_ 8
#define N_ 2048
#define F_ 256
#define H_ 128
#define K_ 1025
#define OUTC 384
#define CAP 256

// ---------------- scratch (device globals; no allocation allowed) ----------
__device__ float g_T [(size_t)B_*N_*N_];
__device__ float g_Ac[(size_t)B_*N_*N_];
__device__ float g_A3[(size_t)B_*N_*N_];
__device__ __nv_bfloat16 g_Ahi[(size_t)B_*N_*N_], g_Alo[(size_t)B_*N_*N_];
__device__ __nv_bfloat16 g_SThi[(size_t)B_*N_*N_], g_STlo[(size_t)B_*N_*N_];
__device__ __nv_bfloat16 g_TThi[(size_t)B_*N_*N_], g_TTlo[(size_t)B_*N_*N_];
__device__ __nv_bfloat16 g_xTh[B_*H_*N_], g_xTl[B_*H_*N_];
__device__ float g_xW [B_*N_*F_];
__device__ float g_x1 [B_*N_*H_];
__device__ float g_xc [B_*N_*H_];
__device__ float g_x3 [B_*N_*H_];
__device__ int   g_lst[(size_t)B_*N_*CAP];
__device__ int   g_deg[B_*N_];
__device__ int   g_hasd[B_*N_];
__device__ float g_d0[B_*N_], g_d1[B_*N_], g_rnz[B_*N_];
__device__ float g_d2[B_*N_], g_rz2[B_*N_];
__device__ float g_v[B_*N_], g_alp[B_*N_], g_ca[B_*N_], g_srec[B_*N_];
__device__ float g_cut[B_];
__device__ float g_maskc[B_*N_], g_mrest[B_];
__device__ int   g_idx[B_*N_], g_ginv[B_*N_], g_cnt[B_];
__device__ float g_p1[B_*4*H_], g_p2[B_*4*F_];

// ---------------- async-copy / mma helpers -----------------------------------
#define CP16(dst, src) { \
    unsigned _a = (unsigned)__cvta_generic_to_shared(dst); \
    asm volatile("cp.async.cg.shared.global [%0], [%1], 16;\n" :: "r"(_a), "l"(src)); }
#define CP_COMMIT() asm volatile("cp.async.commit_group;\n")
#define CP_WAIT0()  asm volatile("cp.async.wait_group 0;\n")

__device__ __forceinline__ void mma_bf16(float* c, const uint32_t* a, uint32_t b0, uint32_t b1) {
    asm volatile("mma.sync.aligned.m16n8k16.row.col.f32.bf16.bf16.f32 "
        "{%0,%1,%2,%3}, {%4,%5,%6,%7}, {%8,%9}, {%0,%1,%2,%3};"
        : "+f"(c[0]), "+f"(c[1]), "+f"(c[2]), "+f"(c[3])
        : "r"(a[0]), "r"(a[1]), "r"(a[2]), "r"(a[3]), "r"(b0), "r"(b1));
}
__device__ __forceinline__ void ldsm4(uint32_t* r, const void* p) {
    uint32_t a = (uint32_t)__cvta_generic_to_shared(p);
    asm volatile("ldmatrix.sync.aligned.m8n8.x4.shared.b16 {%0,%1,%2,%3}, [%4];"
        : "=r"(r[0]), "=r"(r[1]), "=r"(r[2]), "=r"(r[3]) : "r"(a));
}
__device__ __forceinline__ __nv_bfloat162 split_hi2(float v0, float v1) {
    __nv_bfloat162 h; h.x = __float2bfloat16(v0); h.y = __float2bfloat16(v1); return h;
}
__device__ __forceinline__ __nv_bfloat162 split_lo2(float v0, float v1, __nv_bfloat162 h) {
    __nv_bfloat162 l;
    l.x = __float2bfloat16(v0 - __bfloat162float(h.x));
    l.y = __float2bfloat16(v1 - __bfloat162float(h.y));
    return l;
}

// ---------------- CSR build + degree stats (one adj scan, float4) -----------
__global__ void csr_build_kernel(const float* __restrict__ adj, int* __restrict__ lst,
                                 int* __restrict__ deg, int* __restrict__ hasd,
                                 float* __restrict__ d0, float* __restrict__ d1,
                                 float* __restrict__ rnz) {
    __shared__ int sc[256];
    __shared__ int hd;
    int b = blockIdx.y, i = blockIdx.x, tid = threadIdx.x;
    const float4* arow4 = (const float4*)(adj + ((size_t)(b * N_ + i)) * N_);
    if (tid == 0) hd = 0;
    __syncthreads();
    float vals[8];
    *(float4*)(vals)     = arow4[tid * 2];
    *(float4*)(vals + 4) = arow4[tid * 2 + 1];
    int f[8];
    int c = 0, hloc = 0;
    #pragma unroll
    for (int e = 0; e < 8; e++) {
        int j = tid * 8 + e;
        f[e] = (vals[e] != 0.f) ? 1 : 0;
        c += f[e];
        if (f[e] && j == i) hloc = 1;
    }
    if (hloc) hd = 1;
    sc[tid] = c; __syncthreads();
    for (int o = 1; o < 256; o <<= 1) {
        int v = (tid >= o) ? sc[tid - o] : 0; __syncthreads();
        sc[tid] += v; __syncthreads();
    }
    int base = sc[tid] - c;
    int* l = lst + ((size_t)(b * N_ + i)) * CAP;
    #pragma unroll
    for (int e = 0; e < 8; e++) {
        if (f[e]) { if (base < CAP) l[base] = tid * 8 + e; base++; }
    }
    __syncthreads();
    if (tid == 0) {
        int total = sc[255];
        deg[b * N_ + i] = (total > CAP) ? CAP : total;
        hasd[b * N_ + i] = hd;
        d0[b * N_ + i] = rsqrtf(fmaxf((float)(total - hd) + 1.f, 1.f));
        d1[b * N_ + i] = rsqrtf((float)total + 1.f);
        rnz[b * N_ + i] = (total > 0) ? 1.f : 0.f;
    }
}

// -- GCN layer 1 sparse aggregation; fused v = x1 @ Watt + batt ---------------
__global__ void gcn1_kernel(const int* __restrict__ lst, const int* __restrict__ deg,
                            const float* __restrict__ d0, const float* __restrict__ xW,
                            const float* __restrict__ b1, const float* __restrict__ mask,
                            const float* __restrict__ Watt, const float* __restrict__ batt,
                            float* __restrict__ x1, float* __restrict__ v) {
    __shared__ int   jl[CAP];
    __shared__ float cf[CAP];
    __shared__ float red[128];
    int b = blockIdx.y, i = blockIdx.x, c = threadIdx.x;   // 128 threads
    int dg = deg[b * N_ + i];
    const int* l = lst + ((size_t)(b * N_ + i)) * CAP;
    float di = d0[b * N_ + i];
    for (int p = c; p < dg; p += 128) {
        int j = l[p];
        jl[p] = j;
        cf[p] = (j == i) ? 0.f : di * d0[b * N_ + j];
    }
    __syncthreads();
    float acc = di * di * xW[((size_t)(b * N_ + i)) * H_ + c];
    #pragma unroll 4
    for (int p = 0; p < dg; p++)
        acc = fmaf(cf[p], xW[((size_t)(b * N_ + jl[p])) * H_ + c], acc);
    float vv = (acc + b1[c]) * mask[b * N_ + i];
    vv = fmaxf(vv, 0.f);
    x1[((size_t)(b * N_ + i)) * H_ + c] = vv;
    red[c] = vv * Watt[c];
    __syncthreads();
    for (int o = 64; o > 0; o >>= 1) { if (c < o) red[c] += red[c + o]; __syncthreads(); }
    if (c == 0) v[b * N_ + i] = red[0] + batt[0];
}

// ---------------- layer-1 alpha (sparse) --------------------------------------
__global__ void alpha1_kernel(const int* __restrict__ lst, const int* __restrict__ deg,
                              const float* __restrict__ d1, const float* __restrict__ rnz,
                              const float* __restrict__ v, float* __restrict__ alp) {
    int b = blockIdx.y;
    int i = blockIdx.x * 8 + (threadIdx.x >> 5);
    int lane = threadIdx.x & 31;
    const int* l = lst + ((size_t)(b * N_ + i)) * CAP;
    int dg = deg[b * N_ + i];
    float s = 0.f;
    for (int p = lane; p < dg; p += 32) { int j = l[p]; s += d1[b * N_ + j] * v[b * N_ + j]; }
    #pragma unroll
    for (int o = 16; o > 0; o >>= 1) s += __shfl_down_sync(0xffffffffu, s, o);
    if (lane == 0) {
        float di = d1[b * N_ + i];
        float r = rnz[b * N_ + i] * di * (s + di * v[b * N_ + i]);
        float z = r * r;
        alp[b * N_ + i] = 1.f / (1.f + expf(-z));
    }
}

// ---- exact K-th largest via 4-pass radix select; fused ca epilogue ----------
__global__ void topk_cut_kernel(const float* __restrict__ alp, float* __restrict__ cut,
                                float* __restrict__ ca) {
    __shared__ int hist[256];
    __shared__ unsigned pref;
    __shared__ int rem;
    int b = blockIdx.x, t = threadIdx.x;   // 1024 threads
    float a0 = alp[b * N_ + t], a1 = alp[b * N_ + t + 1024];
    unsigned v0 = __float_as_uint(a0);
    unsigned v1 = __float_as_uint(a1);
    if (t == 0) { pref = 0u; rem = N_ - K_ + 1; }
    __syncthreads();
    #pragma unroll
    for (int pass = 0; pass < 4; pass++) {
        int shift = 24 - pass * 8;
        if (t < 256) hist[t] = 0;
        __syncthreads();
        unsigned maskA = (pass == 0) ? 0u : (0xFFFFFFFFu << (shift + 8));
        unsigned pr = pref;
        if ((v0 & maskA) == pr) atomicAdd(&hist[(v0 >> shift) & 255], 1);
        if ((v1 & maskA) == pr) atomicAdd(&hist[(v1 >> shift) & 255], 1);
        __syncthreads();
        if (t == 0) {
            int r = rem;
            unsigned bin = 0;
            #pragma unroll 8
            for (int q = 0; q < 256; q++) {
                int h = hist[q];
                if (r - h <= 0) { bin = q; break; }
                r -= h;
            }
            rem = r;
            pref = pr | (bin << shift);
        }
        __syncthreads();
    }
    float cv = __uint_as_float(pref);
    if (t == 0) cut[b] = cv;
    ca[b * N_ + t]        = fmaxf(a0 + 1e-7f - cv, 0.f);
    ca[b * N_ + t + 1024] = fmaxf(a1 + 1e-7f - cv, 0.f);
}

// -------- kept-set compaction (prefix scan) + fused maskc/mrest --------------
__global__ void compact_kernel(const float* __restrict__ ca, const float* __restrict__ mask,
                               int* __restrict__ idx, int* __restrict__ ginv,
                               int* __restrict__ cnt, float* __restrict__ maskc,
                               float* __restrict__ mrest) {
    __shared__ int sc[1024];
    __shared__ float redm[1024];
    int b = blockIdx.x, t = threadIdx.x;   // 1024 threads
    int f0 = (ca[b * N_ + 2 * t]     > 0.f) ? 1 : 0;
    int f1 = (ca[b * N_ + 2 * t + 1] > 0.f) ? 1 : 0;
    ginv[b * N_ + 2 * t] = -1;
    ginv[b * N_ + 2 * t + 1] = -1;
    int c = f0 + f1;
    sc[t] = c; __syncthreads();
    for (int o = 1; o < 1024; o <<= 1) {
        int v = (t >= o) ? sc[t - o] : 0; __syncthreads();
        sc[t] += v; __syncthreads();
    }
    int base = sc[t] - c;
    if (f0) { idx[b * N_ + base] = 2 * t;     ginv[b * N_ + 2 * t]     = base; base++; }
    if (f1) { idx[b * N_ + base] = 2 * t + 1; ginv[b * N_ + 2 * t + 1] = base; }
    if (t == 1023) cnt[b] = sc[1023];
    __syncthreads();
    int cn = sc[1023];
    // maskc + total mask sum
    float local = mask[b * N_ + 2 * t] + mask[b * N_ + 2 * t + 1];
    #pragma unroll
    for (int r = 0; r < 2; r++) {
        int i = t + r * 1024;
        float mv = 0.f;
        if (i < cn) mv = mask[b * N_ + idx[b * N_ + i]];
        maskc[b * N_ + i] = mv;
    }
    redm[t] = local; __syncthreads();
    for (int o = 512; o > 0; o >>= 1) { if (t < o) redm[t] += redm[t + o]; __syncthreads(); }
    if (t == 0) mrest[b] = redm[0];
}

// ---------------- layer-1 S row normalizer -----------------------------------
__global__ void srec_kernel(const int* __restrict__ lst, const int* __restrict__ deg,
                            const float* __restrict__ d1, const float* __restrict__ rnz,
                            const float* __restrict__ ca, float* __restrict__ srec) {
    int b = blockIdx.y;
    int i = blockIdx.x * 8 + (threadIdx.x >> 5);
    int lane = threadIdx.x & 31;
    const int* l = lst + ((size_t)(b * N_ + i)) * CAP;
    int dg = deg[b * N_ + i];
    float s = 0.f;
    for (int p = lane; p < dg; p += 32) { int j = l[p]; s += d1[b * N_ + j] * ca[b * N_ + j]; }
    #pragma unroll
    for (int o = 16; o > 0; o >>= 1) s += __shfl_down_sync(0xffffffffu, s, o);
    if (lane == 0) {
        float di = d1[b * N_ + i];
        float raw = rnz[b * N_ + i] * di * (s + di * ca[b * N_ + i]);
        srec[b * N_ + i] = rnz[b * N_ + i] * di / fmaxf(raw, 1e-12f);
    }
}

// -- xc[ic,:] = sum_n S[n, idx[ic]] * x1[n,:]; fused v2 = xc @ Watt + batt ----
__global__ void xupd_kernel(const int* __restrict__ lst, const int* __restrict__ deg,
                            const int* __restrict__ hasd, const float* __restrict__ d1,
                            const float* __restrict__ ca, const float* __restrict__ srec,
                            const int* __restrict__ idx, const int* __restrict__ cnt,
                            const float* __restrict__ x1, const float* __restrict__ Watt,
                            const float* __restrict__ batt,
                            float* __restrict__ xc, float* __restrict__ v) {
    __shared__ int   jl[CAP + 1];
    __shared__ float sv[CAP + 1];
    __shared__ float red[128];
    int b = blockIdx.y, ic = blockIdx.x, c = threadIdx.x;   // 128 threads
    int cn = cnt[b], cnp = (cn + 127) & ~127;
    if (ic >= cnp) return;
    float* orow = xc + ((size_t)(b * N_ + ic)) * H_;
    if (ic >= cn) {
        orow[c] = 0.f;
        if (c == 0) v[b * N_ + ic] = batt[0];
        return;
    }
    int m = idx[b * N_ + ic];
    float dmcam = d1[b * N_ + m] * ca[b * N_ + m];
    int dg = deg[b * N_ + m];
    const int* l = lst + ((size_t)(b * N_ + m)) * CAP;
    for (int p = c; p < dg; p += 128) {
        int n = l[p];
        jl[p] = n;
        sv[p] = srec[b * N_ + n] * dmcam * ((n == m) ? 2.f : 1.f);
    }
    int dgE = dg + (hasd[b * N_ + m] ? 0 : 1);
    if (c == 0 && dgE > dg) { jl[dg] = m; sv[dg] = srec[b * N_ + m] * dmcam; }
    __syncthreads();
    float acc = 0.f;
    #pragma unroll 4
    for (int p = 0; p < dgE; p++)
        acc = fmaf(sv[p], x1[((size_t)(b * N_ + jl[p])) * H_ + c], acc);
    orow[c] = acc;
    red[c] = acc * Watt[c];
    __syncthreads();
    for (int o = 64; o > 0; o >>= 1) { if (c < o) red[c] += red[c + o]; __syncthreads(); }
    if (c == 0) v[b * N_ + ic] = red[0] + batt[0];
}

// ---- Tc[i,:] = sum_{j in list_i} S_row_j, S rows expanded on the fly --------
__global__ void adjS_sparse_kernel(const int* __restrict__ lst, const int* __restrict__ deg,
                                   const int* __restrict__ hasd, const float* __restrict__ d1,
                                   const float* __restrict__ ca, const float* __restrict__ srec,
                                   const int* __restrict__ ginv, const int* __restrict__ cnt,
                                   float* __restrict__ Tc) {
    __shared__ float acc[4][N_];
    int b = blockIdx.y, tid = threadIdx.x;   // 128 threads = 4 warps
    int w = tid >> 5, lane = tid & 31;
    int i = blockIdx.x * 4 + w;
    int cnp = (cnt[b] + 127) & ~127;
    float* a = acc[w];
    float4* a4 = (float4*)a;
    float4 z4 = make_float4(0.f, 0.f, 0.f, 0.f);
    for (int jc = lane; jc < (cnp >> 2); jc += 32) a4[jc] = z4;
    __syncwarp();
    int dgi = deg[b * N_ + i];
    const int* li = lst + ((size_t)(b * N_ + i)) * CAP;
    const int* gv = ginv + b * N_;
    for (int p = 0; p < dgi; p++) {
        int j = li[p];
        int dgj = deg[b * N_ + j];
        const int* lj = lst + ((size_t)(b * N_ + j)) * CAP;
        float sr = srec[b * N_ + j];
        for (int q = lane; q < dgj; q += 32) {
            int m = lj[q];
            int jc = gv[m];
            if (jc >= 0) {
                float coef = (m == j) ? 2.f : 1.f;
                a[jc] += sr * d1[b * N_ + m] * ca[b * N_ + m] * coef;
            }
        }
        __syncwarp();
        if (lane == 0 && !hasd[b * N_ + j]) {
            int jc = gv[j];
            if (jc >= 0) a[jc] += sr * d1[b * N_ + j] * ca[b * N_ + j];
        }
        __syncwarp();
    }
    float4* trow4 = (float4*)(Tc + (size_t)b * N_ * N_ + (size_t)i * cnp);
    for (int jc = lane; jc < (cnp >> 2); jc += 32) trow4[jc] = a4[jc];
}

// -- Ac row = floorq(sum S*Tc); REGISTER accumulators + staged coef lists -----
__global__ void STT_kernel(const int* __restrict__ lst, const int* __restrict__ deg,
                           const int* __restrict__ hasd, const float* __restrict__ d1,
                           const float* __restrict__ ca, const float* __restrict__ srec,
                           const int* __restrict__ idx, const int* __restrict__ cnt,
                           const float* __restrict__ Tc, float* __restrict__ Ac,
                           __nv_bfloat16* __restrict__ Achi, __nv_bfloat16* __restrict__ Aclo,
                           float* __restrict__ d2out, float* __restrict__ rz2out) {
    __shared__ int   nls[CAP + 1];
    __shared__ float svs[CAP + 1];
    __shared__ float red[256];
    int b = blockIdx.y, ic = blockIdx.x, tid = threadIdx.x;
    int cn = cnt[b], cnp = (cn + 127) & ~127, cnp4 = cnp >> 2;
    if (ic >= cnp) return;
    size_t rowoff = ((size_t)(b * N_ + ic)) * N_;
    float4* orow4 = (float4*)(Ac + rowoff);
    __nv_bfloat162* ohi = (__nv_bfloat162*)(Achi + rowoff);
    __nv_bfloat162* olo = (__nv_bfloat162*)(Aclo + rowoff);
    float4 z4 = make_float4(0.f, 0.f, 0.f, 0.f);
    if (ic >= cn) {
        __nv_bfloat162 zb; zb.x = __float2bfloat16(0.f); zb.y = zb.x;
        for (int jc = tid; jc < cnp4; jc += 256) {
            orow4[jc] = z4;
            ohi[jc * 2] = zb; ohi[jc * 2 + 1] = zb;
            olo[jc * 2] = zb; olo[jc * 2 + 1] = zb;
        }
        if (tid == 0) { d2out[b * N_ + ic] = 1.f; rz2out[b * N_ + ic] = 0.f; }
        return;
    }
    int m = idx[b * N_ + ic];
    float dmcam = d1[b * N_ + m] * ca[b * N_ + m];
    int dg = deg[b * N_ + m];
    const int* l = lst + ((size_t)(b * N_ + m)) * CAP;
    for (int p = tid; p < dg; p += 256) {
        int n = l[p];
        nls[p] = n;
        svs[p] = srec[b * N_ + n] * dmcam * ((n == m) ? 2.f : 1.f);
    }
    int dgE = dg + (hasd[b * N_ + m] ? 0 : 1);
    if (tid == 0 && dgE > dg) { nls[dg] = m; svs[dg] = srec[b * N_ + m] * dmcam; }
    __syncthreads();
    const float* Tb = Tc + (size_t)b * N_ * N_;
    int j0 = tid, j1 = tid + 256;
    bool h1 = (j1 < cnp4);
    float4 a0 = z4, a1 = z4;
    #pragma unroll 2
    for (int p = 0; p < dgE; p++) {
        float sv = svs[p];
        const float4* trow = (const float4*)(Tb + (size_t)nls[p] * cnp);
        float4 t0 = trow[j0];
        a0.x = fmaf(sv, t0.x, a0.x); a0.y = fmaf(sv, t0.y, a0.y);
        a0.z = fmaf(sv, t0.z, a0.z); a0.w = fmaf(sv, t0.w, a0.w);
        if (h1) {
            float4 t1 = trow[j1];
            a1.x = fmaf(sv, t1.x, a1.x); a1.y = fmaf(sv, t1.y, a1.y);
            a1.z = fmaf(sv, t1.z, a1.z); a1.w = fmaf(sv, t1.w, a1.w);
        }
    }
    float part = 0.f;
    #pragma unroll
    for (int r = 0; r < 2; r++) {
        int jc = (r == 0) ? j0 : j1;
        if (r == 1 && !h1) break;
        float4 a = (r == 0) ? a0 : a1;
        a.x = floorf(a.x * 10000.f) / 10000.f;
        a.y = floorf(a.y * 10000.f) / 10000.f;
        a.z = floorf(a.z * 10000.f) / 10000.f;
        a.w = floorf(a.w * 10000.f) / 10000.f;
        orow4[jc] = a;
        part += (a.x + a.y) + (a.z + a.w);
        __nv_bfloat162 h01 = split_hi2(a.x, a.y), h23 = split_hi2(a.z, a.w);
        ohi[jc * 2] = h01; ohi[jc * 2 + 1] = h23;
        olo[jc * 2] = split_lo2(a.x, a.y, h01); olo[jc * 2 + 1] = split_lo2(a.z, a.w, h23);
    }
    red[tid] = part; __syncthreads();
    for (int o = 128; o > 0; o >>= 1) { if (tid < o) red[tid] += red[tid + o]; __syncthreads(); }
    if (tid == 0) {
        float sum = red[0];
        d2out[b * N_ + ic] = rsqrtf(fmaxf(sum + 1.f, 1.f));
        rz2out[b * N_ + ic] = (sum > 0.f) ? 1.f : 0.f;
    }
}

// ---------------- layer-2 / final helpers ------------------------------------
__global__ void rowstats_c_kernel(const float* __restrict__ A, const int* __restrict__ cnt,
                                  float* __restrict__ dout, float* __restrict__ rnz, int mode) {
    int b = blockIdx.y, i = blockIdx.x, tid = threadIdx.x;
    int cnp = (cnt[b] + 127) & ~127;
    if (i >= cnp) return;
    const float* row = A + ((size_t)(b * N_ + i)) * N_;
    const float4* row4 = (const float4*)row;
    float s = 0.f;
    for (int j = tid; j < (cnp >> 2); j += 256) {
        float4 a = row4[j]; s += (a.x + a.y) + (a.z + a.w);
    }
    __shared__ float red[256];
    red[tid] = s; __syncthreads();
    for (int o = 128; o > 0; o >>= 1) { if (tid < o) red[tid] += red[tid + o]; __syncthreads(); }
    if (tid == 0) {
        float sum = red[0];
        if (mode == 0) {
            dout[b * N_ + i] = rsqrtf(fmaxf(sum - row[i] + 1.f, 1.f));
        } else {
            dout[b * N_ + i] = rsqrtf(fmaxf(sum + 1.f, 1.f));
            rnz[b * N_ + i] = (sum > 0.f) ? 1.f : 0.f;
        }
    }
}

__global__ void alpha2d_kernel(const float* __restrict__ Ac, const float* __restrict__ d2,
                               const float* __restrict__ rz2, const float* __restrict__ v,
                               const int* __restrict__ cnt, float* __restrict__ alp) {
    __shared__ float dv[N_];
    __shared__ float red[256];
    int b = blockIdx.y, n = blockIdx.x, tid = threadIdx.x;
    int cnp = (cnt[b] + 127) & ~127;
    if (n >= cnp) { if (tid == 0) alp[b * N_ + n] = 0.5f; return; }
    for (int m = tid; m < cnp; m += 256) dv[m] = d2[b * N_ + m] * v[b * N_ + m];
    __syncthreads();
    const float4* row4 = (const float4*)(Ac + ((size_t)(b * N_ + n)) * N_);
    const float4* dv4 = (const float4*)dv;
    float s = 0.f;
    for (int m = tid; m < (cnp >> 2); m += 256) {
        float4 a = row4[m], w = dv4[m];
        s += a.x * w.x + a.y * w.y + a.z * w.z + a.w * w.w;
    }
    red[tid] = s; __syncthreads();
    for (int o = 128; o > 0; o >>= 1) { if (tid < o) red[tid] += red[tid + o]; __syncthreads(); }
    if (tid == 0) {
        float r = rz2[b * N_ + n] * d2[b * N_ + n] * (red[0] + dv[n]);
        alp[b * N_ + n] = 1.f / (1.f + expf(-r * r));
    }
}

__global__ void s2inv_kernel(const float* __restrict__ Ac, const float* __restrict__ d2,
                             const float* __restrict__ rz2, const float* __restrict__ ca,
                             const int* __restrict__ cnt, float* __restrict__ sinv) {
    __shared__ float dca[N_];
    __shared__ float red[256];
    int b = blockIdx.y, n = blockIdx.x, tid = threadIdx.x;
    int cnp = (cnt[b] + 127) & ~127;
    if (n >= cnp) return;
    for (int m = tid; m < cnp; m += 256) dca[m] = d2[b * N_ + m] * ca[b * N_ + m];
    __syncthreads();
    const float4* row4 = (const float4*)(Ac + ((size_t)(b * N_ + n)) * N_);
    const float4* dca4 = (const float4*)dca;
    float s = 0.f;
    for (int m = tid; m < (cnp >> 2); m += 256) {
        float4 a = row4[m], w = dca4[m];
        s += a.x * w.x + a.y * w.y + a.z * w.z + a.w * w.w;
    }
    red[tid] = s; __syncthreads();
    for (int o = 128; o > 0; o >>= 1) { if (tid < o) red[tid] += red[tid + o]; __syncthreads(); }
    if (tid == 0) {
        float sum = red[0] + dca[n];
        float f = rz2[b * N_ + n] * d2[b * N_ + n];
        sinv[b * N_ + n] = f / fmaxf(f * sum, 1e-12f);
    }
}

__global__ void buildST_kernel(const float* __restrict__ Ac, const float* __restrict__ d2,
                               const float* __restrict__ ca, const float* __restrict__ sinv,
                               const int* __restrict__ cnt,
                               __nv_bfloat16* __restrict__ SThi, __nv_bfloat16* __restrict__ STlo) {
    __shared__ float siv[N_];
    int b = blockIdx.y, m = blockIdx.x, tid = threadIdx.x;
    int cnp = (cnt[b] + 127) & ~127;
    if (m >= cnp) return;
    for (int n = tid; n < cnp; n += 256) siv[n] = sinv[b * N_ + n];
    __syncthreads();
    float dcam = d2[b * N_ + m] * ca[b * N_ + m];
    size_t ro = ((size_t)(b * N_ + m)) * N_;
    const float4* row4 = (const float4*)(Ac + ro);
    __nv_bfloat162* ohi = (__nv_bfloat162*)(SThi + ro);
    __nv_bfloat162* olo = (__nv_bfloat162*)(STlo + ro);
    for (int q = tid; q < (cnp >> 2); q += 256) {
        float4 a = row4[q];
        int n = q << 2;
        float v0 = (a.x + ((n    ) == m ? 1.f : 0.f)) * dcam * siv[n];
        float v1 = (a.y + ((n + 1) == m ? 1.f : 0.f)) * dcam * siv[n + 1];
        float v2 = (a.z + ((n + 2) == m ? 1.f : 0.f)) * dcam * siv[n + 2];
        float v3 = (a.w + ((n + 3) == m ? 1.f : 0.f)) * dcam * siv[n + 3];
        __nv_bfloat162 h01 = split_hi2(v0, v1), h23 = split_hi2(v2, v3);
        ohi[q * 2] = h01; ohi[q * 2 + 1] = h23;
        olo[q * 2] = split_lo2(v0, v1, h01); olo[q * 2 + 1] = split_lo2(v2, v3, h23);
    }
}

__global__ void wvec_kernel(const float* __restrict__ A3, const float* __restrict__ d2,
                            const float* __restrict__ maskc, const int* __restrict__ cnt,
                            float* __restrict__ wv) {
    __shared__ float dv[N_];
    __shared__ float red[256];
    int b = blockIdx.y, k = blockIdx.x, tid = threadIdx.x;
    int cnp = (cnt[b] + 127) & ~127;
    if (k >= cnp) return;
    for (int m = tid; m < cnp; m += 256) dv[m] = d2[b * N_ + m] * maskc[b * N_ + m];
    __syncthreads();
    const float* row = A3 + ((size_t)(b * N_ + k)) * N_;
    const float4* row4 = (const float4*)row;
    const float4* dv4 = (const float4*)dv;
    float s = 0.f;
    for (int m = tid; m < (cnp >> 2); m += 256) {
        float4 a = row4[m], w = dv4[m];
        s += a.x * w.x + a.y * w.y + a.z * w.z + a.w * w.w;
    }
    red[tid] = s; __syncthreads();
    for (int o = 128; o > 0; o >>= 1) { if (tid < o) red[tid] += red[tid + o]; __syncthreads(); }
    if (tid == 0)
        wv[b * N_ + k] = d2[b * N_ + k] * (red[0] - row[k] * dv[k] + dv[k]);
}

// yv partial: yp[b][q][c] = sum_{k in chunk q} wv[k] * x3[k][c]   (c < H_)
__global__ void out2v_kernel(const float* __restrict__ x3, const float* __restrict__ wv,
                             const int* __restrict__ cnt, float* __restrict__ yp) {
    int b = blockIdx.y, q = blockIdx.x, c = threadIdx.x;   // 128 threads
    int cnp = (cnt[b] + 127) & ~127;
    int lo = q * 512, hi = (q + 1) * 512; if (hi > cnp) hi = cnp;
    float s = 0.f;
    for (int k = lo; k < hi; k++)
        s = fmaf(wv[b * N_ + k], x3[((size_t)(b * N_ + k)) * H_ + c], s);
    yp[(b * 4 + q) * F_ + c] = s;
}

__global__ void split_tr_kernel(const float* __restrict__ in, __nv_bfloat16* __restrict__ hi,
                                __nv_bfloat16* __restrict__ lo, const int* __restrict__ cnt,
                                int Rfixed, int Cfixed, int ld, long sIn, long sOut) {
    __shared__ float tile[32][33];
    int b = blockIdx.z;
    int cnp = (cnt[b] + 127) & ~127;
    int R = Rfixed ? Rfixed : cnp;
    int C = Cfixed ? Cfixed : cnp;
    int i0 = blockIdx.y * 32, j0 = blockIdx.x * 32;
    if (i0 >= R || j0 >= C) return;
    const float* inb = in + (size_t)b * sIn;
    size_t boff = (size_t)b * sOut;
    int tx = threadIdx.x, ty = threadIdx.y;   // (32, 8)
    #pragma unroll
    for (int r = 0; r < 4; r++) {
        int i = ty + r * 8;
        tile[i][tx] = inb[(size_t)(i0 + i) * ld + j0 + tx];
    }
    __syncthreads();
    #pragma unroll
    for (int r = 0; r < 4; r++) {
        int j = ty + r * 8;
        float v = tile[tx][j];
        __nv_bfloat16 h = __float2bfloat16(v);
        size_t o = boff + (size_t)(j0 + j) * N_ + i0 + tx;
        hi[o] = h;
        lo[o] = __float2bfloat16(v - __bfloat162float(h));
    }
}

// ---------------- bf16-split tensor GEMM, single-K-pass ----------------------
#define TSZ (128 * 40)
template<int EPI>
__global__ void __launch_bounds__(256, 2) gemm_bf16_kernel(
    const __nv_bfloat16* __restrict__ Ahi, const __nv_bfloat16* __restrict__ Alo,
    const __nv_bfloat16* __restrict__ BThi, const __nv_bfloat16* __restrict__ BTlo,
    float* __restrict__ C, const int* __restrict__ cnt,
    int ldc, long sC,
    __nv_bfloat16* __restrict__ Chi, __nv_bfloat16* __restrict__ Clo,
    const __nv_bfloat16* __restrict__ B2hi, const __nv_bfloat16* __restrict__ B2lo,
    float* __restrict__ C2, int ldc2, long sC2) {
    extern __shared__ __nv_bfloat16 sm[];
    const int b = blockIdx.z;
    const int cnp = (cnt[b] + 127) & ~127;
    const int m0 = blockIdx.y * 128;
    const int n0 = blockIdx.x * 128;
    const bool reg2 = (EPI == 4) && (blockIdx.x == gridDim.x - 1);
    if (m0 >= cnp) return;
    if (!reg2) {
        if (n0 >= cnp) return;
        if (EPI == 5 && m0 > n0) return;
    }
    const size_t boff = (size_t)b * N_ * N_;
    const int tid = threadIdx.x;
    const int wid = tid >> 5, lane = tid & 31;
    const int wm = wid >> 1, wn = wid & 1;
    const int g = lane >> 2, t4 = lane & 3;
    const int a_row = lane & 15;
    const int a_k   = (lane & 16) ? 8 : 0;
    const int b_row = (lane & 7) + ((lane & 16) ? 8 : 0);
    const int b_k   = (lane & 8) ? 8 : 0;
    const int KT = cnp >> 5;

    float acc[2][8][4];
    #pragma unroll
    for (int fm = 0; fm < 2; fm++)
        #pragma unroll
        for (int fn = 0; fn < 8; fn++)
            #pragma unroll
            for (int r = 0; r < 4; r++) acc[fm][fn][r] = 0.f;

    const __nv_bfloat16* gsrc[4];
    auto stage = [&](int kt, int buf) {
        gsrc[0] = Ahi + boff + (size_t)m0 * N_ + kt * 32;
        gsrc[1] = Alo + boff + (size_t)m0 * N_ + kt * 32;
        if (reg2) {
            gsrc[2] = B2hi + (size_t)b * H_ * N_ + kt * 32;
            gsrc[3] = B2lo + (size_t)b * H_ * N_ + kt * 32;
        } else {
            gsrc[2] = BThi + boff + (size_t)n0 * N_ + kt * 32;
            gsrc[3] = BTlo + boff + (size_t)n0 * N_ + kt * 32;
        }
        int row = tid >> 2, cc = (tid & 3) * 8;
        #pragma unroll
        for (int w = 0; w < 4; w++) {
            __nv_bfloat16* dst = sm + (size_t)(buf * 4 + w) * TSZ;
            CP16(dst + row * 40 + cc,        gsrc[w] + (size_t)row * N_ + cc);
            CP16(dst + (row + 64) * 40 + cc, gsrc[w] + (size_t)(row + 64) * N_ + cc);
        }
    };

    stage(0, 0);
    CP_COMMIT();

    for (int t = 0; t < KT; t++) {
        CP_WAIT0();
        __syncthreads();
        if (t + 1 < KT) { stage(t + 1, (t + 1) & 1); CP_COMMIT(); }
        const __nv_bfloat16* Ah = sm + (size_t)((t & 1) * 4 + 0) * TSZ;
        const __nv_bfloat16* Al = sm + (size_t)((t & 1) * 4 + 1) * TSZ;
        const __nv_bfloat16* Bh = sm + (size_t)((t & 1) * 4 + 2) * TSZ;
        const __nv_bfloat16* Bl = sm + (size_t)((t & 1) * 4 + 3) * TSZ;
        #pragma unroll
        for (int kh = 0; kh < 32; kh += 16) {
            uint32_t ah[2][4], al[2][4];
            #pragma unroll
            for (int fm = 0; fm < 2; fm++) {
                int ao = (wm * 32 + fm * 16 + a_row) * 40 + kh + a_k;
                ldsm4(ah[fm], Ah + ao);
                ldsm4(al[fm], Al + ao);
            }
            #pragma unroll
            for (int fn2 = 0; fn2 < 4; fn2++) {
                int bo = (wn * 64 + fn2 * 16 + b_row) * 40 + kh + b_k;
                uint32_t bh[4], bl[4];
                ldsm4(bh, Bh + bo);
                ldsm4(bl, Bl + bo);
                #pragma unroll
                for (int fm = 0; fm < 2; fm++) {
                    mma_bf16(acc[fm][2 * fn2],     ah[fm], bh[0], bh[1]);
                    mma_bf16(acc[fm][2 * fn2],     ah[fm], bl[0], bl[1]);
                    mma_bf16(acc[fm][2 * fn2],     al[fm], bh[0], bh[1]);
                    mma_bf16(acc[fm][2 * fn2 + 1], ah[fm], bh[2], bh[3]);
                    mma_bf16(acc[fm][2 * fn2 + 1], ah[fm], bl[2], bl[3]);
                    mma_bf16(acc[fm][2 * fn2 + 1], al[fm], bh[2], bh[3]);
                }
            }
        }
        __syncthreads();
    }

    float* smf = (float*)sm;
    #pragma unroll
    for (int fm = 0; fm < 2; fm++) {
        int mr = m0 + wm * 32 + fm * 16 + g;
        #pragma unroll
        for (int fn = 0; fn < 8; fn++) {
            int lc = wn * 64 + fn * 8 + t4 * 2;
            float v0 = acc[fm][fn][0], v1 = acc[fm][fn][1];
            float v2 = acc[fm][fn][2], v3 = acc[fm][fn][3];
            if (reg2) {
                float* p0 = C2 + (size_t)b * sC2 + (size_t)mr * ldc2 + lc;
                p0[0] = v0; p0[1] = v1;
                float* p1 = p0 + 8 * (size_t)ldc2;
                p1[0] = v2; p1[1] = v3;
            } else if (EPI == 5) {
                v0 = floorf(v0 * 10000.f) / 10000.f;
                v1 = floorf(v1 * 10000.f) / 10000.f;
                v2 = floorf(v2 * 10000.f) / 10000.f;
                v3 = floorf(v3 * 10000.f) / 10000.f;
                int r = wm * 32 + fm * 16 + g;
                smf[(lc    ) * 133 + r]     = v0;
                smf[(lc + 1) * 133 + r]     = v1;
                smf[(lc    ) * 133 + r + 8] = v2;
                smf[(lc + 1) * 133 + r + 8] = v3;
                int n = n0 + lc;
                float* p0 = C + (size_t)b * sC + (size_t)mr * ldc + n;
                p0[0] = v0; p0[1] = v1;
                float* p1 = p0 + 8 * (size_t)ldc;
                p1[0] = v2; p1[1] = v3;
            } else {
                int n = n0 + lc;
                size_t o0 = (size_t)b * sC + (size_t)mr * ldc + n;
                size_t o1 = o0 + 8 * (size_t)ldc;
                __nv_bfloat162 h0 = split_hi2(v0, v1), h1 = split_hi2(v2, v3);
                *(__nv_bfloat162*)(Chi + o0) = h0;
                *(__nv_bfloat162*)(Chi + o1) = h1;
                *(__nv_bfloat162*)(Clo + o0) = split_lo2(v0, v1, h0);
                *(__nv_bfloat162*)(Clo + o1) = split_lo2(v2, v3, h1);
            }
        }
    }
    if (EPI == 5 && m0 != n0) {
        __syncthreads();
        float* Cb = C + (size_t)b * sC;
        for (int e = tid; e < 128 * 128; e += 256) {
            int r2 = e >> 7, c2 = e & 127;
            Cb[(size_t)(n0 + r2) * ldc + m0 + c2] = smf[r2 * 133 + c2];
        }
    }
}

// ---------------- double-buffered cp.async SIMT GEMM (x@W1 only) -------------
template<int TRANSA, int EPI>
__global__ void __launch_bounds__(256, 2) gemm2_kernel(
    const float* __restrict__ A, const float* __restrict__ Bm, float* __restrict__ C,
    int M, int Kd, int Nc, int lda, int ldb, int ldc,
    long sA, long sB, long sC,
    const float* __restrict__ bias, const float* __restrict__ mask,
    const int* __restrict__ cnt, int dynM, int dynK, int dynN) {
    __shared__ float As[2][128 * 16];
    __shared__ float Bs[2][16 * 128];
    const int b = blockIdx.z;
    int Mp = M, Kp = Kd, Np = Nc;
    if (cnt) {
        int p = (cnt[b] + 127) & ~127;
        if (dynM) Mp = p; if (dynK) Kp = p; if (dynN) Np = p;
    }
    const int n0 = blockIdx.x * 128, m0 = blockIdx.y * 128;
    if (m0 >= Mp || n0 >= Np) return;
    A  += (size_t)b * sA;
    Bm += (size_t)b * sB;
    C  += (size_t)b * sC;
    const int tid = threadIdx.x, tx = tid & 15, ty = tid >> 4;
    float acc[8][8];
    #pragma unroll
    for (int i = 0; i < 8; i++)
        #pragma unroll
        for (int j = 0; j < 8; j++) acc[i][j] = 0.f;

    const int Kt = Kp >> 4;

    auto load_tiles = [&](int k0, int buf) {
        if (!TRANSA) {
            #pragma unroll
            for (int q = 0; q < 2; q++) {
                int c = tid + q * 256;
                int row = c >> 2, col4 = (c & 3) * 4;
                const float* src = A + (size_t)(m0 + row) * lda + k0 + col4;
                CP16(&As[buf][row * 16 + col4], src);
            }
        } else {
            #pragma unroll
            for (int q = 0; q < 2; q++) {
                int c = tid + q * 256;
                int row = c >> 5, col4 = (c & 31) * 4;
                const float* src = A + (size_t)(k0 + row) * lda + m0 + col4;
                CP16(&As[buf][row * 128 + col4], src);
            }
        }
        #pragma unroll
        for (int q = 0; q < 2; q++) {
            int c = tid + q * 256;
            int row = c >> 5, col4 = (c & 31) * 4;
            const float* src = Bm + (size_t)(k0 + row) * ldb + n0 + col4;
            CP16(&Bs[buf][row * 128 + col4], src);
        }
    };

    load_tiles(0, 0);
    CP_COMMIT();

    for (int t = 0; t < Kt; t++) {
        CP_WAIT0();
        __syncthreads();
        if (t + 1 < Kt) { load_tiles((t + 1) << 4, (t + 1) & 1); CP_COMMIT(); }
        const int buf = t & 1;
        #pragma unroll
        for (int k = 0; k < 16; k++) {
            float a[8], bv[8];
            if (!TRANSA) {
                #pragma unroll
                for (int i = 0; i < 8; i++) a[i] = As[buf][(ty * 8 + i) * 16 + k];
            } else {
                *(float4*)(a)     = *(const float4*)&As[buf][k * 128 + ty * 8];
                *(float4*)(a + 4) = *(const float4*)&As[buf][k * 128 + ty * 8 + 4];
            }
            *(float4*)(bv)     = *(const float4*)&Bs[buf][k * 128 + tx * 8];
            *(float4*)(bv + 4) = *(const float4*)&Bs[buf][k * 128 + tx * 8 + 4];
            #pragma unroll
            for (int i = 0; i < 8; i++)
                #pragma unroll
                for (int j = 0; j < 8; j++) acc[i][j] = fmaf(a[i], bv[j], acc[i][j]);
        }
        __syncthreads();
    }
    #pragma unroll
    for (int i = 0; i < 8; i++) {
        int m = m0 + ty * 8 + i;
        float mk = (EPI == 2) ? mask[(size_t)b * N_ + m] : 1.f;
        #pragma unroll
        for (int j = 0; j < 8; j++) {
            int n = n0 + tx * 8 + j;
            float v = acc[i][j];
            if (EPI == 2)      { v = (v + bias[n]) * mk; }
            else if (EPI == 3) { v = floorf(v * 10000.f) / 10000.f; }
            C[(size_t)m * ldc + n] = v;
        }
    }
}

// ---------------- output means ------------------------------------------------
__global__ void mean1_part_kernel(const float* __restrict__ x1, float* __restrict__ p1) {
    int b = blockIdx.y, q = blockIdx.x, c = threadIdx.x;   // 128 threads
    float s = 0.f;
    for (int n = q * 512; n < (q + 1) * 512; n++) s += x1[((size_t)(b * N_ + n)) * H_ + c];
    p1[(b * 4 + q) * H_ + c] = s;
}

// out[b][0:H] = mean(x1); out[b][H:] = (y @ W2 + b2*smask)/N, y = sum of yp
__global__ void mean_combine_kernel(const float* __restrict__ p1, const float* __restrict__ yp,
                                    const float* __restrict__ W2, const float* __restrict__ b2,
                                    const float* __restrict__ smask, float* __restrict__ out) {
    __shared__ float ysh[H_];
    int b = blockIdx.x, c = threadIdx.x;   // 384 threads
    if (c < H_) {
        float y = 0.f;
        for (int q = 0; q < 4; q++) y += yp[(b * 4 + q) * F_ + c];
        ysh[c] = y;
    }
    __syncthreads();
    if (c < H_) {
        float s = 0.f;
        for (int q = 0; q < 4; q++) s += p1[(b * 4 + q) * H_ + c];
        out[b * OUTC + c] = s / (float)N_;
    } else {
        int f = c - H_;
        float s = b2[f] * smask[b];
        #pragma unroll 4
        for (int cc = 0; cc < H_; cc++)
            s = fmaf(ysh[cc], W2[cc * F_ + f], s);
        out[b * OUTC + c] = s / (float)N_;
    }
}

extern "C" void kernel_launch(void* const* d_in, const int* in_sizes, int n_in,
                              void* d_out, int out_size) {
    const float* x    = (const float*)d_in[0];
    const float* adj  = (const float*)d_in[1];
    const float* mask = (const float*)d_in[2];
    const float* W1   = (const float*)d_in[3];
    const float* b1   = (const float*)d_in[4];
    const float* Watt = (const float*)d_in[5];
    const float* batt = (const float*)d_in[6];
    const float* W2   = (const float*)d_in[7];
    const float* b2   = (const float*)d_in[8];
    float* out = (float*)d_out;

    float *pT,*pAc,*pA3,*pxW,*px1,*pxc,*px3;
    float *pv,*palp,*pca,*psrec,*pd0,*pd1,*prnz,*pd2,*prz2,*pcut,*pmaskc,*pmrest,*pp1,*pp2;
    __nv_bfloat16 *pAhi,*pAlo,*pSThi,*pSTlo,*pTThi,*pTTlo,*pxTh,*pxTl;
    int *plst,*pdeg,*phasd,*pidx,*pginv,*pcnt;
    cudaGetSymbolAddress((void**)&pT,   g_T);
    cudaGetSymbolAddress((void**)&pAc,  g_Ac);
    cudaGetSymbolAddress((void**)&pA3,  g_A3);
    cudaGetSymbolAddress((void**)&pAhi, g_Ahi);
    cudaGetSymbolAddress((void**)&pAlo, g_Alo);
    cudaGetSymbolAddress((void**)&pSThi,g_SThi);
    cudaGetSymbolAddress((void**)&pSTlo,g_STlo);
    cudaGetSymbolAddress((void**)&pTThi,g_TThi);
    cudaGetSymbolAddress((void**)&pTTlo,g_TTlo);
    cudaGetSymbolAddress((void**)&pxTh, g_xTh);
    cudaGetSymbolAddress((void**)&pxTl, g_xTl);
    cudaGetSymbolAddress((void**)&pxW,  g_xW);
    cudaGetSymbolAddress((void**)&px1,  g_x1);
    cudaGetSymbolAddress((void**)&pxc,  g_xc);
    cudaGetSymbolAddress((void**)&px3,  g_x3);
    cudaGetSymbolAddress((void**)&pv,   g_v);
    cudaGetSymbolAddress((void**)&palp, g_alp);
    cudaGetSymbolAddress((void**)&pca,  g_ca);
    cudaGetSymbolAddress((void**)&psrec,g_srec);
    cudaGetSymbolAddress((void**)&pd0,  g_d0);
    cudaGetSymbolAddress((void**)&pd1,  g_d1);
    cudaGetSymbolAddress((void**)&prnz, g_rnz);
    cudaGetSymbolAddress((void**)&pd2,  g_d2);
    cudaGetSymbolAddress((void**)&prz2, g_rz2);
    cudaGetSymbolAddress((void**)&pcut, g_cut);
    cudaGetSymbolAddress((void**)&pmaskc, g_maskc);
    cudaGetSymbolAddress((void**)&pmrest, g_mrest);
    cudaGetSymbolAddress((void**)&pp1,  g_p1);
    cudaGetSymbolAddress((void**)&pp2,  g_p2);
    cudaGetSymbolAddress((void**)&plst, g_lst);
    cudaGetSymbolAddress((void**)&pdeg, g_deg);
    cudaGetSymbolAddress((void**)&phasd,g_hasd);
    cudaGetSymbolAddress((void**)&pidx, g_idx);
    cudaGetSymbolAddress((void**)&pginv,g_ginv);
    cudaGetSymbolAddress((void**)&pcnt, g_cnt);

    const int BF16_SMEM = 2 * 4 * TSZ * 2;   // 81920 bytes
    cudaFuncSetAttribute(gemm_bf16_kernel<4>, cudaFuncAttributeMaxDynamicSharedMemorySize, BF16_SMEM);
    cudaFuncSetAttribute(gemm_bf16_kernel<5>, cudaFuncAttributeMaxDynamicSharedMemorySize, BF16_SMEM);

    // ---- CSR + degree stats ----
    csr_build_kernel<<<dim3(N_, B_), 256>>>(adj, plst, pdeg, phasd, pd0, pd1, prnz);

    // ---- GCN layer 1 (fused v) ----
    gemm2_kernel<0,0><<<dim3(1,16,B_),256>>>(x, W1, pxW, N_, F_, H_, F_, H_, H_,
        (long)N_*F_, 0, (long)N_*H_, nullptr, nullptr, nullptr, 0,0,0);
    gcn1_kernel<<<dim3(N_, B_), 128>>>(plst, pdeg, pd0, pxW, b1, mask, Watt, batt, px1, pv);

    // ---- coarsen layer 1 (sparse) ----
    alpha1_kernel<<<dim3(N_/8, B_), 256>>>(plst, pdeg, pd1, prnz, pv, palp);
    topk_cut_kernel<<<B_, 1024>>>(palp, pcut, pca);
    compact_kernel<<<B_, 1024>>>(pca, mask, pidx, pginv, pcnt, pmaskc, pmrest);
    srec_kernel<<<dim3(N_/8, B_), 256>>>(plst, pdeg, pd1, prnz, pca, psrec);
    xupd_kernel<<<dim3(N_, B_), 128>>>(plst, pdeg, phasd, pd1, pca, psrec, pidx, pcnt,
                                       px1, Watt, batt, pxc, pv);
    adjS_sparse_kernel<<<dim3(N_/4, B_), 128>>>(plst, pdeg, phasd, pd1, pca, psrec,
                                                pginv, pcnt, pT);
    STT_kernel<<<dim3(N_, B_), 256>>>(plst, pdeg, phasd, pd1, pca, psrec, pidx, pcnt,
                                      pT, pAc, pAhi, pAlo, pd2, prz2);

    // ---- coarsen layer 2 ----
    alpha2d_kernel<<<dim3(N_, B_), 256>>>(pAc, pd2, prz2, pv, pcnt, palp);
    topk_cut_kernel<<<B_, 1024>>>(palp, pcut, pca);
    s2inv_kernel<<<dim3(N_, B_), 256>>>(pAc, pd2, prz2, pca, pcnt, psrec);
    buildST_kernel<<<dim3(N_, B_), 256>>>(pAc, pd2, pca, psrec, pcnt, pSThi, pSTlo);
    split_tr_kernel<<<dim3(4, 64, B_), dim3(32, 8)>>>(pxc, pxTh, pxTl, pcnt,
        0, H_, H_, (long)N_*H_, (long)H_*N_);
    // MERGED: T2^T = ST @ Ac^T (bf16 split -> TT)  AND  x3 = ST @ xc (fp32)
    gemm_bf16_kernel<4><<<dim3(17,16,B_),256,BF16_SMEM>>>(pSThi, pSTlo, pAhi, pAlo,
        nullptr, pcnt, N_, (long)N_*N_, pTThi, pTTlo,
        pxTh, pxTl, px3, H_, (long)N_*H_);
    // A3 = ST @ T2 (symmetric): upper blocks only, floor-quant, mirror write
    gemm_bf16_kernel<5><<<dim3(16,16,B_),256,BF16_SMEM>>>(pSThi, pSTlo, pTThi, pTTlo,
        pA3, pcnt, N_, (long)N_*N_, nullptr, nullptr,
        nullptr, nullptr, nullptr, 0, 0);

    // ---- final GCN: mean only; reassociated (w^T x3) @ W2 ----
    rowstats_c_kernel<<<dim3(N_, B_), 256>>>(pA3, pcnt, pd2, nullptr, 0);
    wvec_kernel<<<dim3(N_, B_), 256>>>(pA3, pd2, pmaskc, pcnt, pv);
    out2v_kernel<<<dim3(4, B_), 128>>>(px3, pv, pcnt, pp2);

    // ---- concat means ----
    mean1_part_kernel<<<dim3(4, B_), 128>>>(px1, pp1);
    mean_combine_kernel<<<B_, 384>>>(pp1, pp2, W2, b2, pmrest, out);
}

// round 16
// speedup vs baseline: 8.9280x; 1.0207x over previous
#include <cuda_runtime.h>
#include <cuda_bf16.h>
#include <math.h>
#include <stdint.h>

#define B_ 8
#define N_ 2048
#define F_ 256
#define H_ 128
#define K_ 1025
#define OUTC 384
#define CAP 256

// ---------------- scratch (device globals; no allocation allowed) ----------
__device__ float g_T [(size_t)B_*N_*N_];
__device__ float g_Ac[(size_t)B_*N_*N_];
__device__ float g_A3[(size_t)B_*N_*N_];
__device__ __nv_bfloat16 g_Ahi[(size_t)B_*N_*N_], g_Alo[(size_t)B_*N_*N_];
__device__ __nv_bfloat16 g_SThi[(size_t)B_*N_*N_], g_STlo[(size_t)B_*N_*N_];
__device__ __nv_bfloat16 g_TThi[(size_t)B_*N_*N_], g_TTlo[(size_t)B_*N_*N_];
__device__ __nv_bfloat16 g_xTh[B_*H_*N_], g_xTl[B_*H_*N_];
__device__ float g_xW [B_*N_*F_];
__device__ float g_x1 [B_*N_*H_];
__device__ float g_xc [B_*N_*H_];
__device__ float g_x3 [B_*N_*H_];
__device__ int   g_lst[(size_t)B_*N_*CAP];
__device__ int   g_deg[B_*N_];
__device__ int   g_hasd[B_*N_];
__device__ float g_d0[B_*N_], g_d1[B_*N_], g_rnz[B_*N_];
__device__ float g_d2[B_*N_], g_rz2[B_*N_];
__device__ float g_v[B_*N_], g_alp[B_*N_], g_ca[B_*N_], g_srec[B_*N_];
__device__ int2  g_pk[B_*N_];   // {ginv, bitcast(d1*ca)}
__device__ float g_cut[B_];
__device__ float g_maskc[B_*N_], g_mrest[B_];
__device__ int   g_idx[B_*N_], g_ginv[B_*N_], g_cnt[B_];
__device__ float g_p1[B_*4*H_], g_p2[B_*4*F_];

// ---------------- async-copy / mma helpers -----------------------------------
#define CP16(dst, src) { \
    unsigned _a = (unsigned)__cvta_generic_to_shared(dst); \
    asm volatile("cp.async.cg.shared.global [%0], [%1], 16;\n" :: "r"(_a), "l"(src)); }
#define CP_COMMIT() asm volatile("cp.async.commit_group;\n")
#define CP_WAIT0()  asm volatile("cp.async.wait_group 0;\n")

__device__ __forceinline__ void mma_bf16(float* c, const uint32_t* a, uint32_t b0, uint32_t b1) {
    asm volatile("mma.sync.aligned.m16n8k16.row.col.f32.bf16.bf16.f32 "
        "{%0,%1,%2,%3}, {%4,%5,%6,%7}, {%8,%9}, {%0,%1,%2,%3};"
        : "+f"(c[0]), "+f"(c[1]), "+f"(c[2]), "+f"(c[3])
        : "r"(a[0]), "r"(a[1]), "r"(a[2]), "r"(a[3]), "r"(b0), "r"(b1));
}
__device__ __forceinline__ void ldsm4(uint32_t* r, const void* p) {
    uint32_t a = (uint32_t)__cvta_generic_to_shared(p);
    asm volatile("ldmatrix.sync.aligned.m8n8.x4.shared.b16 {%0,%1,%2,%3}, [%4];"
        : "=r"(r[0]), "=r"(r[1]), "=r"(r[2]), "=r"(r[3]) : "r"(a));
}
__device__ __forceinline__ __nv_bfloat162 split_hi2(float v0, float v1) {
    __nv_bfloat162 h; h.x = __float2bfloat16(v0); h.y = __float2bfloat16(v1); return h;
}
__device__ __forceinline__ __nv_bfloat162 split_lo2(float v0, float v1, __nv_bfloat162 h) {
    __nv_bfloat162 l;
    l.x = __float2bfloat16(v0 - __bfloat162float(h.x));
    l.y = __float2bfloat16(v1 - __bfloat162float(h.y));
    return l;
}

// ---------------- CSR build + degree stats (one adj scan, float4) -----------
__global__ void csr_build_kernel(const float* __restrict__ adj, int* __restrict__ lst,
                                 int* __restrict__ deg, int* __restrict__ hasd,
                                 float* __restrict__ d0, float* __restrict__ d1,
                                 float* __restrict__ rnz) {
    __shared__ int sc[256];
    __shared__ int hd;
    int b = blockIdx.y, i = blockIdx.x, tid = threadIdx.x;
    const float4* arow4 = (const float4*)(adj + ((size_t)(b * N_ + i)) * N_);
    if (tid == 0) hd = 0;
    __syncthreads();
    float vals[8];
    *(float4*)(vals)     = arow4[tid * 2];
    *(float4*)(vals + 4) = arow4[tid * 2 + 1];
    int f[8];
    int c = 0, hloc = 0;
    #pragma unroll
    for (int e = 0; e < 8; e++) {
        int j = tid * 8 + e;
        f[e] = (vals[e] != 0.f) ? 1 : 0;
        c += f[e];
        if (f[e] && j == i) hloc = 1;
    }
    if (hloc) hd = 1;
    sc[tid] = c; __syncthreads();
    for (int o = 1; o < 256; o <<= 1) {
        int v = (tid >= o) ? sc[tid - o] : 0; __syncthreads();
        sc[tid] += v; __syncthreads();
    }
    int base = sc[tid] - c;
    int* l = lst + ((size_t)(b * N_ + i)) * CAP;
    #pragma unroll
    for (int e = 0; e < 8; e++) {
        if (f[e]) { if (base < CAP) l[base] = tid * 8 + e; base++; }
    }
    __syncthreads();
    if (tid == 0) {
        int total = sc[255];
        deg[b * N_ + i] = (total > CAP) ? CAP : total;
        hasd[b * N_ + i] = hd;
        d0[b * N_ + i] = rsqrtf(fmaxf((float)(total - hd) + 1.f, 1.f));
        d1[b * N_ + i] = rsqrtf((float)total + 1.f);
        rnz[b * N_ + i] = (total > 0) ? 1.f : 0.f;
    }
}

// -- GCN layer 1 sparse aggregation; fused v = x1 @ Watt + batt ---------------
__global__ void gcn1_kernel(const int* __restrict__ lst, const int* __restrict__ deg,
                            const float* __restrict__ d0, const float* __restrict__ xW,
                            const float* __restrict__ b1, const float* __restrict__ mask,
                            const float* __restrict__ Watt, const float* __restrict__ batt,
                            float* __restrict__ x1, float* __restrict__ v) {
    __shared__ int   jl[CAP];
    __shared__ float cf[CAP];
    __shared__ float red[128];
    int b = blockIdx.y, i = blockIdx.x, c = threadIdx.x;   // 128 threads
    int dg = deg[b * N_ + i];
    const int* l = lst + ((size_t)(b * N_ + i)) * CAP;
    float di = d0[b * N_ + i];
    for (int p = c; p < dg; p += 128) {
        int j = l[p];
        jl[p] = j;
        cf[p] = (j == i) ? 0.f : di * d0[b * N_ + j];
    }
    __syncthreads();
    float acc = di * di * xW[((size_t)(b * N_ + i)) * H_ + c];
    #pragma unroll 4
    for (int p = 0; p < dg; p++)
        acc = fmaf(cf[p], xW[((size_t)(b * N_ + jl[p])) * H_ + c], acc);
    float vv = (acc + b1[c]) * mask[b * N_ + i];
    vv = fmaxf(vv, 0.f);
    x1[((size_t)(b * N_ + i)) * H_ + c] = vv;
    red[c] = vv * Watt[c];
    __syncthreads();
    for (int o = 64; o > 0; o >>= 1) { if (c < o) red[c] += red[c + o]; __syncthreads(); }
    if (c == 0) v[b * N_ + i] = red[0] + batt[0];
}

// ---------------- layer-1 alpha (sparse) --------------------------------------
__global__ void alpha1_kernel(const int* __restrict__ lst, const int* __restrict__ deg,
                              const float* __restrict__ d1, const float* __restrict__ rnz,
                              const float* __restrict__ v, float* __restrict__ alp) {
    int b = blockIdx.y;
    int i = blockIdx.x * 8 + (threadIdx.x >> 5);
    int lane = threadIdx.x & 31;
    const int* l = lst + ((size_t)(b * N_ + i)) * CAP;
    int dg = deg[b * N_ + i];
    float s = 0.f;
    for (int p = lane; p < dg; p += 32) { int j = l[p]; s += d1[b * N_ + j] * v[b * N_ + j]; }
    #pragma unroll
    for (int o = 16; o > 0; o >>= 1) s += __shfl_down_sync(0xffffffffu, s, o);
    if (lane == 0) {
        float di = d1[b * N_ + i];
        float r = rnz[b * N_ + i] * di * (s + di * v[b * N_ + i]);
        float z = r * r;
        alp[b * N_ + i] = 1.f / (1.f + expf(-z));
    }
}

// ---- exact K-th largest via 4-pass radix select; fused ca epilogue ----------
__global__ void topk_cut_kernel(const float* __restrict__ alp, float* __restrict__ cut,
                                float* __restrict__ ca) {
    __shared__ int hist[256];
    __shared__ unsigned pref;
    __shared__ int rem;
    int b = blockIdx.x, t = threadIdx.x;   // 1024 threads
    float a0 = alp[b * N_ + t], a1 = alp[b * N_ + t + 1024];
    unsigned v0 = __float_as_uint(a0);
    unsigned v1 = __float_as_uint(a1);
    if (t == 0) { pref = 0u; rem = N_ - K_ + 1; }
    __syncthreads();
    #pragma unroll
    for (int pass = 0; pass < 4; pass++) {
        int shift = 24 - pass * 8;
        if (t < 256) hist[t] = 0;
        __syncthreads();
        unsigned maskA = (pass == 0) ? 0u : (0xFFFFFFFFu << (shift + 8));
        unsigned pr = pref;
        if ((v0 & maskA) == pr) atomicAdd(&hist[(v0 >> shift) & 255], 1);
        if ((v1 & maskA) == pr) atomicAdd(&hist[(v1 >> shift) & 255], 1);
        __syncthreads();
        if (t == 0) {
            int r = rem;
            unsigned bin = 0;
            #pragma unroll 8
            for (int q = 0; q < 256; q++) {
                int h = hist[q];
                if (r - h <= 0) { bin = q; break; }
                r -= h;
            }
            rem = r;
            pref = pr | (bin << shift);
        }
        __syncthreads();
    }
    float cv = __uint_as_float(pref);
    if (t == 0) cut[b] = cv;
    ca[b * N_ + t]        = fmaxf(a0 + 1e-7f - cv, 0.f);
    ca[b * N_ + t + 1024] = fmaxf(a1 + 1e-7f - cv, 0.f);
}

// -------- compaction + fused maskc/mrest + packed {ginv, d1*ca} --------------
__global__ void compact_kernel(const float* __restrict__ ca, const float* __restrict__ mask,
                               const float* __restrict__ d1,
                               int* __restrict__ idx, int* __restrict__ ginv,
                               int* __restrict__ cnt, float* __restrict__ maskc,
                               float* __restrict__ mrest, int2* __restrict__ pk) {
    __shared__ int sc[1024];
    __shared__ float redm[1024];
    int b = blockIdx.x, t = threadIdx.x;   // 1024 threads
    float c0 = ca[b * N_ + 2 * t], c1 = ca[b * N_ + 2 * t + 1];
    int f0 = (c0 > 0.f) ? 1 : 0;
    int f1 = (c1 > 0.f) ? 1 : 0;
    int g0 = -1, g1 = -1;
    int c = f0 + f1;
    sc[t] = c; __syncthreads();
    for (int o = 1; o < 1024; o <<= 1) {
        int v = (t >= o) ? sc[t - o] : 0; __syncthreads();
        sc[t] += v; __syncthreads();
    }
    int base = sc[t] - c;
    if (f0) { idx[b * N_ + base] = 2 * t;     g0 = base; base++; }
    if (f1) { idx[b * N_ + base] = 2 * t + 1; g1 = base; }
    ginv[b * N_ + 2 * t]     = g0;
    ginv[b * N_ + 2 * t + 1] = g1;
    pk[b * N_ + 2 * t]     = make_int2(g0, __float_as_int(d1[b * N_ + 2 * t]     * c0));
    pk[b * N_ + 2 * t + 1] = make_int2(g1, __float_as_int(d1[b * N_ + 2 * t + 1] * c1));
    if (t == 1023) cnt[b] = sc[1023];
    __syncthreads();
    int cn = sc[1023];
    float local = mask[b * N_ + 2 * t] + mask[b * N_ + 2 * t + 1];
    #pragma unroll
    for (int r = 0; r < 2; r++) {
        int i = t + r * 1024;
        float mv = 0.f;
        if (i < cn) mv = mask[b * N_ + idx[b * N_ + i]];
        maskc[b * N_ + i] = mv;
    }
    redm[t] = local; __syncthreads();
    for (int o = 512; o > 0; o >>= 1) { if (t < o) redm[t] += redm[t + o]; __syncthreads(); }
    if (t == 0) mrest[b] = redm[0];
}

// ---------------- layer-1 S row normalizer (uses packed dca) -----------------
__global__ void srec_kernel(const int* __restrict__ lst, const int* __restrict__ deg,
                            const float* __restrict__ d1, const float* __restrict__ rnz,
                            const int2* __restrict__ pk, const float* __restrict__ ca,
                            float* __restrict__ srec) {
    int b = blockIdx.y;
    int i = blockIdx.x * 8 + (threadIdx.x >> 5);
    int lane = threadIdx.x & 31;
    const int* l = lst + ((size_t)(b * N_ + i)) * CAP;
    int dg = deg[b * N_ + i];
    float s = 0.f;
    for (int p = lane; p < dg; p += 32) {
        int j = l[p];
        s += __int_as_float(pk[b * N_ + j].y);
    }
    #pragma unroll
    for (int o = 16; o > 0; o >>= 1) s += __shfl_down_sync(0xffffffffu, s, o);
    if (lane == 0) {
        float di = d1[b * N_ + i];
        float raw = rnz[b * N_ + i] * di * (s + di * ca[b * N_ + i]);
        srec[b * N_ + i] = rnz[b * N_ + i] * di / fmaxf(raw, 1e-12f);
    }
}

// -- xc[ic,:] = sum_n S[n, idx[ic]] * x1[n,:]; fused v2 = xc @ Watt + batt ----
__global__ void xupd_kernel(const int* __restrict__ lst, const int* __restrict__ deg,
                            const int* __restrict__ hasd, const float* __restrict__ d1,
                            const float* __restrict__ ca, const float* __restrict__ srec,
                            const int* __restrict__ idx, const int* __restrict__ cnt,
                            const float* __restrict__ x1, const float* __restrict__ Watt,
                            const float* __restrict__ batt,
                            float* __restrict__ xc, float* __restrict__ v) {
    __shared__ int   jl[CAP + 1];
    __shared__ float sv[CAP + 1];
    __shared__ float red[128];
    int b = blockIdx.y, ic = blockIdx.x, c = threadIdx.x;   // 128 threads
    int cn = cnt[b], cnp = (cn + 127) & ~127;
    if (ic >= cnp) return;
    float* orow = xc + ((size_t)(b * N_ + ic)) * H_;
    if (ic >= cn) {
        orow[c] = 0.f;
        if (c == 0) v[b * N_ + ic] = batt[0];
        return;
    }
    int m = idx[b * N_ + ic];
    float dmcam = d1[b * N_ + m] * ca[b * N_ + m];
    int dg = deg[b * N_ + m];
    const int* l = lst + ((size_t)(b * N_ + m)) * CAP;
    for (int p = c; p < dg; p += 128) {
        int n = l[p];
        jl[p] = n;
        sv[p] = srec[b * N_ + n] * dmcam * ((n == m) ? 2.f : 1.f);
    }
    int dgE = dg + (hasd[b * N_ + m] ? 0 : 1);
    if (c == 0 && dgE > dg) { jl[dg] = m; sv[dg] = srec[b * N_ + m] * dmcam; }
    __syncthreads();
    float acc = 0.f;
    #pragma unroll 4
    for (int p = 0; p < dgE; p++)
        acc = fmaf(sv[p], x1[((size_t)(b * N_ + jl[p])) * H_ + c], acc);
    orow[c] = acc;
    red[c] = acc * Watt[c];
    __syncthreads();
    for (int o = 64; o > 0; o >>= 1) { if (c < o) red[c] += red[c + o]; __syncthreads(); }
    if (c == 0) v[b * N_ + ic] = red[0] + batt[0];
}

// ---- Tc[i,:] = sum_{j in list_i} S_row_j; packed {jc, dca} gathers ----------
__global__ void adjS_sparse_kernel(const int* __restrict__ lst, const int* __restrict__ deg,
                                   const int* __restrict__ hasd, const float* __restrict__ srec,
                                   const int2* __restrict__ pk, const int* __restrict__ cnt,
                                   float* __restrict__ Tc) {
    __shared__ float acc[4][N_];
    int b = blockIdx.y, tid = threadIdx.x;   // 128 threads = 4 warps
    int w = tid >> 5, lane = tid & 31;
    int i = blockIdx.x * 4 + w;
    int cnp = (cnt[b] + 127) & ~127;
    float* a = acc[w];
    float4* a4 = (float4*)a;
    float4 z4 = make_float4(0.f, 0.f, 0.f, 0.f);
    for (int jc = lane; jc < (cnp >> 2); jc += 32) a4[jc] = z4;
    __syncwarp();
    int dgi = deg[b * N_ + i];
    const int* li = lst + ((size_t)(b * N_ + i)) * CAP;
    const int2* pkb = pk + b * N_;
    for (int p = 0; p < dgi; p++) {
        int j = li[p];
        int dgj = deg[b * N_ + j];
        const int* lj = lst + ((size_t)(b * N_ + j)) * CAP;
        float sr = srec[b * N_ + j];
        for (int q = lane; q < dgj; q += 32) {
            int m = lj[q];
            int2 pm = pkb[m];
            if (pm.x >= 0) {
                float coef = (m == j) ? 2.f : 1.f;
                a[pm.x] += sr * __int_as_float(pm.y) * coef;
            }
        }
        __syncwarp();
        if (lane == 0 && !hasd[b * N_ + j]) {
            int2 pj = pkb[j];
            if (pj.x >= 0) a[pj.x] += sr * __int_as_float(pj.y);
        }
        __syncwarp();
    }
    float4* trow4 = (float4*)(Tc + (size_t)b * N_ * N_ + (size_t)i * cnp);
    for (int jc = lane; jc < (cnp >> 2); jc += 32) trow4[jc] = a4[jc];
}

// -- Ac row = floorq(sum S*Tc); REGISTER accumulators + staged coef lists -----
__global__ void STT_kernel(const int* __restrict__ lst, const int* __restrict__ deg,
                           const int* __restrict__ hasd, const float* __restrict__ d1,
                           const float* __restrict__ ca, const float* __restrict__ srec,
                           const int* __restrict__ idx, const int* __restrict__ cnt,
                           const float* __restrict__ Tc, float* __restrict__ Ac,
                           __nv_bfloat16* __restrict__ Achi, __nv_bfloat16* __restrict__ Aclo,
                           float* __restrict__ d2out, float* __restrict__ rz2out) {
    __shared__ int   nls[CAP + 1];
    __shared__ float svs[CAP + 1];
    __shared__ float red[256];
    int b = blockIdx.y, ic = blockIdx.x, tid = threadIdx.x;
    int cn = cnt[b], cnp = (cn + 127) & ~127, cnp4 = cnp >> 2;
    if (ic >= cnp) return;
    size_t rowoff = ((size_t)(b * N_ + ic)) * N_;
    float4* orow4 = (float4*)(Ac + rowoff);
    __nv_bfloat162* ohi = (__nv_bfloat162*)(Achi + rowoff);
    __nv_bfloat162* olo = (__nv_bfloat162*)(Aclo + rowoff);
    float4 z4 = make_float4(0.f, 0.f, 0.f, 0.f);
    if (ic >= cn) {
        __nv_bfloat162 zb; zb.x = __float2bfloat16(0.f); zb.y = zb.x;
        for (int jc = tid; jc < cnp4; jc += 256) {
            orow4[jc] = z4;
            ohi[jc * 2] = zb; ohi[jc * 2 + 1] = zb;
            olo[jc * 2] = zb; olo[jc * 2 + 1] = zb;
        }
        if (tid == 0) { d2out[b * N_ + ic] = 1.f; rz2out[b * N_ + ic] = 0.f; }
        return;
    }
    int m = idx[b * N_ + ic];
    float dmcam = d1[b * N_ + m] * ca[b * N_ + m];
    int dg = deg[b * N_ + m];
    const int* l = lst + ((size_t)(b * N_ + m)) * CAP;
    for (int p = tid; p < dg; p += 256) {
        int n = l[p];
        nls[p] = n;
        svs[p] = srec[b * N_ + n] * dmcam * ((n == m) ? 2.f : 1.f);
    }
    int dgE = dg + (hasd[b * N_ + m] ? 0 : 1);
    if (tid == 0 && dgE > dg) { nls[dg] = m; svs[dg] = srec[b * N_ + m] * dmcam; }
    __syncthreads();
    const float* Tb = Tc + (size_t)b * N_ * N_;
    int j0 = tid, j1 = tid + 256;
    bool h1 = (j1 < cnp4);
    float4 a0 = z4, a1 = z4;
    #pragma unroll 2
    for (int p = 0; p < dgE; p++) {
        float sv = svs[p];
        const float4* trow = (const float4*)(Tb + (size_t)nls[p] * cnp);
        float4 t0 = trow[j0];
        a0.x = fmaf(sv, t0.x, a0.x); a0.y = fmaf(sv, t0.y, a0.y);
        a0.z = fmaf(sv, t0.z, a0.z); a0.w = fmaf(sv, t0.w, a0.w);
        if (h1) {
            float4 t1 = trow[j1];
            a1.x = fmaf(sv, t1.x, a1.x); a1.y = fmaf(sv, t1.y, a1.y);
            a1.z = fmaf(sv, t1.z, a1.z); a1.w = fmaf(sv, t1.w, a1.w);
        }
    }
    float part = 0.f;
    #pragma unroll
    for (int r = 0; r < 2; r++) {
        int jc = (r == 0) ? j0 : j1;
        if (r == 1 && !h1) break;
        float4 a = (r == 0) ? a0 : a1;
        a.x = floorf(a.x * 10000.f) / 10000.f;
        a.y = floorf(a.y * 10000.f) / 10000.f;
        a.z = floorf(a.z * 10000.f) / 10000.f;
        a.w = floorf(a.w * 10000.f) / 10000.f;
        orow4[jc] = a;
        part += (a.x + a.y) + (a.z + a.w);
        __nv_bfloat162 h01 = split_hi2(a.x, a.y), h23 = split_hi2(a.z, a.w);
        ohi[jc * 2] = h01; ohi[jc * 2 + 1] = h23;
        olo[jc * 2] = split_lo2(a.x, a.y, h01); olo[jc * 2 + 1] = split_lo2(a.z, a.w, h23);
    }
    red[tid] = part; __syncthreads();
    for (int o = 128; o > 0; o >>= 1) { if (tid < o) red[tid] += red[tid + o]; __syncthreads(); }
    if (tid == 0) {
        float sum = red[0];
        d2out[b * N_ + ic] = rsqrtf(fmaxf(sum + 1.f, 1.f));
        rz2out[b * N_ + ic] = (sum > 0.f) ? 1.f : 0.f;
    }
}

// ---------------- layer-2 / final helpers ------------------------------------
__global__ void rowstats_c_kernel(const float* __restrict__ A, const int* __restrict__ cnt,
                                  float* __restrict__ dout, float* __restrict__ rnz, int mode) {
    int b = blockIdx.y, i = blockIdx.x, tid = threadIdx.x;
    int cnp = (cnt[b] + 127) & ~127;
    if (i >= cnp) return;
    const float* row = A + ((size_t)(b * N_ + i)) * N_;
    const float4* row4 = (const float4*)row;
    float s = 0.f;
    for (int j = tid; j < (cnp >> 2); j += 256) {
        float4 a = row4[j]; s += (a.x + a.y) + (a.z + a.w);
    }
    __shared__ float red[256];
    red[tid] = s; __syncthreads();
    for (int o = 128; o > 0; o >>= 1) { if (tid < o) red[tid] += red[tid + o]; __syncthreads(); }
    if (tid == 0) {
        float sum = red[0];
        if (mode == 0) {
            dout[b * N_ + i] = rsqrtf(fmaxf(sum - row[i] + 1.f, 1.f));
        } else {
            dout[b * N_ + i] = rsqrtf(fmaxf(sum + 1.f, 1.f));
            rnz[b * N_ + i] = (sum > 0.f) ? 1.f : 0.f;
        }
    }
}

__global__ void alpha2d_kernel(const float* __restrict__ Ac, const float* __restrict__ d2,
                               const float* __restrict__ rz2, const float* __restrict__ v,
                               const int* __restrict__ cnt, float* __restrict__ alp) {
    __shared__ float dv[N_];
    __shared__ float red[256];
    int b = blockIdx.y, n = blockIdx.x, tid = threadIdx.x;
    int cnp = (cnt[b] + 127) & ~127;
    if (n >= cnp) { if (tid == 0) alp[b * N_ + n] = 0.5f; return; }
    for (int m = tid; m < cnp; m += 256) dv[m] = d2[b * N_ + m] * v[b * N_ + m];
    __syncthreads();
    const float4* row4 = (const float4*)(Ac + ((size_t)(b * N_ + n)) * N_);
    const float4* dv4 = (const float4*)dv;
    float s = 0.f;
    for (int m = tid; m < (cnp >> 2); m += 256) {
        float4 a = row4[m], w = dv4[m];
        s += a.x * w.x + a.y * w.y + a.z * w.z + a.w * w.w;
    }
    red[tid] = s; __syncthreads();
    for (int o = 128; o > 0; o >>= 1) { if (tid < o) red[tid] += red[tid + o]; __syncthreads(); }
    if (tid == 0) {
        float r = rz2[b * N_ + n] * d2[b * N_ + n] * (red[0] + dv[n]);
        alp[b * N_ + n] = 1.f / (1.f + expf(-r * r));
    }
}

__global__ void s2inv_kernel(const float* __restrict__ Ac, const float* __restrict__ d2,
                             const float* __restrict__ rz2, const float* __restrict__ ca,
                             const int* __restrict__ cnt, float* __restrict__ sinv) {
    __shared__ float dca[N_];
    __shared__ float red[256];
    int b = blockIdx.y, n = blockIdx.x, tid = threadIdx.x;
    int cnp = (cnt[b] + 127) & ~127;
    if (n >= cnp) return;
    for (int m = tid; m < cnp; m += 256) dca[m] = d2[b * N_ + m] * ca[b * N_ + m];
    __syncthreads();
    const float4* row4 = (const float4*)(Ac + ((size_t)(b * N_ + n)) * N_);
    const float4* dca4 = (const float4*)dca;
    float s = 0.f;
    for (int m = tid; m < (cnp >> 2); m += 256) {
        float4 a = row4[m], w = dca4[m];
        s += a.x * w.x + a.y * w.y + a.z * w.z + a.w * w.w;
    }
    red[tid] = s; __syncthreads();
    for (int o = 128; o > 0; o >>= 1) { if (tid < o) red[tid] += red[tid + o]; __syncthreads(); }
    if (tid == 0) {
        float sum = red[0] + dca[n];
        float f = rz2[b * N_ + n] * d2[b * N_ + n];
        sinv[b * N_ + n] = f / fmaxf(f * sum, 1e-12f);
    }
}

__global__ void buildST_kernel(const float* __restrict__ Ac, const float* __restrict__ d2,
                               const float* __restrict__ ca, const float* __restrict__ sinv,
                               const int* __restrict__ cnt,
                               __nv_bfloat16* __restrict__ SThi, __nv_bfloat16* __restrict__ STlo) {
    __shared__ float siv[N_];
    int b = blockIdx.y, m = blockIdx.x, tid = threadIdx.x;
    int cnp = (cnt[b] + 127) & ~127;
    if (m >= cnp) return;
    for (int n = tid; n < cnp; n += 256) siv[n] = sinv[b * N_ + n];
    __syncthreads();
    float dcam = d2[b * N_ + m] * ca[b * N_ + m];
    size_t ro = ((size_t)(b * N_ + m)) * N_;
    const float4* row4 = (const float4*)(Ac + ro);
    __nv_bfloat162* ohi = (__nv_bfloat162*)(SThi + ro);
    __nv_bfloat162* olo = (__nv_bfloat162*)(STlo + ro);
    for (int q = tid; q < (cnp >> 2); q += 256) {
        float4 a = row4[q];
        int n = q << 2;
        float v0 = (a.x + ((n    ) == m ? 1.f : 0.f)) * dcam * siv[n];
        float v1 = (a.y + ((n + 1) == m ? 1.f : 0.f)) * dcam * siv[n + 1];
        float v2 = (a.z + ((n + 2) == m ? 1.f : 0.f)) * dcam * siv[n + 2];
        float v3 = (a.w + ((n + 3) == m ? 1.f : 0.f)) * dcam * siv[n + 3];
        __nv_bfloat162 h01 = split_hi2(v0, v1), h23 = split_hi2(v2, v3);
        ohi[q * 2] = h01; ohi[q * 2 + 1] = h23;
        olo[q * 2] = split_lo2(v0, v1, h01); olo[q * 2 + 1] = split_lo2(v2, v3, h23);
    }
}

__global__ void wvec_kernel(const float* __restrict__ A3, const float* __restrict__ d2,
                            const float* __restrict__ maskc, const int* __restrict__ cnt,
                            float* __restrict__ wv) {
    __shared__ float dv[N_];
    __shared__ float red[256];
    int b = blockIdx.y, k = blockIdx.x, tid = threadIdx.x;
    int cnp = (cnt[b] + 127) & ~127;
    if (k >= cnp) return;
    for (int m = tid; m < cnp; m += 256) dv[m] = d2[b * N_ + m] * maskc[b * N_ + m];
    __syncthreads();
    const float* row = A3 + ((size_t)(b * N_ + k)) * N_;
    const float4* row4 = (const float4*)row;
    const float4* dv4 = (const float4*)dv;
    float s = 0.f;
    for (int m = tid; m < (cnp >> 2); m += 256) {
        float4 a = row4[m], w = dv4[m];
        s += a.x * w.x + a.y * w.y + a.z * w.z + a.w * w.w;
    }
    red[tid] = s; __syncthreads();
    for (int o = 128; o > 0; o >>= 1) { if (tid < o) red[tid] += red[tid + o]; __syncthreads(); }
    if (tid == 0)
        wv[b * N_ + k] = d2[b * N_ + k] * (red[0] - row[k] * dv[k] + dv[k]);
}

// yv partial: yp[b][q][c] = sum_{k in chunk q} wv[k] * x3[k][c]   (c < H_)
__global__ void out2v_kernel(const float* __restrict__ x3, const float* __restrict__ wv,
                             const int* __restrict__ cnt, float* __restrict__ yp) {
    int b = blockIdx.y, q = blockIdx.x, c = threadIdx.x;   // 128 threads
    int cnp = (cnt[b] + 127) & ~127;
    int lo = q * 512, hi = (q + 1) * 512; if (hi > cnp) hi = cnp;
    float s = 0.f;
    for (int k = lo; k < hi; k++)
        s = fmaf(wv[b * N_ + k], x3[((size_t)(b * N_ + k)) * H_ + c], s);
    yp[(b * 4 + q) * F_ + c] = s;
}

__global__ void split_tr_kernel(const float* __restrict__ in, __nv_bfloat16* __restrict__ hi,
                                __nv_bfloat16* __restrict__ lo, const int* __restrict__ cnt,
                                int Rfixed, int Cfixed, int ld, long sIn, long sOut) {
    __shared__ float tile[32][33];
    int b = blockIdx.z;
    int cnp = (cnt[b] + 127) & ~127;
    int R = Rfixed ? Rfixed : cnp;
    int C = Cfixed ? Cfixed : cnp;
    int i0 = blockIdx.y * 32, j0 = blockIdx.x * 32;
    if (i0 >= R || j0 >= C) return;
    const float* inb = in + (size_t)b * sIn;
    size_t boff = (size_t)b * sOut;
    int tx = threadIdx.x, ty = threadIdx.y;   // (32, 8)
    #pragma unroll
    for (int r = 0; r < 4; r++) {
        int i = ty + r * 8;
        tile[i][tx] = inb[(size_t)(i0 + i) * ld + j0 + tx];
    }
    __syncthreads();
    #pragma unroll
    for (int r = 0; r < 4; r++) {
        int j = ty + r * 8;
        float v = tile[tx][j];
        __nv_bfloat16 h = __float2bfloat16(v);
        size_t o = boff + (size_t)(j0 + j) * N_ + i0 + tx;
        hi[o] = h;
        lo[o] = __float2bfloat16(v - __bfloat162float(h));
    }
}

// ---------------- bf16-split tensor GEMM, single-K-pass ----------------------
#define TSZ (128 * 40)
template<int EPI>
__global__ void __launch_bounds__(256, 2) gemm_bf16_kernel(
    const __nv_bfloat16* __restrict__ Ahi, const __nv_bfloat16* __restrict__ Alo,
    const __nv_bfloat16* __restrict__ BThi, const __nv_bfloat16* __restrict__ BTlo,
    float* __restrict__ C, const int* __restrict__ cnt,
    int ldc, long sC,
    __nv_bfloat16* __restrict__ Chi, __nv_bfloat16* __restrict__ Clo,
    const __nv_bfloat16* __restrict__ B2hi, const __nv_bfloat16* __restrict__ B2lo,
    float* __restrict__ C2, int ldc2, long sC2) {
    extern __shared__ __nv_bfloat16 sm[];
    const int b = blockIdx.z;
    const int cnp = (cnt[b] + 127) & ~127;
    const int m0 = blockIdx.y * 128;
    const int n0 = blockIdx.x * 128;
    const bool reg2 = (EPI == 4) && (blockIdx.x == gridDim.x - 1);
    if (m0 >= cnp) return;
    if (!reg2) {
        if (n0 >= cnp) return;
        if (EPI == 5 && m0 > n0) return;
    }
    const size_t boff = (size_t)b * N_ * N_;
    const int tid = threadIdx.x;
    const int wid = tid >> 5, lane = tid & 31;
    const int wm = wid >> 1, wn = wid & 1;
    const int g = lane >> 2, t4 = lane & 3;
    const int a_row = lane & 15;
    const int a_k   = (lane & 16) ? 8 : 0;
    const int b_row = (lane & 7) + ((lane & 16) ? 8 : 0);
    const int b_k   = (lane & 8) ? 8 : 0;
    const int KT = cnp >> 5;

    float acc[2][8][4];
    #pragma unroll
    for (int fm = 0; fm < 2; fm++)
        #pragma unroll
        for (int fn = 0; fn < 8; fn++)
            #pragma unroll
            for (int r = 0; r < 4; r++) acc[fm][fn][r] = 0.f;

    const __nv_bfloat16* gsrc[4];
    auto stage = [&](int kt, int buf) {
        gsrc[0] = Ahi + boff + (size_t)m0 * N_ + kt * 32;
        gsrc[1] = Alo + boff + (size_t)m0 * N_ + kt * 32;
        if (reg2) {
            gsrc[2] = B2hi + (size_t)b * H_ * N_ + kt * 32;
            gsrc[3] = B2lo + (size_t)b * H_ * N_ + kt * 32;
        } else {
            gsrc[2] = BThi + boff + (size_t)n0 * N_ + kt * 32;
            gsrc[3] = BTlo + boff + (size_t)n0 * N_ + kt * 32;
        }
        int row = tid >> 2, cc = (tid & 3) * 8;
        #pragma unroll
        for (int w = 0; w < 4; w++) {
            __nv_bfloat16* dst = sm + (size_t)(buf * 4 + w) * TSZ;
            CP16(dst + row * 40 + cc,        gsrc[w] + (size_t)row * N_ + cc);
            CP16(dst + (row + 64) * 40 + cc, gsrc[w] + (size_t)(row + 64) * N_ + cc);
        }
    };

    stage(0, 0);
    CP_COMMIT();

    for (int t = 0; t < KT; t++) {
        CP_WAIT0();
        __syncthreads();
        if (t + 1 < KT) { stage(t + 1, (t + 1) & 1); CP_COMMIT(); }
        const __nv_bfloat16* Ah = sm + (size_t)((t & 1) * 4 + 0) * TSZ;
        const __nv_bfloat16* Al = sm + (size_t)((t & 1) * 4 + 1) * TSZ;
        const __nv_bfloat16* Bh = sm + (size_t)((t & 1) * 4 + 2) * TSZ;
        const __nv_bfloat16* Bl = sm + (size_t)((t & 1) * 4 + 3) * TSZ;
        #pragma unroll
        for (int kh = 0; kh < 32; kh += 16) {
            uint32_t ah[2][4], al[2][4];
            #pragma unroll
            for (int fm = 0; fm < 2; fm++) {
                int ao = (wm * 32 + fm * 16 + a_row) * 40 + kh + a_k;
                ldsm4(ah[fm], Ah + ao);
                ldsm4(al[fm], Al + ao);
            }
            #pragma unroll
            for (int fn2 = 0; fn2 < 4; fn2++) {
                int bo = (wn * 64 + fn2 * 16 + b_row) * 40 + kh + b_k;
                uint32_t bh[4], bl[4];
                ldsm4(bh, Bh + bo);
                ldsm4(bl, Bl + bo);
                #pragma unroll
                for (int fm = 0; fm < 2; fm++) {
                    mma_bf16(acc[fm][2 * fn2],     ah[fm], bh[0], bh[1]);
                    mma_bf16(acc[fm][2 * fn2],     ah[fm], bl[0], bl[1]);
                    mma_bf16(acc[fm][2 * fn2],     al[fm], bh[0], bh[1]);
                    mma_bf16(acc[fm][2 * fn2 + 1], ah[fm], bh[2], bh[3]);
                    mma_bf16(acc[fm][2 * fn2 + 1], ah[fm], bl[2], bl[3]);
                    mma_bf16(acc[fm][2 * fn2 + 1], al[fm], bh[2], bh[3]);
                }
            }
        }
        __syncthreads();
    }

    float* smf = (float*)sm;
    #pragma unroll
    for (int fm = 0; fm < 2; fm++) {
        int mr = m0 + wm * 32 + fm * 16 + g;
        #pragma unroll
        for (int fn = 0; fn < 8; fn++) {
            int lc = wn * 64 + fn * 8 + t4 * 2;
            float v0 = acc[fm][fn][0], v1 = acc[fm][fn][1];
            float v2 = acc[fm][fn][2], v3 = acc[fm][fn][3];
            if (reg2) {
                float* p0 = C2 + (size_t)b * sC2 + (size_t)mr * ldc2 + lc;
                p0[0] = v0; p0[1] = v1;
                float* p1 = p0 + 8 * (size_t)ldc2;
                p1[0] = v2; p1[1] = v3;
            } else if (EPI == 5) {
                v0 = floorf(v0 * 10000.f) / 10000.f;
                v1 = floorf(v1 * 10000.f) / 10000.f;
                v2 = floorf(v2 * 10000.f) / 10000.f;
                v3 = floorf(v3 * 10000.f) / 10000.f;
                int r = wm * 32 + fm * 16 + g;
                smf[(lc    ) * 133 + r]     = v0;
                smf[(lc + 1) * 133 + r]     = v1;
                smf[(lc    ) * 133 + r + 8] = v2;
                smf[(lc + 1) * 133 + r + 8] = v3;
                int n = n0 + lc;
                float* p0 = C + (size_t)b * sC + (size_t)mr * ldc + n;
                p0[0] = v0; p0[1] = v1;
                float* p1 = p0 + 8 * (size_t)ldc;
                p1[0] = v2; p1[1] = v3;
            } else {
                int n = n0 + lc;
                size_t o0 = (size_t)b * sC + (size_t)mr * ldc + n;
                size_t o1 = o0 + 8 * (size_t)ldc;
                __nv_bfloat162 h0 = split_hi2(v0, v1), h1 = split_hi2(v2, v3);
                *(__nv_bfloat162*)(Chi + o0) = h0;
                *(__nv_bfloat162*)(Chi + o1) = h1;
                *(__nv_bfloat162*)(Clo + o0) = split_lo2(v0, v1, h0);
                *(__nv_bfloat162*)(Clo + o1) = split_lo2(v2, v3, h1);
            }
        }
    }
    if (EPI == 5 && m0 != n0) {
        __syncthreads();
        float* Cb = C + (size_t)b * sC;
        for (int e = tid; e < 128 * 128; e += 256) {
            int r2 = e >> 7, c2 = e & 127;
            Cb[(size_t)(n0 + r2) * ldc + m0 + c2] = smf[r2 * 133 + c2];
        }
    }
}

// ---------------- double-buffered cp.async SIMT GEMM (x@W1 only) -------------
template<int TRANSA, int EPI>
__global__ void __launch_bounds__(256, 2) gemm2_kernel(
    const float* __restrict__ A, const float* __restrict__ Bm, float* __restrict__ C,
    int M, int Kd, int Nc, int lda, int ldb, int ldc,
    long sA, long sB, long sC,
    const float* __restrict__ bias, const float* __restrict__ mask,
    const int* __restrict__ cnt, int dynM, int dynK, int dynN) {
    __shared__ float As[2][128 * 16];
    __shared__ float Bs[2][16 * 128];
    const int b = blockIdx.z;
    int Mp = M, Kp = Kd, Np = Nc;
    if (cnt) {
        int p = (cnt[b] + 127) & ~127;
        if (dynM) Mp = p; if (dynK) Kp = p; if (dynN) Np = p;
    }
    const int n0 = blockIdx.x * 128, m0 = blockIdx.y * 128;
    if (m0 >= Mp || n0 >= Np) return;
    A  += (size_t)b * sA;
    Bm += (size_t)b * sB;
    C  += (size_t)b * sC;
    const int tid = threadIdx.x, tx = tid & 15, ty = tid >> 4;
    float acc[8][8];
    #pragma unroll
    for (int i = 0; i < 8; i++)
        #pragma unroll
        for (int j = 0; j < 8; j++) acc[i][j] = 0.f;

    const int Kt = Kp >> 4;

    auto load_tiles = [&](int k0, int buf) {
        if (!TRANSA) {
            #pragma unroll
            for (int q = 0; q < 2; q++) {
                int c = tid + q * 256;
                int row = c >> 2, col4 = (c & 3) * 4;
                const float* src = A + (size_t)(m0 + row) * lda + k0 + col4;
                CP16(&As[buf][row * 16 + col4], src);
            }
        } else {
            #pragma unroll
            for (int q = 0; q < 2; q++) {
                int c = tid + q * 256;
                int row = c >> 5, col4 = (c & 31) * 4;
                const float* src = A + (size_t)(k0 + row) * lda + m0 + col4;
                CP16(&As[buf][row * 128 + col4], src);
            }
        }
        #pragma unroll
        for (int q = 0; q < 2; q++) {
            int c = tid + q * 256;
            int row = c >> 5, col4 = (c & 31) * 4;
            const float* src = Bm + (size_t)(k0 + row) * ldb + n0 + col4;
            CP16(&Bs[buf][row * 128 + col4], src);
        }
    };

    load_tiles(0, 0);
    CP_COMMIT();

    for (int t = 0; t < Kt; t++) {
        CP_WAIT0();
        __syncthreads();
        if (t + 1 < Kt) { load_tiles((t + 1) << 4, (t + 1) & 1); CP_COMMIT(); }
        const int buf = t & 1;
        #pragma unroll
        for (int k = 0; k < 16; k++) {
            float a[8], bv[8];
            if (!TRANSA) {
                #pragma unroll
                for (int i = 0; i < 8; i++) a[i] = As[buf][(ty * 8 + i) * 16 + k];
            } else {
                *(float4*)(a)     = *(const float4*)&As[buf][k * 128 + ty * 8];
                *(float4*)(a + 4) = *(const float4*)&As[buf][k * 128 + ty * 8 + 4];
            }
            *(float4*)(bv)     = *(const float4*)&Bs[buf][k * 128 + tx * 8];
            *(float4*)(bv + 4) = *(const float4*)&Bs[buf][k * 128 + tx * 8 + 4];
            #pragma unroll
            for (int i = 0; i < 8; i++)
                #pragma unroll
                for (int j = 0; j < 8; j++) acc[i][j] = fmaf(a[i], bv[j], acc[i][j]);
        }
        __syncthreads();
    }
    #pragma unroll
    for (int i = 0; i < 8; i++) {
        int m = m0 + ty * 8 + i;
        float mk = (EPI == 2) ? mask[(size_t)b * N_ + m] : 1.f;
        #pragma unroll
        for (int j = 0; j < 8; j++) {
            int n = n0 + tx * 8 + j;
            float v = acc[i][j];
            if (EPI == 2)      { v = (v + bias[n]) * mk; }
            else if (EPI == 3) { v = floorf(v * 10000.f) / 10000.f; }
            C[(size_t)m * ldc + n] = v;
        }
    }
}

// ---------------- output means ------------------------------------------------
__global__ void mean1_part_kernel(const float* __restrict__ x1, float* __restrict__ p1) {
    int b = blockIdx.y, q = blockIdx.x, c = threadIdx.x;   // 128 threads
    float s = 0.f;
    for (int n = q * 512; n < (q + 1) * 512; n++) s += x1[((size_t)(b * N_ + n)) * H_ + c];
    p1[(b * 4 + q) * H_ + c] = s;
}

__global__ void mean_combine_kernel(const float* __restrict__ p1, const float* __restrict__ yp,
                                    const float* __restrict__ W2, const float* __restrict__ b2,
                                    const float* __restrict__ smask, float* __restrict__ out) {
    __shared__ float ysh[H_];
    int b = blockIdx.x, c = threadIdx.x;   // 384 threads
    if (c < H_) {
        float y = 0.f;
        for (int q = 0; q < 4; q++) y += yp[(b * 4 + q) * F_ + c];
        ysh[c] = y;
    }
    __syncthreads();
    if (c < H_) {
        float s = 0.f;
        for (int q = 0; q < 4; q++) s += p1[(b * 4 + q) * H_ + c];
        out[b * OUTC + c] = s / (float)N_;
    } else {
        int f = c - H_;
        float s = b2[f] * smask[b];
        #pragma unroll 4
        for (int cc = 0; cc < H_; cc++)
            s = fmaf(ysh[cc], W2[cc * F_ + f], s);
        out[b * OUTC + c] = s / (float)N_;
    }
}

extern "C" void kernel_launch(void* const* d_in, const int* in_sizes, int n_in,
                              void* d_out, int out_size) {
    const float* x    = (const float*)d_in[0];
    const float* adj  = (const float*)d_in[1];
    const float* mask = (const float*)d_in[2];
    const float* W1   = (const float*)d_in[3];
    const float* b1   = (const float*)d_in[4];
    const float* Watt = (const float*)d_in[5];
    const float* batt = (const float*)d_in[6];
    const float* W2   = (const float*)d_in[7];
    const float* b2   = (const float*)d_in[8];
    float* out = (float*)d_out;

    float *pT,*pAc,*pA3,*pxW,*px1,*pxc,*px3;
    float *pv,*palp,*pca,*psrec,*pd0,*pd1,*prnz,*pd2,*prz2,*pcut,*pmaskc,*pmrest,*pp1,*pp2;
    __nv_bfloat16 *pAhi,*pAlo,*pSThi,*pSTlo,*pTThi,*pTTlo,*pxTh,*pxTl;
    int *plst,*pdeg,*phasd,*pidx,*pginv,*pcnt;
    int2 *ppk;
    cudaGetSymbolAddress((void**)&pT,   g_T);
    cudaGetSymbolAddress((void**)&pAc,  g_Ac);
    cudaGetSymbolAddress((void**)&pA3,  g_A3);
    cudaGetSymbolAddress((void**)&pAhi, g_Ahi);
    cudaGetSymbolAddress((void**)&pAlo, g_Alo);
    cudaGetSymbolAddress((void**)&pSThi,g_SThi);
    cudaGetSymbolAddress((void**)&pSTlo,g_STlo);
    cudaGetSymbolAddress((void**)&pTThi,g_TThi);
    cudaGetSymbolAddress((void**)&pTTlo,g_TTlo);
    cudaGetSymbolAddress((void**)&pxTh, g_xTh);
    cudaGetSymbolAddress((void**)&pxTl, g_xTl);
    cudaGetSymbolAddress((void**)&pxW,  g_xW);
    cudaGetSymbolAddress((void**)&px1,  g_x1);
    cudaGetSymbolAddress((void**)&pxc,  g_xc);
    cudaGetSymbolAddress((void**)&px3,  g_x3);
    cudaGetSymbolAddress((void**)&pv,   g_v);
    cudaGetSymbolAddress((void**)&palp, g_alp);
    cudaGetSymbolAddress((void**)&pca,  g_ca);
    cudaGetSymbolAddress((void**)&psrec,g_srec);
    cudaGetSymbolAddress((void**)&pd0,  g_d0);
    cudaGetSymbolAddress((void**)&pd1,  g_d1);
    cudaGetSymbolAddress((void**)&prnz, g_rnz);
    cudaGetSymbolAddress((void**)&pd2,  g_d2);
    cudaGetSymbolAddress((void**)&prz2, g_rz2);
    cudaGetSymbolAddress((void**)&pcut, g_cut);
    cudaGetSymbolAddress((void**)&pmaskc, g_maskc);
    cudaGetSymbolAddress((void**)&pmrest, g_mrest);
    cudaGetSymbolAddress((void**)&pp1,  g_p1);
    cudaGetSymbolAddress((void**)&pp2,  g_p2);
    cudaGetSymbolAddress((void**)&plst, g_lst);
    cudaGetSymbolAddress((void**)&pdeg, g_deg);
    cudaGetSymbolAddress((void**)&phasd,g_hasd);
    cudaGetSymbolAddress((void**)&pidx, g_idx);
    cudaGetSymbolAddress((void**)&pginv,g_ginv);
    cudaGetSymbolAddress((void**)&pcnt, g_cnt);
    cudaGetSymbolAddress((void**)&ppk,  g_pk);

    const int BF16_SMEM = 2 * 4 * TSZ * 2;   // 81920 bytes
    cudaFuncSetAttribute(gemm_bf16_kernel<4>, cudaFuncAttributeMaxDynamicSharedMemorySize, BF16_SMEM);
    cudaFuncSetAttribute(gemm_bf16_kernel<5>, cudaFuncAttributeMaxDynamicSharedMemorySize, BF16_SMEM);

    // ---- CSR + degree stats ----
    csr_build_kernel<<<dim3(N_, B_), 256>>>(adj, plst, pdeg, phasd, pd0, pd1, prnz);

    // ---- GCN layer 1 (fused v) ----
    gemm2_kernel<0,0><<<dim3(1,16,B_),256>>>(x, W1, pxW, N_, F_, H_, F_, H_, H_,
        (long)N_*F_, 0, (long)N_*H_, nullptr, nullptr, nullptr, 0,0,0);
    gcn1_kernel<<<dim3(N_, B_), 128>>>(plst, pdeg, pd0, pxW, b1, mask, Watt, batt, px1, pv);

    // ---- coarsen layer 1 (sparse) ----
    alpha1_kernel<<<dim3(N_/8, B_), 256>>>(plst, pdeg, pd1, prnz, pv, palp);
    topk_cut_kernel<<<B_, 1024>>>(palp, pcut, pca);
    compact_kernel<<<B_, 1024>>>(pca, mask, pd1, pidx, pginv, pcnt, pmaskc, pmrest, ppk);
    srec_kernel<<<dim3(N_/8, B_), 256>>>(plst, pdeg, pd1, prnz, ppk, pca, psrec);
    xupd_kernel<<<dim3(N_, B_), 128>>>(plst, pdeg, phasd, pd1, pca, psrec, pidx, pcnt,
                                       px1, Watt, batt, pxc, pv);
    adjS_sparse_kernel<<<dim3(N_/4, B_), 128>>>(plst, pdeg, phasd, psrec, ppk, pcnt, pT);
    STT_kernel<<<dim3(N_, B_), 256>>>(plst, pdeg, phasd, pd1, pca, psrec, pidx, pcnt,
                                      pT, pAc, pAhi, pAlo, pd2, prz2);

    // ---- coarsen layer 2 ----
    alpha2d_kernel<<<dim3(N_, B_), 256>>>(pAc, pd2, prz2, pv, pcnt, palp);
    topk_cut_kernel<<<B_, 1024>>>(palp, pcut, pca);
    s2inv_kernel<<<dim3(N_, B_), 256>>>(pAc, pd2, prz2, pca, pcnt, psrec);
    buildST_kernel<<<dim3(N_, B_), 256>>>(pAc, pd2, pca, psrec, pcnt, pSThi, pSTlo);
    split_tr_kernel<<<dim3(4, 64, B_), dim3(32, 8)>>>(pxc, pxTh, pxTl, pcnt,
        0, H_, H_, (long)N_*H_, (long)H_*N_);
    // MERGED: T2^T = ST @ Ac^T (bf16 split -> TT)  AND  x3 = ST @ xc (fp32)
    gemm_bf16_kernel<4><<<dim3(17,16,B_),256,BF16_SMEM>>>(pSThi, pSTlo, pAhi, pAlo,
        nullptr, pcnt, N_, (long)N_*N_, pTThi, pTTlo,
        pxTh, pxTl, px3, H_, (long)N_*H_);
    // A3 = ST @ T2 (symmetric): upper blocks only, floor-quant, mirror write
    gemm_bf16_kernel<5><<<dim3(16,16,B_),256,BF16_SMEM>>>(pSThi, pSTlo, pTThi, pTTlo,
        pA3, pcnt, N_, (long)N_*N_, nullptr, nullptr,
        nullptr, nullptr, nullptr, 0, 0);

    // ---- final GCN: mean only; reassociated (w^T x3) @ W2 ----
    rowstats_c_kernel<<<dim3(N_, B_), 256>>>(pA3, pcnt, pd2, nullptr, 0);
    wvec_kernel<<<dim3(N_, B_), 256>>>(pA3, pd2, pmaskc, pcnt, pv);
    out2v_kernel<<<dim3(4, B_), 128>>>(px3, pv, pcnt, pp2);

    // ---- concat means ----
    mean1_part_kernel<<<dim3(4, B_), 128>>>(px1, pp1);
    mean_combine_kernel<<<B_, 384>>>(pp1, pp2, W2, b2, pmrest, out);
}